// round 2
// baseline (speedup 1.0000x reference)
#include <cuda_runtime.h>
#include <math.h>

#define CC   64
#define HH   80
#define WW   160
#define HWSZ (HH * WW)      // 12800
#define BB   3
#define LL   4
#define EPSB 1e-5f
#define NEGV -1e30f

// Scratch: A[b][j][pix][o]  (conv partial of warped-neighbor half of layer1, channel-last)
//          E[b][pix][o]     (conv partial of ego half of layer1, for i=0 -> node[b,0])
__device__ __align__(16) float g_A[(size_t)BB * LL * HWSZ * 128];   // 78.6 MB
__device__ __align__(16) float g_E[(size_t)BB * HWSZ * 128];        // 19.7 MB

// ---------------- f32x2 helpers (Blackwell packed fp32) ----------------
__device__ __forceinline__ unsigned long long pack2f(float a, float b) {
    unsigned long long r;
    asm("mov.b64 %0, {%1, %2};" : "=l"(r) : "f"(a), "f"(b));
    return r;
}
__device__ __forceinline__ void fma2(unsigned long long &d, unsigned long long a, unsigned long long b) {
    asm("fma.rn.f32x2 %0, %1, %2, %0;" : "+l"(d) : "l"(a), "l"(b));
}

// ---------------- Kernel 1: per-agent GEMM  [12800 x 64] @ [64 x 128] ----------------
// jobs 0..11  : A for (b = job/4, j = job%4)  using w1 rows [0,64)   (skip if j >= rec[b])
// jobs 12..14 : E for b = job-12              using w1 rows [64,128)
__global__ __launch_bounds__(256) void disco_k1(const float* __restrict__ x,
                                                const int* __restrict__ rec,
                                                const float* __restrict__ w1) {
    __shared__ __align__(16) float Xs[64][64];     // [k][pixel]
    __shared__ __align__(16) float Ws[64][128];    // [k][o]

    int job   = blockIdx.y;
    int ptile = blockIdx.x * 64;
    int r0 = rec[0], r1 = rec[1], r2 = rec[2];

    const float* src;
    float* dst;
    int wrow0;
    if (job < 12) {
        int b = job >> 2, j = job & 3;
        int rb   = (b == 0) ? r0 : ((b == 1) ? r1 : r2);
        if (j >= rb) return;
        int aoff = (b == 0) ? 0 : ((b == 1) ? r0 : (r0 + r1));
        src   = x + (size_t)(aoff + j) * CC * HWSZ;
        dst   = g_A + (size_t)job * HWSZ * 128;
        wrow0 = 0;
    } else {
        int b = job - 12;
        int aoff = (b == 0) ? 0 : ((b == 1) ? r0 : (r0 + r1));
        src   = x + (size_t)aoff * CC * HWSZ;
        dst   = g_E + (size_t)b * HWSZ * 128;
        wrow0 = 64;
    }

    int t = threadIdx.x;
    for (int i = t; i < 64 * 64; i += 256) {
        int c = i >> 6, p = i & 63;
        Xs[c][p] = src[c * HWSZ + ptile + p];
    }
    for (int i = t; i < 64 * 128; i += 256) {
        int c = i >> 7, o = i & 127;
        Ws[c][o] = w1[(wrow0 + c) * 128 + o];
    }
    __syncthreads();

    // thread (tn, tp): 4 pixels (tp*4 ..) x 8 outs {tn*4..tn*4+3} U {64+tn*4..64+tn*4+3}
    int tn = t & 15, tp = t >> 4;

    unsigned long long acc[4][4];
#pragma unroll
    for (int i = 0; i < 4; i++)
#pragma unroll
        for (int j = 0; j < 4; j++) acc[i][j] = 0ULL;

#pragma unroll 8
    for (int k = 0; k < 64; k++) {
        float4 xv = *(const float4*)&Xs[k][tp * 4];
        ulonglong2 wa = *(const ulonglong2*)&Ws[k][tn * 4];
        ulonglong2 wb = *(const ulonglong2*)&Ws[k][64 + tn * 4];
        unsigned long long x0 = pack2f(xv.x, xv.x);
        unsigned long long x1 = pack2f(xv.y, xv.y);
        unsigned long long x2 = pack2f(xv.z, xv.z);
        unsigned long long x3 = pack2f(xv.w, xv.w);
        fma2(acc[0][0], x0, wa.x); fma2(acc[0][1], x0, wa.y);
        fma2(acc[0][2], x0, wb.x); fma2(acc[0][3], x0, wb.y);
        fma2(acc[1][0], x1, wa.x); fma2(acc[1][1], x1, wa.y);
        fma2(acc[1][2], x1, wb.x); fma2(acc[1][3], x1, wb.y);
        fma2(acc[2][0], x2, wa.x); fma2(acc[2][1], x2, wa.y);
        fma2(acc[2][2], x2, wb.x); fma2(acc[2][3], x2, wb.y);
        fma2(acc[3][0], x3, wa.x); fma2(acc[3][1], x3, wa.y);
        fma2(acc[3][2], x3, wb.x); fma2(acc[3][3], x3, wb.y);
    }

#pragma unroll
    for (int i = 0; i < 4; i++) {
        float* dp = dst + (size_t)(ptile + tp * 4 + i) * 128;
        ulonglong2 s0; s0.x = acc[i][0]; s0.y = acc[i][1];
        ulonglong2 s1; s1.x = acc[i][2]; s1.y = acc[i][3];
        *(ulonglong2*)(dp + tn * 4)      = s0;
        *(ulonglong2*)(dp + 64 + tn * 4) = s1;
    }
}

// ---------------- Kernel 2: warp-per-pixel fusion ----------------
__global__ __launch_bounds__(256) void disco_k2(
    const float* __restrict__ x, const float* __restrict__ mask,
    const int* __restrict__ rec, const float* __restrict__ ptm,
    const float* __restrict__ cb1, const float* __restrict__ ga1,
    const float* __restrict__ be1, const float* __restrict__ rm1, const float* __restrict__ rv1,
    const float* __restrict__ w2, const float* __restrict__ cb2, const float* __restrict__ ga2,
    const float* __restrict__ be2, const float* __restrict__ rm2, const float* __restrict__ rv2,
    const float* __restrict__ w3, const float* __restrict__ cb3, const float* __restrict__ ga3,
    const float* __restrict__ be3, const float* __restrict__ rm3, const float* __restrict__ rv3,
    const float* __restrict__ w4, const float* __restrict__ cb4,
    const float* __restrict__ mlpw, const float* __restrict__ mlpb,
    float* __restrict__ out)
{
    __shared__ __align__(16) float s_f1s[128], s_f1b[128];
    __shared__ __align__(16) float s_w2t[32][132];   // w2 transposed [o][c], padded (conflict-free .128)
    __shared__ __align__(16) float s_f2s[32], s_f2b[32];
    __shared__ __align__(16) float s_w3[256];        // [o][k]
    __shared__ __align__(16) float s_f3s[8], s_f3b[8], s_w4[8];
    __shared__ float s_cb4v;
    __shared__ __align__(16) float s_mw[4096];       // mlp_w [c][d]
    __shared__ __align__(16) float s_mb[64];
    __shared__ __align__(16) float s_h1[8][128];
    __shared__ __align__(16) float s_u[8][64];
    __shared__ __align__(16) float s_o[64][8];

    int t = threadIdx.x;
    if (t < 128) {
        float sc = ga1[t] * rsqrtf(rv1[t] + EPSB);
        s_f1s[t] = sc;
        s_f1b[t] = (cb1[t] - rm1[t]) * sc + be1[t];
    }
    for (int i = t; i < 4096; i += 256) {
        int c = i >> 5, o = i & 31;
        s_w2t[o][c] = w2[i];
        s_mw[i] = mlpw[i];
    }
    if (t < 32) {
        float sc = ga2[t] * rsqrtf(rv2[t] + EPSB);
        s_f2s[t] = sc;
        s_f2b[t] = (cb2[t] - rm2[t]) * sc + be2[t];
    }
    s_w3[t] = w3[t & 255];                 // 256 threads, 256 elems
    if (t < 8) {
        float sc = ga3[t] * rsqrtf(rv3[t] + EPSB);
        s_f3s[t] = sc;
        s_f3b[t] = (cb3[t] - rm3[t]) * sc + be3[t];
        s_w4[t] = w4[t];
    }
    if (t == 0) s_cb4v = cb4[0];
    if (t < 64) s_mb[t] = mlpb[t];
    __syncthreads();

    int wp = t >> 5, lane = t & 31;
    int p   = blockIdx.x * 8 + wp;         // flat pixel 0..38399
    int b   = p / HWSZ;
    int rem = p - b * HWSZ;
    int hh  = rem / WW;
    int wpx = rem - hh * WW;
    float gx = -1.0f + wpx * (2.0f / (WW - 1));
    float gy = -1.0f + hh  * (2.0f / (HH - 1));

    int r0 = rec[0], r1 = rec[1], r2 = rec[2];
    int rb   = (b == 0) ? r0 : ((b == 1) ? r1 : r2);
    int aoff = (b == 0) ? 0 : ((b == 1) ? r0 : (r0 + r1));

    const float* Ep = g_E + (size_t)p * 128;
    float e0 = Ep[lane], e1 = Ep[lane + 32], e2 = Ep[lane + 64], e3 = Ep[lane + 96];

    float sj[4], comj[4];
    float twj[4][4];
    int   trj[4][4];

#pragma unroll
    for (int j = 0; j < 4; j++) {
        if (j >= rb) { sj[j] = NEGV; comj[j] = 0.0f; continue; }
        // theta = ptm[b][j][0]  (after swapaxes, i=0)
        const float* th = ptm + (size_t)(b * 4 + j) * 24;
        float t00 = th[0], t01 = th[1], t02 = th[2];
        float t10 = th[3], t11 = th[4], t12 = th[5];
        float px = (t00 * gx + t01 * gy + t02 + 1.0f) * ((WW - 1) * 0.5f);
        float py = (t10 * gx + t11 * gy + t12 + 1.0f) * ((HH - 1) * 0.5f);
        float x0f = floorf(px), y0f = floorf(py);
        float wx = px - x0f, wy = py - y0f;
        int x0 = (int)x0f, y0 = (int)y0f;
        float wt[4] = { (1.0f - wx) * (1.0f - wy), wx * (1.0f - wy),
                        (1.0f - wx) * wy,          wx * wy };
        const float* Ab = g_A + (size_t)(b * 4 + j) * HWSZ * 128;
        const float* Mb = mask + (size_t)(b * 4 + j) * HWSZ;
        float com = 0.0f;
        float a0 = 0.f, a1 = 0.f, a2 = 0.f, a3 = 0.f;
#pragma unroll
        for (int tap = 0; tap < 4; tap++) {
            int xi = x0 + (tap & 1);
            int yi = y0 + (tap >> 1);
            bool inb = (xi >= 0) && (xi < WW) && (yi >= 0) && (yi < HH);
            int xc = min(max(xi, 0), WW - 1);
            int yc = min(max(yi, 0), HH - 1);
            float tw = inb ? wt[tap] : 0.0f;
            int rt = yc * WW + xc;
            twj[j][tap] = tw;
            trj[j][tap] = rt;
            com += tw * Mb[rt];
            const float* Ap = Ab + (size_t)rt * 128;
            a0 = fmaf(tw, Ap[lane],      a0);
            a1 = fmaf(tw, Ap[lane + 32], a1);
            a2 = fmaf(tw, Ap[lane + 64], a2);
            a3 = fmaf(tw, Ap[lane + 96], a3);
        }
        comj[j] = com;

        // layer1 = relu( (A_interp + E) * bn_scale + bn_bias(folded with cb1) )
        float* hb = s_h1[wp];
        hb[lane]      = fmaxf(0.0f, (a0 + e0) * s_f1s[lane]      + s_f1b[lane]);
        hb[lane + 32] = fmaxf(0.0f, (a1 + e1) * s_f1s[lane + 32] + s_f1b[lane + 32]);
        hb[lane + 64] = fmaxf(0.0f, (a2 + e2) * s_f1s[lane + 64] + s_f1b[lane + 64]);
        hb[lane + 96] = fmaxf(0.0f, (a3 + e3) * s_f1s[lane + 96] + s_f1b[lane + 96]);
        __syncwarp();

        // layer2: o = lane, 128-dot
        float acc2 = 0.0f;
        const float* wrow = &s_w2t[lane][0];
#pragma unroll
        for (int c4 = 0; c4 < 32; c4++) {
            float4 hv = *(const float4*)(hb + c4 * 4);
            float4 wv = *(const float4*)(wrow + c4 * 4);
            acc2 = fmaf(hv.x, wv.x, acc2);
            acc2 = fmaf(hv.y, wv.y, acc2);
            acc2 = fmaf(hv.z, wv.z, acc2);
            acc2 = fmaf(hv.w, wv.w, acc2);
        }
        __syncwarp();
        float h2 = fmaxf(0.0f, acc2 * s_f2s[lane] + s_f2b[lane]);

        // layer3: 32 -> 8 via per-lane partials + butterfly reduce
        float4 wa = *(const float4*)&s_w3[lane * 8];
        float4 wb = *(const float4*)&s_w3[lane * 8 + 4];
        float p3[8] = { h2 * wa.x, h2 * wa.y, h2 * wa.z, h2 * wa.w,
                        h2 * wb.x, h2 * wb.y, h2 * wb.z, h2 * wb.w };
#pragma unroll
        for (int off = 16; off >= 1; off >>= 1) {
#pragma unroll
            for (int k = 0; k < 8; k++)
                p3[k] += __shfl_xor_sync(0xffffffffu, p3[k], off);
        }
        // layer4: 8 -> 1
        float s4 = s_cb4v;
#pragma unroll
        for (int k = 0; k < 8; k++) {
            float h3 = fmaxf(0.0f, p3[k] * s_f3s[k] + s_f3b[k]);
            s4 = fmaf(h3, s_w4[k], s4);
        }
        sj[j] = (com == 0.0f) ? NEGV : fmaxf(0.0f, s4);
    }

    // softmax over j
    float m = fmaxf(fmaxf(sj[0], sj[1]), fmaxf(sj[2], sj[3]));
    float ex[4];
    float ssum = 0.0f;
#pragma unroll
    for (int j = 0; j < 4; j++) { ex[j] = expf(sj[j] - m); ssum += ex[j]; }
    float inv = 1.0f / ssum;

    // updated[c] = sum_j aw_j * com_j * nbr[j][c]   (c = lane, lane+32)
    float u0 = 0.0f, u1 = 0.0f;
#pragma unroll
    for (int j = 0; j < 4; j++) {
        if (j >= rb) continue;
        float wgt = ex[j] * inv * comj[j];
        if (wgt == 0.0f) continue;
        const float* xb = x + (size_t)(aoff + j) * CC * HWSZ;
        float n0 = 0.0f, n1 = 0.0f;
#pragma unroll
        for (int tap = 0; tap < 4; tap++) {
            float tw = twj[j][tap];
            int rt = trj[j][tap];
            n0 = fmaf(tw, xb[(size_t)lane * HWSZ + rt],        n0);
            n1 = fmaf(tw, xb[(size_t)(lane + 32) * HWSZ + rt], n1);
        }
        u0 = fmaf(wgt, n0, u0);
        u1 = fmaf(wgt, n1, u1);
    }

    s_u[wp][lane]      = u0;
    s_u[wp][lane + 32] = u1;
    __syncwarp();

    // final mlp: out[d] = sum_c u[c] * mlp_w[c][d] + mlp_b[d]   (d = lane, lane+32)
    float acc0 = s_mb[lane], acc1 = s_mb[lane + 32];
    const float* ub = s_u[wp];
#pragma unroll 16
    for (int c = 0; c < 64; c++) {
        float uc = ub[c];
        acc0 = fmaf(uc, s_mw[c * 64 + lane],      acc0);
        acc1 = fmaf(uc, s_mw[c * 64 + lane + 32], acc1);
    }
    s_o[lane][wp]      = acc0;
    s_o[lane + 32][wp] = acc1;
    __syncthreads();

    // coalesced transposed store (8 consecutive pixels never cross batch: 12800 % 8 == 0)
    int pbase = blockIdx.x * 8;
    int bb = pbase / HWSZ;
    int rbase = pbase - bb * HWSZ;
#pragma unroll
    for (int e = t; e < 512; e += 256) {
        int d = e >> 3, pix = e & 7;
        out[((size_t)bb * CC + d) * HWSZ + rbase + pix] = s_o[d][pix];
    }
}

extern "C" void kernel_launch(void* const* d_in, const int* in_sizes, int n_in,
                              void* d_out, int out_size) {
    (void)in_sizes; (void)n_in; (void)out_size;
    const float* x    = (const float*)d_in[0];
    const float* mask = (const float*)d_in[1];
    const int*   rec  = (const int*)d_in[2];
    const float* ptm  = (const float*)d_in[3];
    const float* w1   = (const float*)d_in[4];
    const float* cb1  = (const float*)d_in[5];
    const float* ga1  = (const float*)d_in[6];
    const float* be1  = (const float*)d_in[7];
    const float* rm1  = (const float*)d_in[8];
    const float* rv1  = (const float*)d_in[9];
    const float* w2   = (const float*)d_in[10];
    const float* cb2  = (const float*)d_in[11];
    const float* ga2  = (const float*)d_in[12];
    const float* be2  = (const float*)d_in[13];
    const float* rm2  = (const float*)d_in[14];
    const float* rv2  = (const float*)d_in[15];
    const float* w3   = (const float*)d_in[16];
    const float* cb3  = (const float*)d_in[17];
    const float* ga3  = (const float*)d_in[18];
    const float* be3  = (const float*)d_in[19];
    const float* rm3  = (const float*)d_in[20];
    const float* rv3  = (const float*)d_in[21];
    const float* w4   = (const float*)d_in[22];
    const float* cb4  = (const float*)d_in[23];
    const float* mlpw = (const float*)d_in[24];
    const float* mlpb = (const float*)d_in[25];
    float* out = (float*)d_out;

    dim3 grid1(HWSZ / 64, 15);            // 200 pixel-tiles x 15 jobs (invalid jobs self-skip)
    disco_k1<<<grid1, 256>>>(x, rec, w1);

    disco_k2<<<(BB * HWSZ) / 8, 256>>>(x, mask, rec, ptm,
                                       cb1, ga1, be1, rm1, rv1,
                                       w2, cb2, ga2, be2, rm2, rv2,
                                       w3, cb3, ga3, be3, rm3, rv3,
                                       w4, cb4, mlpw, mlpb, out);
}

// round 3
// speedup vs baseline: 1.2725x; 1.2725x over previous
#include <cuda_runtime.h>
#include <math.h>

#define CC   64
#define HH   80
#define WW   160
#define HWSZ (HH * WW)      // 12800
#define BB   3
#define LL   4
#define EPSB 1e-5f
#define NEGV -1e30f

// Scratch:
//  g_A[b*4+j][pix][o]  conv partial (warped-neighbor half of layer1), channel-last, 128 ch
//  g_E[b][pix][o]      conv partial (ego half, node[b,0]), channel-last, 128 ch
//  g_xt[b*4+j][pix][c] raw x transposed to channel-last (64 ch) for the updated-gather
__device__ __align__(16) float g_A[(size_t)BB * LL * HWSZ * 128];   // 78.6 MB
__device__ __align__(16) float g_E[(size_t)BB * HWSZ * 128];        // 19.7 MB
__device__ __align__(16) float g_xt[(size_t)BB * LL * HWSZ * 64];   // 39.3 MB

// ---------------- f32x2 helpers (Blackwell packed fp32) ----------------
__device__ __forceinline__ unsigned long long pack2f(float a, float b) {
    unsigned long long r;
    asm("mov.b64 %0, {%1, %2};" : "=l"(r) : "f"(a), "f"(b));
    return r;
}
__device__ __forceinline__ void fma2(unsigned long long &d, unsigned long long a, unsigned long long b) {
    asm("fma.rn.f32x2 %0, %1, %2, %0;" : "+l"(d) : "l"(a), "l"(b));
}

// ---------------- Kernel 1: per-agent GEMM  [12800 x 64] @ [64 x 128] ----------------
// jobs 0..11  : A for (b = job/4, j = job%4)  using w1 rows [0,64)   (skip if j >= rec[b])
//               + writes x_t (channel-last raw x) for that agent
// jobs 12..14 : E for b = job-12              using w1 rows [64,128)
__global__ __launch_bounds__(256) void disco_k1(const float* __restrict__ x,
                                                const int* __restrict__ rec,
                                                const float* __restrict__ w1) {
    __shared__ __align__(16) float Xs[64][68];     // [k][pixel], padded for transpose pass
    __shared__ __align__(16) float Ws[64][128];    // [k][o]

    int job   = blockIdx.y;
    int ptile = blockIdx.x * 64;
    int r0 = rec[0], r1 = rec[1], r2 = rec[2];

    const float* src;
    float* dst;
    int wrow0;
    bool isA = (job < 12);
    if (isA) {
        int b = job >> 2, j = job & 3;
        int rb   = (b == 0) ? r0 : ((b == 1) ? r1 : r2);
        if (j >= rb) return;
        int aoff = (b == 0) ? 0 : ((b == 1) ? r0 : (r0 + r1));
        src   = x + (size_t)(aoff + j) * CC * HWSZ;
        dst   = g_A + (size_t)job * HWSZ * 128;
        wrow0 = 0;
    } else {
        int b = job - 12;
        int aoff = (b == 0) ? 0 : ((b == 1) ? r0 : (r0 + r1));
        src   = x + (size_t)aoff * CC * HWSZ;
        dst   = g_E + (size_t)b * HWSZ * 128;
        wrow0 = 64;
    }

    int t = threadIdx.x;
    for (int i = t; i < 64 * 64; i += 256) {
        int c = i >> 6, p = i & 63;
        Xs[c][p] = src[c * HWSZ + ptile + p];
    }
    for (int i = t; i < 64 * 128; i += 256) {
        int c = i >> 7, o = i & 127;
        Ws[c][o] = w1[(wrow0 + c) * 128 + o];
    }
    __syncthreads();

    // thread (tn, tp): 4 pixels (tp*4 ..) x 8 outs {tn*4..tn*4+3} U {64+tn*4..64+tn*4+3}
    int tn = t & 15, tp = t >> 4;

    unsigned long long acc[4][4];
#pragma unroll
    for (int i = 0; i < 4; i++)
#pragma unroll
        for (int j = 0; j < 4; j++) acc[i][j] = 0ULL;

#pragma unroll 8
    for (int k = 0; k < 64; k++) {
        float4 xv = *(const float4*)&Xs[k][tp * 4];
        ulonglong2 wa = *(const ulonglong2*)&Ws[k][tn * 4];
        ulonglong2 wb = *(const ulonglong2*)&Ws[k][64 + tn * 4];
        unsigned long long x0 = pack2f(xv.x, xv.x);
        unsigned long long x1 = pack2f(xv.y, xv.y);
        unsigned long long x2 = pack2f(xv.z, xv.z);
        unsigned long long x3 = pack2f(xv.w, xv.w);
        fma2(acc[0][0], x0, wa.x); fma2(acc[0][1], x0, wa.y);
        fma2(acc[0][2], x0, wb.x); fma2(acc[0][3], x0, wb.y);
        fma2(acc[1][0], x1, wa.x); fma2(acc[1][1], x1, wa.y);
        fma2(acc[1][2], x1, wb.x); fma2(acc[1][3], x1, wb.y);
        fma2(acc[2][0], x2, wa.x); fma2(acc[2][1], x2, wa.y);
        fma2(acc[2][2], x2, wb.x); fma2(acc[2][3], x2, wb.y);
        fma2(acc[3][0], x3, wa.x); fma2(acc[3][1], x3, wa.y);
        fma2(acc[3][2], x3, wb.x); fma2(acc[3][3], x3, wb.y);
    }

#pragma unroll
    for (int i = 0; i < 4; i++) {
        float* dp = dst + (size_t)(ptile + tp * 4 + i) * 128;
        ulonglong2 s0; s0.x = acc[i][0]; s0.y = acc[i][1];
        ulonglong2 s1; s1.x = acc[i][2]; s1.y = acc[i][3];
        *(ulonglong2*)(dp + tn * 4)      = s0;
        *(ulonglong2*)(dp + 64 + tn * 4) = s1;
    }

    // Transposed raw-x writeback for A-jobs (Xs not modified since load sync)
    if (isA) {
        float* xt = g_xt + (size_t)job * HWSZ * 64;
        for (int i = t; i < 64 * 64; i += 256) {
            int p = i >> 6, c = i & 63;
            xt[(size_t)(ptile + p) * 64 + c] = Xs[c][p];
        }
    }
}

// ---------------- Kernel 2: warp-per-pixel fusion ----------------
__global__ __launch_bounds__(256) void disco_k2(
    const float* __restrict__ mask,
    const int* __restrict__ rec, const float* __restrict__ ptm,
    const float* __restrict__ cb1, const float* __restrict__ ga1,
    const float* __restrict__ be1, const float* __restrict__ rm1, const float* __restrict__ rv1,
    const float* __restrict__ w2, const float* __restrict__ cb2, const float* __restrict__ ga2,
    const float* __restrict__ be2, const float* __restrict__ rm2, const float* __restrict__ rv2,
    const float* __restrict__ w3, const float* __restrict__ cb3, const float* __restrict__ ga3,
    const float* __restrict__ be3, const float* __restrict__ rm3, const float* __restrict__ rv3,
    const float* __restrict__ w4, const float* __restrict__ cb4,
    const float* __restrict__ mlpw, const float* __restrict__ mlpb,
    float* __restrict__ out)
{
    __shared__ __align__(16) float s_f1s[128], s_f1b[128];
    __shared__ __align__(16) float s_w2t[32][132];   // w2 transposed [o][c], padded (conflict-free .128)
    __shared__ __align__(16) float s_f2s[32], s_f2b[32];
    __shared__ __align__(16) float s_w3[256];        // [o][k]
    __shared__ __align__(16) float s_f3s[8], s_f3b[8], s_w4[8];
    __shared__ float s_cb4v;
    __shared__ __align__(16) float s_mw[4096];       // mlp_w [c][d]
    __shared__ __align__(16) float s_mb[64];
    __shared__ __align__(16) float s_h1[8][128];
    __shared__ __align__(16) float s_u[8][64];
    __shared__ __align__(16) float s_o[64][8];

    int t = threadIdx.x;
    if (t < 128) {
        float sc = ga1[t] * rsqrtf(rv1[t] + EPSB);
        s_f1s[t] = sc;
        s_f1b[t] = (cb1[t] - rm1[t]) * sc + be1[t];
    }
    for (int i = t; i < 4096; i += 256) {
        int c = i >> 5, o = i & 31;
        s_w2t[o][c] = w2[i];
        s_mw[i] = mlpw[i];
    }
    if (t < 32) {
        float sc = ga2[t] * rsqrtf(rv2[t] + EPSB);
        s_f2s[t] = sc;
        s_f2b[t] = (cb2[t] - rm2[t]) * sc + be2[t];
    }
    s_w3[t] = w3[t & 255];                 // 256 threads, 256 elems
    if (t < 8) {
        float sc = ga3[t] * rsqrtf(rv3[t] + EPSB);
        s_f3s[t] = sc;
        s_f3b[t] = (cb3[t] - rm3[t]) * sc + be3[t];
        s_w4[t] = w4[t];
    }
    if (t == 0) s_cb4v = cb4[0];
    if (t < 64) s_mb[t] = mlpb[t];
    __syncthreads();

    int wp = t >> 5, lane = t & 31;
    int p   = blockIdx.x * 8 + wp;         // flat pixel 0..38399
    int b   = p / HWSZ;
    int rem = p - b * HWSZ;
    int hh  = rem / WW;
    int wpx = rem - hh * WW;
    float gx = -1.0f + wpx * (2.0f / (WW - 1));
    float gy = -1.0f + hh  * (2.0f / (HH - 1));

    int r0 = rec[0], r1 = rec[1], r2 = rec[2];
    int rb = (b == 0) ? r0 : ((b == 1) ? r1 : r2);

    // channel mapping: this lane owns channels lane*4 .. lane*4+3 (128-ch tensors)
    float4 ev  = *(const float4*)(g_E + (size_t)p * 128 + lane * 4);
    float4 f1s = *(const float4*)&s_f1s[lane * 4];
    float4 f1b = *(const float4*)&s_f1b[lane * 4];

    float sj[4], comj[4];
    float twj[4][4];
    int   trj[4][4];

#pragma unroll
    for (int j = 0; j < 4; j++) {
        if (j >= rb) { sj[j] = NEGV; comj[j] = 0.0f; continue; }
        // theta = ptm[b][j][0]  (after swapaxes, i=0)
        const float* th = ptm + (size_t)(b * 4 + j) * 24;
        float t00 = th[0], t01 = th[1], t02 = th[2];
        float t10 = th[3], t11 = th[4], t12 = th[5];
        float px = (t00 * gx + t01 * gy + t02 + 1.0f) * ((WW - 1) * 0.5f);
        float py = (t10 * gx + t11 * gy + t12 + 1.0f) * ((HH - 1) * 0.5f);
        float x0f = floorf(px), y0f = floorf(py);
        float wx = px - x0f, wy = py - y0f;
        int x0 = (int)x0f, y0 = (int)y0f;
        float wt[4] = { (1.0f - wx) * (1.0f - wy), wx * (1.0f - wy),
                        (1.0f - wx) * wy,          wx * wy };
        const float* Ab = g_A + (size_t)(b * 4 + j) * HWSZ * 128;
        const float* Mb = mask + (size_t)(b * 4 + j) * HWSZ;
        float com = 0.0f;
        float a0 = 0.f, a1 = 0.f, a2 = 0.f, a3 = 0.f;
#pragma unroll
        for (int tap = 0; tap < 4; tap++) {
            int xi = x0 + (tap & 1);
            int yi = y0 + (tap >> 1);
            bool inb = (xi >= 0) && (xi < WW) && (yi >= 0) && (yi < HH);
            int xc = min(max(xi, 0), WW - 1);
            int yc = min(max(yi, 0), HH - 1);
            float tw = inb ? wt[tap] : 0.0f;
            int rt = yc * WW + xc;
            twj[j][tap] = tw;
            trj[j][tap] = rt;
            com += tw * Mb[rt];
            float4 Av = *(const float4*)(Ab + (size_t)rt * 128 + lane * 4);
            a0 = fmaf(tw, Av.x, a0);
            a1 = fmaf(tw, Av.y, a1);
            a2 = fmaf(tw, Av.z, a2);
            a3 = fmaf(tw, Av.w, a3);
        }
        comj[j] = com;

        // layer1 = relu( (A_interp + E) * bn_scale + bn_bias(folded with cb1) )
        float* hb = s_h1[wp];
        float4 h1v;
        h1v.x = fmaxf(0.0f, (a0 + ev.x) * f1s.x + f1b.x);
        h1v.y = fmaxf(0.0f, (a1 + ev.y) * f1s.y + f1b.y);
        h1v.z = fmaxf(0.0f, (a2 + ev.z) * f1s.z + f1b.z);
        h1v.w = fmaxf(0.0f, (a3 + ev.w) * f1s.w + f1b.w);
        *(float4*)&hb[lane * 4] = h1v;
        __syncwarp();

        // layer2: o = lane, 128-dot
        float acc2 = 0.0f;
        const float* wrow = &s_w2t[lane][0];
#pragma unroll
        for (int c4 = 0; c4 < 32; c4++) {
            float4 hv = *(const float4*)(hb + c4 * 4);
            float4 wv = *(const float4*)(wrow + c4 * 4);
            acc2 = fmaf(hv.x, wv.x, acc2);
            acc2 = fmaf(hv.y, wv.y, acc2);
            acc2 = fmaf(hv.z, wv.z, acc2);
            acc2 = fmaf(hv.w, wv.w, acc2);
        }
        __syncwarp();
        float h2 = fmaxf(0.0f, acc2 * s_f2s[lane] + s_f2b[lane]);

        // layer3: 32 -> 8 via per-lane partials + butterfly reduce
        float4 wa = *(const float4*)&s_w3[lane * 8];
        float4 wb = *(const float4*)&s_w3[lane * 8 + 4];
        float p3[8] = { h2 * wa.x, h2 * wa.y, h2 * wa.z, h2 * wa.w,
                        h2 * wb.x, h2 * wb.y, h2 * wb.z, h2 * wb.w };
#pragma unroll
        for (int off = 16; off >= 1; off >>= 1) {
#pragma unroll
            for (int k = 0; k < 8; k++)
                p3[k] += __shfl_xor_sync(0xffffffffu, p3[k], off);
        }
        // layer4: 8 -> 1
        float s4 = s_cb4v;
#pragma unroll
        for (int k = 0; k < 8; k++) {
            float h3 = fmaxf(0.0f, p3[k] * s_f3s[k] + s_f3b[k]);
            s4 = fmaf(h3, s_w4[k], s4);
        }
        sj[j] = (com == 0.0f) ? NEGV : fmaxf(0.0f, s4);
    }

    // softmax over j
    float m = fmaxf(fmaxf(sj[0], sj[1]), fmaxf(sj[2], sj[3]));
    float ex[4];
    float ssum = 0.0f;
#pragma unroll
    for (int j = 0; j < 4; j++) { ex[j] = expf(sj[j] - m); ssum += ex[j]; }
    float inv = 1.0f / ssum;

    // updated[c] = sum_j aw_j * com_j * nbr[j][c]  (this lane: c = lane*2, lane*2+1)
    float u0 = 0.0f, u1 = 0.0f;
#pragma unroll
    for (int j = 0; j < 4; j++) {
        if (j >= rb) continue;
        float wgt = ex[j] * inv * comj[j];
        if (wgt == 0.0f) continue;
        const float* xtb = g_xt + (size_t)(b * 4 + j) * HWSZ * 64;
        float n0 = 0.0f, n1 = 0.0f;
#pragma unroll
        for (int tap = 0; tap < 4; tap++) {
            float tw = twj[j][tap];
            float2 xv = *(const float2*)(xtb + (size_t)trj[j][tap] * 64 + lane * 2);
            n0 = fmaf(tw, xv.x, n0);
            n1 = fmaf(tw, xv.y, n1);
        }
        u0 = fmaf(wgt, n0, u0);
        u1 = fmaf(wgt, n1, u1);
    }

    s_u[wp][lane * 2]     = u0;
    s_u[wp][lane * 2 + 1] = u1;
    __syncwarp();

    // final mlp: out[d] = sum_c u[c] * mlp_w[c][d] + mlp_b[d]   (d = lane, lane+32)
    float acc0 = s_mb[lane], acc1 = s_mb[lane + 32];
    const float* ub = s_u[wp];
#pragma unroll 16
    for (int c = 0; c < 64; c++) {
        float uc = ub[c];
        acc0 = fmaf(uc, s_mw[c * 64 + lane],      acc0);
        acc1 = fmaf(uc, s_mw[c * 64 + lane + 32], acc1);
    }
    s_o[lane][wp]      = acc0;
    s_o[lane + 32][wp] = acc1;
    __syncthreads();

    // coalesced transposed store (8 consecutive pixels never cross batch: 12800 % 8 == 0)
    int pbase = blockIdx.x * 8;
    int bb = pbase / HWSZ;
    int rbase = pbase - bb * HWSZ;
#pragma unroll
    for (int e = t; e < 512; e += 256) {
        int d = e >> 3, pix = e & 7;
        out[((size_t)bb * CC + d) * HWSZ + rbase + pix] = s_o[d][pix];
    }
}

extern "C" void kernel_launch(void* const* d_in, const int* in_sizes, int n_in,
                              void* d_out, int out_size) {
    (void)in_sizes; (void)n_in; (void)out_size;
    const float* x    = (const float*)d_in[0];
    const float* mask = (const float*)d_in[1];
    const int*   rec  = (const int*)d_in[2];
    const float* ptm  = (const float*)d_in[3];
    const float* w1   = (const float*)d_in[4];
    const float* cb1  = (const float*)d_in[5];
    const float* ga1  = (const float*)d_in[6];
    const float* be1  = (const float*)d_in[7];
    const float* rm1  = (const float*)d_in[8];
    const float* rv1  = (const float*)d_in[9];
    const float* w2   = (const float*)d_in[10];
    const float* cb2  = (const float*)d_in[11];
    const float* ga2  = (const float*)d_in[12];
    const float* be2  = (const float*)d_in[13];
    const float* rm2  = (const float*)d_in[14];
    const float* rv2  = (const float*)d_in[15];
    const float* w3   = (const float*)d_in[16];
    const float* cb3  = (const float*)d_in[17];
    const float* ga3  = (const float*)d_in[18];
    const float* be3  = (const float*)d_in[19];
    const float* rm3  = (const float*)d_in[20];
    const float* rv3  = (const float*)d_in[21];
    const float* w4   = (const float*)d_in[22];
    const float* cb4  = (const float*)d_in[23];
    const float* mlpw = (const float*)d_in[24];
    const float* mlpb = (const float*)d_in[25];
    float* out = (float*)d_out;

    dim3 grid1(HWSZ / 64, 15);            // 200 pixel-tiles x 15 jobs (invalid jobs self-skip)
    disco_k1<<<grid1, 256>>>(x, rec, w1);

    disco_k2<<<(BB * HWSZ) / 8, 256>>>(mask, rec, ptm,
                                       cb1, ga1, be1, rm1, rv1,
                                       w2, cb2, ga2, be2, rm2, rv2,
                                       w3, cb3, ga3, be3, rm3, rv3,
                                       w4, cb4, mlpw, mlpb, out);
}

// round 4
// speedup vs baseline: 1.2825x; 1.0078x over previous
#include <cuda_runtime.h>
#include <cuda_fp16.h>
#include <math.h>

#define CC   64
#define HH   80
#define WW   160
#define HWSZ (HH * WW)      // 12800
#define BB   3
#define LL   4
#define EPSB 1e-5f
#define NEGV -1e30f

// Scratch:
//  g_Ah[b*4+j][pix][o/2]  conv partial (warped-neighbor half of layer1), channel-last, 128 ch, fp16
//  g_Eh[b][pix][o/2]      conv partial (ego half, node[b,0]), channel-last, 128 ch, fp16
//  g_xt[b*4+j][pix][c]    raw x transposed to channel-last (64 ch, fp32) for the updated-gather
__device__ __align__(16) __half2 g_Ah[(size_t)BB * LL * HWSZ * 64];  // 39.3 MB
__device__ __align__(16) __half2 g_Eh[(size_t)BB * HWSZ * 64];       // 9.8 MB
__device__ __align__(16) float   g_xt[(size_t)BB * LL * HWSZ * 64];  // 39.3 MB

// ---------------- f32x2 helpers (Blackwell packed fp32) ----------------
__device__ __forceinline__ unsigned long long pack2f(float a, float b) {
    unsigned long long r;
    asm("mov.b64 %0, {%1, %2};" : "=l"(r) : "f"(a), "f"(b));
    return r;
}
__device__ __forceinline__ float2 unpack2f(unsigned long long v) {
    float2 r;
    asm("mov.b64 {%0, %1}, %2;" : "=f"(r.x), "=f"(r.y) : "l"(v));
    return r;
}
__device__ __forceinline__ void fma2(unsigned long long &d, unsigned long long a, unsigned long long b) {
    asm("fma.rn.f32x2 %0, %1, %2, %0;" : "+l"(d) : "l"(a), "l"(b));
}
// load 4 consecutive half channels (8B aligned) -> float4
__device__ __forceinline__ float4 ldh4(const __half2* p) {
    uint2 r = *(const uint2*)p;
    float2 fa = __half22float2(*reinterpret_cast<__half2*>(&r.x));
    float2 fb = __half22float2(*reinterpret_cast<__half2*>(&r.y));
    return make_float4(fa.x, fa.y, fb.x, fb.y);
}

// ---------------- Kernel 1: per-agent GEMM  [12800 x 64] @ [64 x 128] ----------------
// jobs 0..11  : A for (b = job/4, j = job%4)  using w1 rows [0,64)   (skip if j >= rec[b])
//               + writes x_t (channel-last raw x) for that agent
// jobs 12..14 : E for b = job-12              using w1 rows [64,128)
__global__ __launch_bounds__(256) void disco_k1(const float* __restrict__ x,
                                                const int* __restrict__ rec,
                                                const float* __restrict__ w1) {
    __shared__ __align__(16) float Xs[64][68];     // [k][pixel], padded for transpose pass
    __shared__ __align__(16) float Ws[64][128];    // [k][o]

    int job   = blockIdx.y;
    int ptile = blockIdx.x * 64;
    int r0 = rec[0], r1 = rec[1], r2 = rec[2];

    const float* src;
    __half2* dst;
    int wrow0;
    bool isA = (job < 12);
    if (isA) {
        int b = job >> 2, j = job & 3;
        int rb   = (b == 0) ? r0 : ((b == 1) ? r1 : r2);
        if (j >= rb) return;
        int aoff = (b == 0) ? 0 : ((b == 1) ? r0 : (r0 + r1));
        src   = x + (size_t)(aoff + j) * CC * HWSZ;
        dst   = g_Ah + (size_t)job * HWSZ * 64;
        wrow0 = 0;
    } else {
        int b = job - 12;
        int aoff = (b == 0) ? 0 : ((b == 1) ? r0 : (r0 + r1));
        src   = x + (size_t)aoff * CC * HWSZ;
        dst   = g_Eh + (size_t)b * HWSZ * 64;
        wrow0 = 64;
    }

    int t = threadIdx.x;
    for (int i = t; i < 64 * 64; i += 256) {
        int c = i >> 6, p = i & 63;
        Xs[c][p] = src[c * HWSZ + ptile + p];
    }
    for (int i = t; i < 64 * 128; i += 256) {
        int c = i >> 7, o = i & 127;
        Ws[c][o] = w1[(wrow0 + c) * 128 + o];
    }
    __syncthreads();

    // thread (tn, tp): 4 pixels (tp*4 ..) x 8 outs {tn*4..tn*4+3} U {64+tn*4..64+tn*4+3}
    int tn = t & 15, tp = t >> 4;

    unsigned long long acc[4][4];
#pragma unroll
    for (int i = 0; i < 4; i++)
#pragma unroll
        for (int j = 0; j < 4; j++) acc[i][j] = 0ULL;

#pragma unroll 8
    for (int k = 0; k < 64; k++) {
        float4 xv = *(const float4*)&Xs[k][tp * 4];
        ulonglong2 wa = *(const ulonglong2*)&Ws[k][tn * 4];
        ulonglong2 wb = *(const ulonglong2*)&Ws[k][64 + tn * 4];
        unsigned long long x0 = pack2f(xv.x, xv.x);
        unsigned long long x1 = pack2f(xv.y, xv.y);
        unsigned long long x2 = pack2f(xv.z, xv.z);
        unsigned long long x3 = pack2f(xv.w, xv.w);
        fma2(acc[0][0], x0, wa.x); fma2(acc[0][1], x0, wa.y);
        fma2(acc[0][2], x0, wb.x); fma2(acc[0][3], x0, wb.y);
        fma2(acc[1][0], x1, wa.x); fma2(acc[1][1], x1, wa.y);
        fma2(acc[1][2], x1, wb.x); fma2(acc[1][3], x1, wb.y);
        fma2(acc[2][0], x2, wa.x); fma2(acc[2][1], x2, wa.y);
        fma2(acc[2][2], x2, wb.x); fma2(acc[2][3], x2, wb.y);
        fma2(acc[3][0], x3, wa.x); fma2(acc[3][1], x3, wa.y);
        fma2(acc[3][2], x3, wb.x); fma2(acc[3][3], x3, wb.y);
    }

#pragma unroll
    for (int i = 0; i < 4; i++) {
        __half2* dp = dst + (size_t)(ptile + tp * 4 + i) * 64;
        float2 f0 = unpack2f(acc[i][0]);
        float2 f1 = unpack2f(acc[i][1]);
        float2 f2 = unpack2f(acc[i][2]);
        float2 f3 = unpack2f(acc[i][3]);
        __half2 h0 = __float22half2_rn(f0);
        __half2 h1 = __float22half2_rn(f1);
        __half2 h2 = __float22half2_rn(f2);
        __half2 h3 = __float22half2_rn(f3);
        uint2 w0; w0.x = *(unsigned*)&h0; w0.y = *(unsigned*)&h1;
        uint2 w1v; w1v.x = *(unsigned*)&h2; w1v.y = *(unsigned*)&h3;
        *(uint2*)(dp + tn * 2)      = w0;   // channels 4tn..4tn+3
        *(uint2*)(dp + 32 + tn * 2) = w1v;  // channels 64+4tn..64+4tn+3
    }

    // Transposed raw-x writeback for A-jobs (Xs not modified since load sync)
    if (isA) {
        float* xt = g_xt + (size_t)job * HWSZ * 64;
        for (int i = t; i < 64 * 64; i += 256) {
            int p = i >> 6, c = i & 63;
            xt[(size_t)(ptile + p) * 64 + c] = Xs[c][p];
        }
    }
}

// ---------------- Kernel 2: warp-per-pixel fusion ----------------
__global__ __launch_bounds__(256, 3) void disco_k2(
    const float* __restrict__ mask,
    const int* __restrict__ rec, const float* __restrict__ ptm,
    const float* __restrict__ cb1, const float* __restrict__ ga1,
    const float* __restrict__ be1, const float* __restrict__ rm1, const float* __restrict__ rv1,
    const float* __restrict__ w2, const float* __restrict__ cb2, const float* __restrict__ ga2,
    const float* __restrict__ be2, const float* __restrict__ rm2, const float* __restrict__ rv2,
    const float* __restrict__ w3, const float* __restrict__ cb3, const float* __restrict__ ga3,
    const float* __restrict__ be3, const float* __restrict__ rm3, const float* __restrict__ rv3,
    const float* __restrict__ w4, const float* __restrict__ cb4,
    const float* __restrict__ mlpw, const float* __restrict__ mlpb,
    float* __restrict__ out)
{
    __shared__ __align__(16) float s_f1s[128], s_f1b[128];
    __shared__ __align__(16) __half2 s_w2h[32][68];  // w2 [o][c-pairs], stride 68 words (==4 mod 32: conflict-free LDS.128)
    __shared__ __align__(16) float s_f2s[32], s_f2b[32];
    __shared__ __align__(16) float s_w3[256];        // [o][k]
    __shared__ __align__(16) float s_f3s[8], s_f3b[8], s_w4[8];
    __shared__ float s_cb4v;
    __shared__ __align__(16) float s_mw[4096];       // mlp_w [c][d]
    __shared__ __align__(16) float s_mb[64];
    __shared__ __align__(16) float s_h1[8][128];
    __shared__ __align__(16) float s_u[8][64];
    __shared__ __align__(16) float s_o[64][8];

    int t = threadIdx.x;
    if (t < 128) {
        float sc = ga1[t] * rsqrtf(rv1[t] + EPSB);
        s_f1s[t] = sc;
        s_f1b[t] = (cb1[t] - rm1[t]) * sc + be1[t];
    }
    for (int i = t; i < 4096; i += 256) {
        s_mw[i] = mlpw[i];
    }
    // w2 (128,32) row-major -> half2[o][cpair]
    for (int i = t; i < 2048; i += 256) {
        int o = i >> 6, cp = i & 63;
        s_w2h[o][cp] = __floats2half2_rn(w2[(2 * cp) * 32 + o], w2[(2 * cp + 1) * 32 + o]);
    }
    if (t < 32) {
        float sc = ga2[t] * rsqrtf(rv2[t] + EPSB);
        s_f2s[t] = sc;
        s_f2b[t] = (cb2[t] - rm2[t]) * sc + be2[t];
    }
    s_w3[t] = w3[t & 255];                 // 256 threads, 256 elems
    if (t < 8) {
        float sc = ga3[t] * rsqrtf(rv3[t] + EPSB);
        s_f3s[t] = sc;
        s_f3b[t] = (cb3[t] - rm3[t]) * sc + be3[t];
        s_w4[t] = w4[t];
    }
    if (t == 0) s_cb4v = cb4[0];
    if (t < 64) s_mb[t] = mlpb[t];
    __syncthreads();

    int wp = t >> 5, lane = t & 31;
    int p   = blockIdx.x * 8 + wp;         // flat pixel 0..38399
    int b   = p / HWSZ;
    int rem = p - b * HWSZ;
    int hh  = rem / WW;
    int wpx = rem - hh * WW;
    float gx = -1.0f + wpx * (2.0f / (WW - 1));
    float gy = -1.0f + hh  * (2.0f / (HH - 1));

    int r0 = rec[0], r1 = rec[1], r2 = rec[2];
    int rb = (b == 0) ? r0 : ((b == 1) ? r1 : r2);

    // channel mapping: this lane owns channels lane*4 .. lane*4+3 (128-ch tensors)
    float4 ev  = ldh4(g_Eh + (size_t)p * 64 + lane * 2);
    float4 f1s = *(const float4*)&s_f1s[lane * 4];
    float4 f1b = *(const float4*)&s_f1b[lane * 4];

    float sj[4], comj[4];
    float twj[4][4];
    int   trj[4][4];

#pragma unroll
    for (int j = 0; j < 4; j++) {
        if (j >= rb) { sj[j] = NEGV; comj[j] = 0.0f; continue; }
        // theta = ptm[b][j][0]  (after swapaxes, i=0)
        const float* th = ptm + (size_t)(b * 4 + j) * 24;
        float t00 = th[0], t01 = th[1], t02 = th[2];
        float t10 = th[3], t11 = th[4], t12 = th[5];
        float px = (t00 * gx + t01 * gy + t02 + 1.0f) * ((WW - 1) * 0.5f);
        float py = (t10 * gx + t11 * gy + t12 + 1.0f) * ((HH - 1) * 0.5f);
        float x0f = floorf(px), y0f = floorf(py);
        float wx = px - x0f, wy = py - y0f;
        int x0 = (int)x0f, y0 = (int)y0f;
        float wt[4] = { (1.0f - wx) * (1.0f - wy), wx * (1.0f - wy),
                        (1.0f - wx) * wy,          wx * wy };
        const __half2* Ab = g_Ah + (size_t)(b * 4 + j) * HWSZ * 64;
        const float* Mb = mask + (size_t)(b * 4 + j) * HWSZ;
        float com = 0.0f;
        float a0 = 0.f, a1 = 0.f, a2 = 0.f, a3 = 0.f;
#pragma unroll
        for (int tap = 0; tap < 4; tap++) {
            int xi = x0 + (tap & 1);
            int yi = y0 + (tap >> 1);
            bool inb = (xi >= 0) && (xi < WW) && (yi >= 0) && (yi < HH);
            int xc = min(max(xi, 0), WW - 1);
            int yc = min(max(yi, 0), HH - 1);
            float tw = inb ? wt[tap] : 0.0f;
            int rt = yc * WW + xc;
            twj[j][tap] = tw;
            trj[j][tap] = rt;
            com += tw * Mb[rt];
            float4 Av = ldh4(Ab + (size_t)rt * 64 + lane * 2);
            a0 = fmaf(tw, Av.x, a0);
            a1 = fmaf(tw, Av.y, a1);
            a2 = fmaf(tw, Av.z, a2);
            a3 = fmaf(tw, Av.w, a3);
        }
        comj[j] = com;

        // layer1 = relu( (A_interp + E) * bn_scale + bn_bias(folded with cb1) )
        float* hb = s_h1[wp];
        float4 h1v;
        h1v.x = fmaxf(0.0f, (a0 + ev.x) * f1s.x + f1b.x);
        h1v.y = fmaxf(0.0f, (a1 + ev.y) * f1s.y + f1b.y);
        h1v.z = fmaxf(0.0f, (a2 + ev.z) * f1s.z + f1b.z);
        h1v.w = fmaxf(0.0f, (a3 + ev.w) * f1s.w + f1b.w);
        *(float4*)&hb[lane * 4] = h1v;
        __syncwarp();

        // layer2: o = lane, 128-dot; w in half2, h fp32 broadcast, fp32 accumulate
        float acc2 = 0.0f;
        const __half2* wrow = &s_w2h[lane][0];
#pragma unroll
        for (int c8 = 0; c8 < 16; c8++) {
            uint4 wv = *(const uint4*)(wrow + c8 * 4);          // 8 channels of w2
            float4 hA = *(const float4*)(hb + c8 * 8);
            float4 hB = *(const float4*)(hb + c8 * 8 + 4);
            float2 w0 = __half22float2(*reinterpret_cast<__half2*>(&wv.x));
            float2 w1f = __half22float2(*reinterpret_cast<__half2*>(&wv.y));
            float2 w2f = __half22float2(*reinterpret_cast<__half2*>(&wv.z));
            float2 w3f = __half22float2(*reinterpret_cast<__half2*>(&wv.w));
            acc2 = fmaf(hA.x, w0.x, acc2);
            acc2 = fmaf(hA.y, w0.y, acc2);
            acc2 = fmaf(hA.z, w1f.x, acc2);
            acc2 = fmaf(hA.w, w1f.y, acc2);
            acc2 = fmaf(hB.x, w2f.x, acc2);
            acc2 = fmaf(hB.y, w2f.y, acc2);
            acc2 = fmaf(hB.z, w3f.x, acc2);
            acc2 = fmaf(hB.w, w3f.y, acc2);
        }
        __syncwarp();
        float h2 = fmaxf(0.0f, acc2 * s_f2s[lane] + s_f2b[lane]);

        // layer3: 32 -> 8 via per-lane partials + butterfly reduce
        float4 wa = *(const float4*)&s_w3[lane * 8];
        float4 wb = *(const float4*)&s_w3[lane * 8 + 4];
        float p3[8] = { h2 * wa.x, h2 * wa.y, h2 * wa.z, h2 * wa.w,
                        h2 * wb.x, h2 * wb.y, h2 * wb.z, h2 * wb.w };
#pragma unroll
        for (int off = 16; off >= 1; off >>= 1) {
#pragma unroll
            for (int k = 0; k < 8; k++)
                p3[k] += __shfl_xor_sync(0xffffffffu, p3[k], off);
        }
        // layer4: 8 -> 1
        float s4 = s_cb4v;
#pragma unroll
        for (int k = 0; k < 8; k++) {
            float h3 = fmaxf(0.0f, p3[k] * s_f3s[k] + s_f3b[k]);
            s4 = fmaf(h3, s_w4[k], s4);
        }
        sj[j] = (com == 0.0f) ? NEGV : fmaxf(0.0f, s4);
    }

    // softmax over j
    float m = fmaxf(fmaxf(sj[0], sj[1]), fmaxf(sj[2], sj[3]));
    float ex[4];
    float ssum = 0.0f;
#pragma unroll
    for (int j = 0; j < 4; j++) { ex[j] = expf(sj[j] - m); ssum += ex[j]; }
    float inv = 1.0f / ssum;

    // updated[c] = sum_j aw_j * com_j * nbr[j][c]  (this lane: c = lane*2, lane*2+1)
    float u0 = 0.0f, u1 = 0.0f;
#pragma unroll
    for (int j = 0; j < 4; j++) {
        if (j >= rb) continue;
        float wgt = ex[j] * inv * comj[j];
        if (wgt == 0.0f) continue;
        const float* xtb = g_xt + (size_t)(b * 4 + j) * HWSZ * 64;
        float n0 = 0.0f, n1 = 0.0f;
#pragma unroll
        for (int tap = 0; tap < 4; tap++) {
            float tw = twj[j][tap];
            float2 xv = *(const float2*)(xtb + (size_t)trj[j][tap] * 64 + lane * 2);
            n0 = fmaf(tw, xv.x, n0);
            n1 = fmaf(tw, xv.y, n1);
        }
        u0 = fmaf(wgt, n0, u0);
        u1 = fmaf(wgt, n1, u1);
    }

    s_u[wp][lane * 2]     = u0;
    s_u[wp][lane * 2 + 1] = u1;
    __syncwarp();

    // final mlp: out[d] = sum_c u[c] * mlp_w[c][d] + mlp_b[d]   (d = lane, lane+32)
    float acc0 = s_mb[lane], acc1 = s_mb[lane + 32];
    const float* ub = s_u[wp];
#pragma unroll 16
    for (int c = 0; c < 64; c++) {
        float uc = ub[c];
        acc0 = fmaf(uc, s_mw[c * 64 + lane],      acc0);
        acc1 = fmaf(uc, s_mw[c * 64 + lane + 32], acc1);
    }
    s_o[lane][wp]      = acc0;
    s_o[lane + 32][wp] = acc1;
    __syncthreads();

    // coalesced transposed store (8 consecutive pixels never cross batch: 12800 % 8 == 0)
    int pbase = blockIdx.x * 8;
    int bb = pbase / HWSZ;
    int rbase = pbase - bb * HWSZ;
#pragma unroll
    for (int e = t; e < 512; e += 256) {
        int d = e >> 3, pix = e & 7;
        out[((size_t)bb * CC + d) * HWSZ + rbase + pix] = s_o[d][pix];
    }
}

extern "C" void kernel_launch(void* const* d_in, const int* in_sizes, int n_in,
                              void* d_out, int out_size) {
    (void)in_sizes; (void)n_in; (void)out_size;
    const float* x    = (const float*)d_in[0];
    const float* mask = (const float*)d_in[1];
    const int*   rec  = (const int*)d_in[2];
    const float* ptm  = (const float*)d_in[3];
    const float* w1   = (const float*)d_in[4];
    const float* cb1  = (const float*)d_in[5];
    const float* ga1  = (const float*)d_in[6];
    const float* be1  = (const float*)d_in[7];
    const float* rm1  = (const float*)d_in[8];
    const float* rv1  = (const float*)d_in[9];
    const float* w2   = (const float*)d_in[10];
    const float* cb2  = (const float*)d_in[11];
    const float* ga2  = (const float*)d_in[12];
    const float* be2  = (const float*)d_in[13];
    const float* rm2  = (const float*)d_in[14];
    const float* rv2  = (const float*)d_in[15];
    const float* w3   = (const float*)d_in[16];
    const float* cb3  = (const float*)d_in[17];
    const float* ga3  = (const float*)d_in[18];
    const float* be3  = (const float*)d_in[19];
    const float* rm3  = (const float*)d_in[20];
    const float* rv3  = (const float*)d_in[21];
    const float* w4   = (const float*)d_in[22];
    const float* cb4  = (const float*)d_in[23];
    const float* mlpw = (const float*)d_in[24];
    const float* mlpb = (const float*)d_in[25];
    float* out = (float*)d_out;

    dim3 grid1(HWSZ / 64, 15);            // 200 pixel-tiles x 15 jobs (invalid jobs self-skip)
    disco_k1<<<grid1, 256>>>(x, rec, w1);

    disco_k2<<<(BB * HWSZ) / 8, 256>>>(mask, rec, ptm,
                                       cb1, ga1, be1, rm1, rv1,
                                       w2, cb2, ga2, be2, rm2, rv2,
                                       w3, cb3, ga3, be3, rm3, rv3,
                                       w4, cb4, mlpw, mlpb, out);
}

// round 5
// speedup vs baseline: 2.2072x; 1.7210x over previous
#include <cuda_runtime.h>
#include <cuda_fp16.h>
#include <math.h>

#define CC   64
#define HH   80
#define WW   160
#define HWSZ (HH * WW)      // 12800
#define BB   3
#define LL   4
#define EPSB 1e-5f
#define NEGV -1e30f

typedef unsigned int uint;

// Scratch:
//  g_Ah[b*4+j][pix][o/2]  conv partial (warped-neighbor half of layer1), channel-last, 128 ch, fp16
//  g_Eh[b][pix][o/2]      conv partial (ego half, node[b,0]), channel-last, 128 ch, fp16
//  g_xt[b*4+j][pix][c]    raw x transposed to channel-last (64 ch, fp32) for the updated-gather
//  g_S / g_C [b][pix][j]  scores (NEG-masked) and com values
__device__ __align__(16) __half2 g_Ah[(size_t)BB * LL * HWSZ * 64];  // 39.3 MB
__device__ __align__(16) __half2 g_Eh[(size_t)BB * HWSZ * 64];       // 9.8 MB
__device__ __align__(16) float   g_xt[(size_t)BB * LL * HWSZ * 64];  // 39.3 MB
__device__ __align__(16) float   g_S[(size_t)BB * HWSZ * 4];
__device__ __align__(16) float   g_C[(size_t)BB * HWSZ * 4];

// ---------------- f32x2 helpers ----------------
__device__ __forceinline__ unsigned long long pack2f(float a, float b) {
    unsigned long long r;
    asm("mov.b64 %0, {%1, %2};" : "=l"(r) : "f"(a), "f"(b));
    return r;
}
__device__ __forceinline__ float2 unpack2f(unsigned long long v) {
    float2 r;
    asm("mov.b64 {%0, %1}, %2;" : "=f"(r.x), "=f"(r.y) : "l"(v));
    return r;
}
__device__ __forceinline__ void fma2(unsigned long long &d, unsigned long long a, unsigned long long b) {
    asm("fma.rn.f32x2 %0, %1, %2, %0;" : "+l"(d) : "l"(a), "l"(b));
}
__device__ __forceinline__ float2 h2f(uint u) {
    return __half22float2(*reinterpret_cast<__half2*>(&u));
}

// ---------------- Kernel 1: per-agent GEMM  [12800 x 64] @ [64 x 128] ----------------
__global__ __launch_bounds__(256) void disco_k1(const float* __restrict__ x,
                                                const int* __restrict__ rec,
                                                const float* __restrict__ w1) {
    __shared__ __align__(16) float Xs[64][68];
    __shared__ __align__(16) float Ws[64][128];

    int job   = blockIdx.y;
    int ptile = blockIdx.x * 64;
    int r0 = rec[0], r1 = rec[1], r2 = rec[2];

    const float* src;
    __half2* dst;
    int wrow0;
    bool isA = (job < 12);
    if (isA) {
        int b = job >> 2, j = job & 3;
        int rb   = (b == 0) ? r0 : ((b == 1) ? r1 : r2);
        if (j >= rb) return;
        int aoff = (b == 0) ? 0 : ((b == 1) ? r0 : (r0 + r1));
        src   = x + (size_t)(aoff + j) * CC * HWSZ;
        dst   = g_Ah + (size_t)job * HWSZ * 64;
        wrow0 = 0;
    } else {
        int b = job - 12;
        int aoff = (b == 0) ? 0 : ((b == 1) ? r0 : (r0 + r1));
        src   = x + (size_t)aoff * CC * HWSZ;
        dst   = g_Eh + (size_t)b * HWSZ * 64;
        wrow0 = 64;
    }

    int t = threadIdx.x;
    for (int i = t; i < 64 * 64; i += 256) {
        int c = i >> 6, p = i & 63;
        Xs[c][p] = src[c * HWSZ + ptile + p];
    }
    for (int i = t; i < 64 * 128; i += 256) {
        int c = i >> 7, o = i & 127;
        Ws[c][o] = w1[(wrow0 + c) * 128 + o];
    }
    __syncthreads();

    int tn = t & 15, tp = t >> 4;

    unsigned long long acc[4][4];
#pragma unroll
    for (int i = 0; i < 4; i++)
#pragma unroll
        for (int j = 0; j < 4; j++) acc[i][j] = 0ULL;

#pragma unroll 8
    for (int k = 0; k < 64; k++) {
        float4 xv = *(const float4*)&Xs[k][tp * 4];
        ulonglong2 wa = *(const ulonglong2*)&Ws[k][tn * 4];
        ulonglong2 wb = *(const ulonglong2*)&Ws[k][64 + tn * 4];
        unsigned long long x0 = pack2f(xv.x, xv.x);
        unsigned long long x1 = pack2f(xv.y, xv.y);
        unsigned long long x2 = pack2f(xv.z, xv.z);
        unsigned long long x3 = pack2f(xv.w, xv.w);
        fma2(acc[0][0], x0, wa.x); fma2(acc[0][1], x0, wa.y);
        fma2(acc[0][2], x0, wb.x); fma2(acc[0][3], x0, wb.y);
        fma2(acc[1][0], x1, wa.x); fma2(acc[1][1], x1, wa.y);
        fma2(acc[1][2], x1, wb.x); fma2(acc[1][3], x1, wb.y);
        fma2(acc[2][0], x2, wa.x); fma2(acc[2][1], x2, wa.y);
        fma2(acc[2][2], x2, wb.x); fma2(acc[2][3], x2, wb.y);
        fma2(acc[3][0], x3, wa.x); fma2(acc[3][1], x3, wa.y);
        fma2(acc[3][2], x3, wb.x); fma2(acc[3][3], x3, wb.y);
    }

#pragma unroll
    for (int i = 0; i < 4; i++) {
        __half2* dp = dst + (size_t)(ptile + tp * 4 + i) * 64;
        float2 f0 = unpack2f(acc[i][0]);
        float2 f1 = unpack2f(acc[i][1]);
        float2 f2 = unpack2f(acc[i][2]);
        float2 f3 = unpack2f(acc[i][3]);
        __half2 h0 = __float22half2_rn(f0);
        __half2 h1 = __float22half2_rn(f1);
        __half2 h2v = __float22half2_rn(f2);
        __half2 h3 = __float22half2_rn(f3);
        uint2 w0; w0.x = *(uint*)&h0; w0.y = *(uint*)&h1;
        uint2 w1v; w1v.x = *(uint*)&h2v; w1v.y = *(uint*)&h3;
        *(uint2*)(dp + tn * 2)      = w0;
        *(uint2*)(dp + 32 + tn * 2) = w1v;
    }

    if (isA) {
        float* xt = g_xt + (size_t)job * HWSZ * 64;
        for (int i = t; i < 64 * 64; i += 256) {
            int p = i >> 6, c = i & 63;
            xt[(size_t)(ptile + p) * 64 + c] = Xs[c][p];
        }
    }
}

// ---------------- Kernel 2a: score pipeline as tile-GEMM ----------------
// grid = (200 pixel-tiles, 12 (b,j)); block 256
__global__ __launch_bounds__(256) void disco_k2a(
    const float* __restrict__ mask,
    const int* __restrict__ rec, const float* __restrict__ ptm,
    const float* __restrict__ cb1, const float* __restrict__ ga1,
    const float* __restrict__ be1, const float* __restrict__ rm1, const float* __restrict__ rv1,
    const float* __restrict__ w2, const float* __restrict__ cb2, const float* __restrict__ ga2,
    const float* __restrict__ be2, const float* __restrict__ rm2, const float* __restrict__ rv2,
    const float* __restrict__ w3, const float* __restrict__ cb3, const float* __restrict__ ga3,
    const float* __restrict__ be3, const float* __restrict__ rm3, const float* __restrict__ rv3,
    const float* __restrict__ w4, const float* __restrict__ cb4)
{
    __shared__ __align__(16) uint  s_h1[64 * 68];    // h1 half2 [pix][k2]
    __shared__ __align__(16) uint  s_w2p[64 * 36];   // w2 half2 k-pairs [k2][o]
    __shared__ __align__(16) float s_h2[64 * 36];    // h2 [pix][o]
    __shared__ __align__(16) float s_f1s[128], s_f1b[128];
    __shared__ __align__(16) float s_f2s[32], s_f2b[32];
    __shared__ __align__(16) float s_w3[256];
    __shared__ __align__(16) float s_f3s[8], s_f3b[8], s_w4v[8];
    __shared__ float s_cb4v;
    __shared__ float s_com[64];

    int job = blockIdx.y;
    int b = job >> 2, j = job & 3;
    if (j >= rec[b]) return;

    int t = threadIdx.x;
    if (t < 128) {
        float sc = ga1[t] * rsqrtf(rv1[t] + EPSB);
        s_f1s[t] = sc;
        s_f1b[t] = (cb1[t] - rm1[t]) * sc + be1[t];
    }
    for (int i = t; i < 2048; i += 256) {
        int k2 = i >> 5, o = i & 31;
        __half2 hp = __floats2half2_rn(w2[(2 * k2) * 32 + o], w2[(2 * k2 + 1) * 32 + o]);
        s_w2p[k2 * 36 + o] = *(uint*)&hp;
    }
    if (t < 32) {
        float sc = ga2[t] * rsqrtf(rv2[t] + EPSB);
        s_f2s[t] = sc;
        s_f2b[t] = (cb2[t] - rm2[t]) * sc + be2[t];
    }
    s_w3[t] = w3[t & 255];
    if (t < 8) {
        float sc = ga3[t] * rsqrtf(rv3[t] + EPSB);
        s_f3s[t] = sc;
        s_f3b[t] = (cb3[t] - rm3[t]) * sc + be3[t];
        s_w4v[t] = w4[t];
    }
    if (t == 0) s_cb4v = cb4[0];
    __syncthreads();

    int ptile = blockIdx.x * 64;
    const float* th = ptm + (size_t)(b * 4 + j) * 24;
    float t00 = th[0], t01 = th[1], t02 = th[2];
    float t10 = th[3], t11 = th[4], t12 = th[5];

    const __half2* Ab = g_Ah + (size_t)job * HWSZ * 64;
    const __half2* Eb = g_Eh + (size_t)b * HWSZ * 64;
    const float*   Mb = mask + (size_t)(b * 4 + j) * HWSZ;

    // ---- Stage 1: gather A taps + E, bn1+relu -> s_h1 (fp16). 2 passes of 32 pixels.
    int pix0 = t >> 3, cg = t & 7;   // 16 channels per thread
#pragma unroll
    for (int pass = 0; pass < 2; pass++) {
        int pix = pix0 + (pass << 5);
        int pg  = ptile + pix;
        int hh  = pg / WW;
        int wpx = pg - hh * WW;
        float gx = -1.0f + wpx * (2.0f / (WW - 1));
        float gy = -1.0f + hh  * (2.0f / (HH - 1));
        float px = (t00 * gx + t01 * gy + t02 + 1.0f) * ((WW - 1) * 0.5f);
        float py = (t10 * gx + t11 * gy + t12 + 1.0f) * ((HH - 1) * 0.5f);
        float x0f = floorf(px), y0f = floorf(py);
        float wx = px - x0f, wy = py - y0f;
        int x0 = (int)x0f, y0 = (int)y0f;
        float wt4[4] = { (1.0f - wx) * (1.0f - wy), wx * (1.0f - wy),
                         (1.0f - wx) * wy,          wx * wy };
        float acc[16];
#pragma unroll
        for (int i = 0; i < 16; i++) acc[i] = 0.0f;
        float comv = 0.0f;
#pragma unroll
        for (int tap = 0; tap < 4; tap++) {
            int xi = x0 + (tap & 1), yi = y0 + (tap >> 1);
            bool inb = (xi >= 0) && (xi < WW) && (yi >= 0) && (yi < HH);
            int xc = min(max(xi, 0), WW - 1);
            int yc = min(max(yi, 0), HH - 1);
            float tw = inb ? wt4[tap] : 0.0f;
            int rt = yc * WW + xc;
            if (cg == 0) comv += tw * Mb[rt];
            const uint4* Ap = (const uint4*)(Ab + (size_t)rt * 64 + cg * 8);
            uint4 v0 = Ap[0], v1 = Ap[1];
            float2 f;
            f = h2f(v0.x); acc[0]  = fmaf(tw, f.x, acc[0]);  acc[1]  = fmaf(tw, f.y, acc[1]);
            f = h2f(v0.y); acc[2]  = fmaf(tw, f.x, acc[2]);  acc[3]  = fmaf(tw, f.y, acc[3]);
            f = h2f(v0.z); acc[4]  = fmaf(tw, f.x, acc[4]);  acc[5]  = fmaf(tw, f.y, acc[5]);
            f = h2f(v0.w); acc[6]  = fmaf(tw, f.x, acc[6]);  acc[7]  = fmaf(tw, f.y, acc[7]);
            f = h2f(v1.x); acc[8]  = fmaf(tw, f.x, acc[8]);  acc[9]  = fmaf(tw, f.y, acc[9]);
            f = h2f(v1.y); acc[10] = fmaf(tw, f.x, acc[10]); acc[11] = fmaf(tw, f.y, acc[11]);
            f = h2f(v1.z); acc[12] = fmaf(tw, f.x, acc[12]); acc[13] = fmaf(tw, f.y, acc[13]);
            f = h2f(v1.w); acc[14] = fmaf(tw, f.x, acc[14]); acc[15] = fmaf(tw, f.y, acc[15]);
        }
        const uint4* Ep = (const uint4*)(Eb + (size_t)pg * 64 + cg * 8);
        uint4 e0 = Ep[0], e1 = Ep[1];
        int c0 = cg * 16;
        uint ow[8];
        uint ev[8] = { e0.x, e0.y, e0.z, e0.w, e1.x, e1.y, e1.z, e1.w };
#pragma unroll
        for (int i = 0; i < 8; i++) {
            float2 ef = h2f(ev[i]);
            float2 sv = *(const float2*)&s_f1s[c0 + 2 * i];
            float2 bv = *(const float2*)&s_f1b[c0 + 2 * i];
            float h0 = fmaxf(0.0f, (acc[2 * i]     + ef.x) * sv.x + bv.x);
            float h1 = fmaxf(0.0f, (acc[2 * i + 1] + ef.y) * sv.y + bv.y);
            __half2 hp = __floats2half2_rn(h0, h1);
            ow[i] = *(uint*)&hp;
        }
        uint4 wv0; wv0.x = ow[0]; wv0.y = ow[1]; wv0.z = ow[2]; wv0.w = ow[3];
        uint4 wv1; wv1.x = ow[4]; wv1.y = ow[5]; wv1.z = ow[6]; wv1.w = ow[7];
        *(uint4*)&s_h1[pix * 68 + cg * 8]     = wv0;
        *(uint4*)&s_h1[pix * 68 + cg * 8 + 4] = wv1;
        if (cg == 0) s_com[pix] = comv;
    }
    __syncthreads();

    // ---- Stage 2: layer2 GEMM [64 x 128] @ [128 x 32], thread = 2 pix x 4 outs
    {
        int tn = t & 7, tp = t >> 3;
        float acc[2][4];
#pragma unroll
        for (int p = 0; p < 2; p++)
#pragma unroll
            for (int o = 0; o < 4; o++) acc[p][o] = 0.0f;
        const uint* h0p = &s_h1[(2 * tp) * 68];
        const uint* h1p = &s_h1[(2 * tp + 1) * 68];
#pragma unroll 4
        for (int k2 = 0; k2 < 64; k2++) {
            float2 ha = h2f(h0p[k2]);
            float2 hb = h2f(h1p[k2]);
            uint4 wv = *(const uint4*)&s_w2p[k2 * 36 + tn * 4];
            float2 w0 = h2f(wv.x), w1f = h2f(wv.y), w2f = h2f(wv.z), w3f = h2f(wv.w);
            acc[0][0] = fmaf(ha.x, w0.x,  fmaf(ha.y, w0.y,  acc[0][0]));
            acc[0][1] = fmaf(ha.x, w1f.x, fmaf(ha.y, w1f.y, acc[0][1]));
            acc[0][2] = fmaf(ha.x, w2f.x, fmaf(ha.y, w2f.y, acc[0][2]));
            acc[0][3] = fmaf(ha.x, w3f.x, fmaf(ha.y, w3f.y, acc[0][3]));
            acc[1][0] = fmaf(hb.x, w0.x,  fmaf(hb.y, w0.y,  acc[1][0]));
            acc[1][1] = fmaf(hb.x, w1f.x, fmaf(hb.y, w1f.y, acc[1][1]));
            acc[1][2] = fmaf(hb.x, w2f.x, fmaf(hb.y, w2f.y, acc[1][2]));
            acc[1][3] = fmaf(hb.x, w3f.x, fmaf(hb.y, w3f.y, acc[1][3]));
        }
        float4 f2s = *(const float4*)&s_f2s[tn * 4];
        float4 f2b = *(const float4*)&s_f2b[tn * 4];
#pragma unroll
        for (int p = 0; p < 2; p++) {
            float4 hv;
            hv.x = fmaxf(0.0f, acc[p][0] * f2s.x + f2b.x);
            hv.y = fmaxf(0.0f, acc[p][1] * f2s.y + f2b.y);
            hv.z = fmaxf(0.0f, acc[p][2] * f2s.z + f2b.z);
            hv.w = fmaxf(0.0f, acc[p][3] * f2s.w + f2b.w);
            *(float4*)&s_h2[(2 * tp + p) * 36 + tn * 4] = hv;
        }
    }
    __syncthreads();

    // ---- Stage 3: layers 3/4 -> score, write scratch. 64 threads (1 pixel each).
    if (t < 64) {
        int pix = t;
        float p3[8];
#pragma unroll
        for (int o = 0; o < 8; o++) p3[o] = 0.0f;
#pragma unroll
        for (int k4 = 0; k4 < 8; k4++) {
            float4 hv = *(const float4*)&s_h2[pix * 36 + k4 * 4];
            float hk[4] = { hv.x, hv.y, hv.z, hv.w };
#pragma unroll
            for (int kk = 0; kk < 4; kk++) {
                float4 wa = *(const float4*)&s_w3[(k4 * 4 + kk) * 8];
                float4 wb = *(const float4*)&s_w3[(k4 * 4 + kk) * 8 + 4];
                p3[0] = fmaf(hk[kk], wa.x, p3[0]);
                p3[1] = fmaf(hk[kk], wa.y, p3[1]);
                p3[2] = fmaf(hk[kk], wa.z, p3[2]);
                p3[3] = fmaf(hk[kk], wa.w, p3[3]);
                p3[4] = fmaf(hk[kk], wb.x, p3[4]);
                p3[5] = fmaf(hk[kk], wb.y, p3[5]);
                p3[6] = fmaf(hk[kk], wb.z, p3[6]);
                p3[7] = fmaf(hk[kk], wb.w, p3[7]);
            }
        }
        float s4 = s_cb4v;
#pragma unroll
        for (int o = 0; o < 8; o++) {
            float h3 = fmaxf(0.0f, p3[o] * s_f3s[o] + s_f3b[o]);
            s4 = fmaf(h3, s_w4v[o], s4);
        }
        float comv = s_com[pix];
        float sc = (comv == 0.0f) ? NEGV : fmaxf(0.0f, s4);
        size_t base = ((size_t)b * HWSZ + ptile + pix) * 4 + j;
        g_S[base] = sc;
        g_C[base] = comv;
    }
}

// ---------------- Kernel 2b: softmax + update gather + final MLP GEMM ----------------
// grid = 600 (64 pixels each); block 256
__global__ __launch_bounds__(256) void disco_k2b(
    const int* __restrict__ rec, const float* __restrict__ ptm,
    const float* __restrict__ mlpw, const float* __restrict__ mlpb,
    float* __restrict__ out)
{
    __shared__ __align__(16) float s_u[64 * 68];   // u[pix][c] then reused as o[d][pix]
    __shared__ __align__(16) float s_mw[64 * 68];  // mlp_w [c][d] padded
    __shared__ __align__(16) float s_mb[64];

    int t = threadIdx.x;
    for (int i = t; i < 4096; i += 256) {
        int c = i >> 6, d = i & 63;
        s_mw[c * 68 + d] = mlpw[i];
    }
    if (t < 64) s_mb[t] = mlpb[t];

    int gt   = blockIdx.x * 64;
    int b    = gt / HWSZ;
    int prem = gt - b * HWSZ;
    int rb   = rec[b];

    // ---- Phase A: softmax + x_t gather -> s_u
    {
        int pix = t >> 2, cg = t & 3;       // 16 channels
        int pr  = prem + pix;
        size_t sbase = ((size_t)b * HWSZ + pr) * 4;
        float4 sc = *(const float4*)&g_S[sbase];
        float4 cm = *(const float4*)&g_C[sbase];
        float sj[4] = { sc.x, sc.y, sc.z, sc.w };
        float cj[4] = { cm.x, cm.y, cm.z, cm.w };
#pragma unroll
        for (int j = 0; j < 4; j++)
            if (j >= rb) { sj[j] = NEGV; cj[j] = 0.0f; }
        float m = fmaxf(fmaxf(sj[0], sj[1]), fmaxf(sj[2], sj[3]));
        float ex[4], ssum = 0.0f;
#pragma unroll
        for (int j = 0; j < 4; j++) { ex[j] = expf(sj[j] - m); ssum += ex[j]; }
        float inv = 1.0f / ssum;

        int hh  = pr / WW;
        int wpx = pr - hh * WW;
        float gx = -1.0f + wpx * (2.0f / (WW - 1));
        float gy = -1.0f + hh  * (2.0f / (HH - 1));

        float u[16];
#pragma unroll
        for (int i = 0; i < 16; i++) u[i] = 0.0f;

        for (int j = 0; j < 4; j++) {
            if (j >= rb) continue;
            float wgt = ex[j] * inv * cj[j];
            if (wgt == 0.0f) continue;
            const float* th = ptm + (size_t)(b * 4 + j) * 24;
            float t00 = th[0], t01 = th[1], t02 = th[2];
            float t10 = th[3], t11 = th[4], t12 = th[5];
            float px = (t00 * gx + t01 * gy + t02 + 1.0f) * ((WW - 1) * 0.5f);
            float py = (t10 * gx + t11 * gy + t12 + 1.0f) * ((HH - 1) * 0.5f);
            float x0f = floorf(px), y0f = floorf(py);
            float wx = px - x0f, wy = py - y0f;
            int x0 = (int)x0f, y0 = (int)y0f;
            float wt4[4] = { (1.0f - wx) * (1.0f - wy), wx * (1.0f - wy),
                             (1.0f - wx) * wy,          wx * wy };
            const float* xtb = g_xt + (size_t)(b * 4 + j) * HWSZ * 64 + cg * 16;
            float n[16];
#pragma unroll
            for (int i = 0; i < 16; i++) n[i] = 0.0f;
#pragma unroll
            for (int tap = 0; tap < 4; tap++) {
                int xi = x0 + (tap & 1), yi = y0 + (tap >> 1);
                bool inb = (xi >= 0) && (xi < WW) && (yi >= 0) && (yi < HH);
                int xc = min(max(xi, 0), WW - 1);
                int yc = min(max(yi, 0), HH - 1);
                float tw = inb ? wt4[tap] : 0.0f;
                const float4* xp = (const float4*)(xtb + (size_t)(yc * WW + xc) * 64);
#pragma unroll
                for (int q = 0; q < 4; q++) {
                    float4 v = xp[q];
                    n[q * 4 + 0] = fmaf(tw, v.x, n[q * 4 + 0]);
                    n[q * 4 + 1] = fmaf(tw, v.y, n[q * 4 + 1]);
                    n[q * 4 + 2] = fmaf(tw, v.z, n[q * 4 + 2]);
                    n[q * 4 + 3] = fmaf(tw, v.w, n[q * 4 + 3]);
                }
            }
#pragma unroll
            for (int i = 0; i < 16; i++) u[i] = fmaf(wgt, n[i], u[i]);
        }
#pragma unroll
        for (int q = 0; q < 4; q++) {
            float4 v = make_float4(u[q * 4], u[q * 4 + 1], u[q * 4 + 2], u[q * 4 + 3]);
            *(float4*)&s_u[pix * 68 + cg * 16 + q * 4] = v;
        }
    }
    __syncthreads();

    // ---- Phase B: final MLP GEMM [64 x 64] @ [64 x 64], thread = 4 pix x 4 d
    int tp = t >> 4, tn = t & 15;
    float acc[4][4];
#pragma unroll
    for (int p = 0; p < 4; p++)
#pragma unroll
        for (int d = 0; d < 4; d++) acc[p][d] = 0.0f;
#pragma unroll 4
    for (int k4 = 0; k4 < 16; k4++) {
        float4 uv[4];
#pragma unroll
        for (int p = 0; p < 4; p++)
            uv[p] = *(const float4*)&s_u[(tp * 4 + p) * 68 + k4 * 4];
        float4 wv[4];
#pragma unroll
        for (int kk = 0; kk < 4; kk++)
            wv[kk] = *(const float4*)&s_mw[(k4 * 4 + kk) * 68 + tn * 4];
#pragma unroll
        for (int p = 0; p < 4; p++) {
            acc[p][0] = fmaf(uv[p].x, wv[0].x, acc[p][0]);
            acc[p][1] = fmaf(uv[p].x, wv[0].y, acc[p][1]);
            acc[p][2] = fmaf(uv[p].x, wv[0].z, acc[p][2]);
            acc[p][3] = fmaf(uv[p].x, wv[0].w, acc[p][3]);
            acc[p][0] = fmaf(uv[p].y, wv[1].x, acc[p][0]);
            acc[p][1] = fmaf(uv[p].y, wv[1].y, acc[p][1]);
            acc[p][2] = fmaf(uv[p].y, wv[1].z, acc[p][2]);
            acc[p][3] = fmaf(uv[p].y, wv[1].w, acc[p][3]);
            acc[p][0] = fmaf(uv[p].z, wv[2].x, acc[p][0]);
            acc[p][1] = fmaf(uv[p].z, wv[2].y, acc[p][1]);
            acc[p][2] = fmaf(uv[p].z, wv[2].z, acc[p][2]);
            acc[p][3] = fmaf(uv[p].z, wv[2].w, acc[p][3]);
            acc[p][0] = fmaf(uv[p].w, wv[3].x, acc[p][0]);
            acc[p][1] = fmaf(uv[p].w, wv[3].y, acc[p][1]);
            acc[p][2] = fmaf(uv[p].w, wv[3].z, acc[p][2]);
            acc[p][3] = fmaf(uv[p].w, wv[3].w, acc[p][3]);
        }
    }
    float4 bias = *(const float4*)&s_mb[tn * 4];
    __syncthreads();    // all reads of s_u done -> safe to overwrite as o[d][pix]
#pragma unroll
    for (int d = 0; d < 4; d++) {
        float bd = (d == 0) ? bias.x : (d == 1) ? bias.y : (d == 2) ? bias.z : bias.w;
        float4 ov = make_float4(acc[0][d] + bd, acc[1][d] + bd, acc[2][d] + bd, acc[3][d] + bd);
        *(float4*)&s_u[(tn * 4 + d) * 68 + tp * 4] = ov;
    }
    __syncthreads();

    for (int i = t; i < 4096; i += 256) {
        int d = i >> 6, pp = i & 63;
        out[((size_t)b * CC + d) * HWSZ + prem + pp] = s_u[d * 68 + pp];
    }
}

extern "C" void kernel_launch(void* const* d_in, const int* in_sizes, int n_in,
                              void* d_out, int out_size) {
    (void)in_sizes; (void)n_in; (void)out_size;
    const float* x    = (const float*)d_in[0];
    const float* mask = (const float*)d_in[1];
    const int*   rec  = (const int*)d_in[2];
    const float* ptm  = (const float*)d_in[3];
    const float* w1   = (const float*)d_in[4];
    const float* cb1  = (const float*)d_in[5];
    const float* ga1  = (const float*)d_in[6];
    const float* be1  = (const float*)d_in[7];
    const float* rm1  = (const float*)d_in[8];
    const float* rv1  = (const float*)d_in[9];
    const float* w2   = (const float*)d_in[10];
    const float* cb2  = (const float*)d_in[11];
    const float* ga2  = (const float*)d_in[12];
    const float* be2  = (const float*)d_in[13];
    const float* rm2  = (const float*)d_in[14];
    const float* rv2  = (const float*)d_in[15];
    const float* w3   = (const float*)d_in[16];
    const float* cb3  = (const float*)d_in[17];
    const float* ga3  = (const float*)d_in[18];
    const float* be3  = (const float*)d_in[19];
    const float* rm3  = (const float*)d_in[20];
    const float* rv3  = (const float*)d_in[21];
    const float* w4   = (const float*)d_in[22];
    const float* cb4  = (const float*)d_in[23];
    const float* mlpw = (const float*)d_in[24];
    const float* mlpb = (const float*)d_in[25];
    float* out = (float*)d_out;

    dim3 grid1(HWSZ / 64, 15);
    disco_k1<<<grid1, 256>>>(x, rec, w1);

    dim3 grid2a(HWSZ / 64, 12);
    disco_k2a<<<grid2a, 256>>>(mask, rec, ptm,
                               cb1, ga1, be1, rm1, rv1,
                               w2, cb2, ga2, be2, rm2, rv2,
                               w3, cb3, ga3, be3, rm3, rv3,
                               w4, cb4);

    disco_k2b<<<(BB * HWSZ) / 64, 256>>>(rec, ptm, mlpw, mlpb, out);
}

// round 6
// speedup vs baseline: 2.3226x; 1.0523x over previous
#include <cuda_runtime.h>
#include <cuda_fp16.h>
#include <math.h>

#define CC   64
#define HH   80
#define WW   160
#define HWSZ (HH * WW)      // 12800
#define BB   3
#define LL   4
#define EPSB 1e-5f
#define NEGV -1e30f

typedef unsigned int uint;

// Scratch:
//  g_Ah[b*4+j][pix][o/2]  conv partial (warped-neighbor half of layer1), channel-last, 128 ch, fp16
//  g_Eh[b][pix][o/2]      conv partial (ego half, node[b,0]), channel-last, 128 ch, fp16
//  g_xt[b*4+j][pix][c]    raw x transposed to channel-last (64 ch, fp32) for the updated-gather
//  g_S / g_C [b][pix][j]  scores (NEG-masked) and com values
__device__ __align__(16) __half2 g_Ah[(size_t)BB * LL * HWSZ * 64];  // 39.3 MB
__device__ __align__(16) __half2 g_Eh[(size_t)BB * HWSZ * 64];       // 9.8 MB
__device__ __align__(16) float   g_xt[(size_t)BB * LL * HWSZ * 64];  // 39.3 MB
__device__ __align__(16) float   g_S[(size_t)BB * HWSZ * 4];
__device__ __align__(16) float   g_C[(size_t)BB * HWSZ * 4];

// ---------------- f32x2 helpers ----------------
__device__ __forceinline__ unsigned long long pack2f(float a, float b) {
    unsigned long long r;
    asm("mov.b64 %0, {%1, %2};" : "=l"(r) : "f"(a), "f"(b));
    return r;
}
__device__ __forceinline__ float2 unpack2f(unsigned long long v) {
    float2 r;
    asm("mov.b64 {%0, %1}, %2;" : "=f"(r.x), "=f"(r.y) : "l"(v));
    return r;
}
__device__ __forceinline__ void fma2(unsigned long long &d, unsigned long long a, unsigned long long b) {
    asm("fma.rn.f32x2 %0, %1, %2, %0;" : "+l"(d) : "l"(a), "l"(b));
}
__device__ __forceinline__ float2 h2f(uint u) {
    return __half22float2(*reinterpret_cast<__half2*>(&u));
}

// ---------------- Kernel 1: per-agent GEMM  [12800 x 64] @ [64 x 128] ----------------
// 128-pixel tiles; thread tile = 8 pixels x 8 outs.
// jobs 0..11  : A for (b = job/4, j = job%4)  using w1 rows [0,64)  + x_t transpose writeback
// jobs 12..14 : E for b = job-12              using w1 rows [64,128)
__global__ __launch_bounds__(256, 2) void disco_k1(const float* __restrict__ x,
                                                   const int* __restrict__ rec,
                                                   const float* __restrict__ w1) {
    __shared__ __align__(16) float Xs[64][132];    // [k][pixel], padded for transpose pass
    __shared__ __align__(16) float Ws[64][128];    // [k][o]

    int job   = blockIdx.y;
    int ptile = blockIdx.x * 128;
    int r0 = rec[0], r1 = rec[1], r2 = rec[2];

    const float* src;
    __half2* dst;
    int wrow0;
    bool isA = (job < 12);
    if (isA) {
        int b = job >> 2, j = job & 3;
        int rb   = (b == 0) ? r0 : ((b == 1) ? r1 : r2);
        if (j >= rb) return;
        int aoff = (b == 0) ? 0 : ((b == 1) ? r0 : (r0 + r1));
        src   = x + (size_t)(aoff + j) * CC * HWSZ;
        dst   = g_Ah + (size_t)job * HWSZ * 64;
        wrow0 = 0;
    } else {
        int b = job - 12;
        int aoff = (b == 0) ? 0 : ((b == 1) ? r0 : (r0 + r1));
        src   = x + (size_t)aoff * CC * HWSZ;
        dst   = g_Eh + (size_t)b * HWSZ * 64;
        wrow0 = 64;
    }

    int t = threadIdx.x;
    for (int i = t; i < 64 * 128; i += 256) {
        int c = i >> 7, p = i & 127;
        Xs[c][p] = src[c * HWSZ + ptile + p];
    }
    for (int i = t; i < 64 * 128; i += 256) {
        int c = i >> 7, o = i & 127;
        Ws[c][o] = w1[(wrow0 + c) * 128 + o];
    }
    __syncthreads();

    // thread (tn, tp): 8 pixels (tp*8..) x 8 outs {tn*4..+3} U {64+tn*4..+3}
    int tn = t & 15, tp = t >> 4;

    unsigned long long acc[8][4];
#pragma unroll
    for (int i = 0; i < 8; i++)
#pragma unroll
        for (int j = 0; j < 4; j++) acc[i][j] = 0ULL;

#pragma unroll 4
    for (int k = 0; k < 64; k++) {
        float4 xa = *(const float4*)&Xs[k][tp * 8];
        float4 xb = *(const float4*)&Xs[k][tp * 8 + 4];
        ulonglong2 wa = *(const ulonglong2*)&Ws[k][tn * 4];
        ulonglong2 wb = *(const ulonglong2*)&Ws[k][64 + tn * 4];
        float xv[8] = { xa.x, xa.y, xa.z, xa.w, xb.x, xb.y, xb.z, xb.w };
#pragma unroll
        for (int pi = 0; pi < 8; pi++) {
            unsigned long long xp = pack2f(xv[pi], xv[pi]);
            fma2(acc[pi][0], xp, wa.x);
            fma2(acc[pi][1], xp, wa.y);
            fma2(acc[pi][2], xp, wb.x);
            fma2(acc[pi][3], xp, wb.y);
        }
    }

#pragma unroll
    for (int i = 0; i < 8; i++) {
        __half2* dp = dst + (size_t)(ptile + tp * 8 + i) * 64;
        float2 f0 = unpack2f(acc[i][0]);
        float2 f1 = unpack2f(acc[i][1]);
        float2 f2 = unpack2f(acc[i][2]);
        float2 f3 = unpack2f(acc[i][3]);
        __half2 h0 = __float22half2_rn(f0);
        __half2 h1 = __float22half2_rn(f1);
        __half2 h2v = __float22half2_rn(f2);
        __half2 h3 = __float22half2_rn(f3);
        uint2 w0; w0.x = *(uint*)&h0; w0.y = *(uint*)&h1;
        uint2 w1v; w1v.x = *(uint*)&h2v; w1v.y = *(uint*)&h3;
        *(uint2*)(dp + tn * 2)      = w0;
        *(uint2*)(dp + 32 + tn * 2) = w1v;
    }

    if (isA) {
        float* xt = g_xt + (size_t)job * HWSZ * 64;
        for (int i = t; i < 64 * 128; i += 256) {
            int p = i >> 6, c = i & 63;
            xt[(size_t)(ptile + p) * 64 + c] = Xs[c][p];
        }
    }
}

// ---------------- Kernel 2a: score pipeline as tile-GEMM ----------------
// grid = (200 pixel-tiles, 12 (b,j)); block 256
__global__ __launch_bounds__(256) void disco_k2a(
    const float* __restrict__ mask,
    const int* __restrict__ rec, const float* __restrict__ ptm,
    const float* __restrict__ cb1, const float* __restrict__ ga1,
    const float* __restrict__ be1, const float* __restrict__ rm1, const float* __restrict__ rv1,
    const float* __restrict__ w2, const float* __restrict__ cb2, const float* __restrict__ ga2,
    const float* __restrict__ be2, const float* __restrict__ rm2, const float* __restrict__ rv2,
    const float* __restrict__ w3, const float* __restrict__ cb3, const float* __restrict__ ga3,
    const float* __restrict__ be3, const float* __restrict__ rm3, const float* __restrict__ rv3,
    const float* __restrict__ w4, const float* __restrict__ cb4)
{
    __shared__ __align__(16) uint  s_h1[64 * 68];    // h1 half2 [pix][k2]
    __shared__ __align__(16) uint  s_w2p[64 * 36];   // w2 half2 k-pairs [k2][o]
    __shared__ __align__(16) float s_h2[64 * 36];    // h2 [pix][o]
    __shared__ __align__(16) float s_f1s[128], s_f1b[128];
    __shared__ __align__(16) float s_f2s[32], s_f2b[32];
    __shared__ __align__(16) float s_w3[256];
    __shared__ __align__(16) float s_f3s[8], s_f3b[8], s_w4v[8];
    __shared__ float s_cb4v;
    __shared__ float s_com[64];

    int job = blockIdx.y;
    int b = job >> 2, j = job & 3;
    if (j >= rec[b]) return;

    int t = threadIdx.x;
    if (t < 128) {
        float sc = ga1[t] * rsqrtf(rv1[t] + EPSB);
        s_f1s[t] = sc;
        s_f1b[t] = (cb1[t] - rm1[t]) * sc + be1[t];
    }
    for (int i = t; i < 2048; i += 256) {
        int k2 = i >> 5, o = i & 31;
        __half2 hp = __floats2half2_rn(w2[(2 * k2) * 32 + o], w2[(2 * k2 + 1) * 32 + o]);
        s_w2p[k2 * 36 + o] = *(uint*)&hp;
    }
    if (t < 32) {
        float sc = ga2[t] * rsqrtf(rv2[t] + EPSB);
        s_f2s[t] = sc;
        s_f2b[t] = (cb2[t] - rm2[t]) * sc + be2[t];
    }
    s_w3[t] = w3[t & 255];
    if (t < 8) {
        float sc = ga3[t] * rsqrtf(rv3[t] + EPSB);
        s_f3s[t] = sc;
        s_f3b[t] = (cb3[t] - rm3[t]) * sc + be3[t];
        s_w4v[t] = w4[t];
    }
    if (t == 0) s_cb4v = cb4[0];
    __syncthreads();

    int ptile = blockIdx.x * 64;
    const float* th = ptm + (size_t)(b * 4 + j) * 24;
    float t00 = th[0], t01 = th[1], t02 = th[2];
    float t10 = th[3], t11 = th[4], t12 = th[5];

    const __half2* Ab = g_Ah + (size_t)job * HWSZ * 64;
    const __half2* Eb = g_Eh + (size_t)b * HWSZ * 64;
    const float*   Mb = mask + (size_t)(b * 4 + j) * HWSZ;

    // ---- Stage 1: gather A taps + E, bn1+relu -> s_h1 (fp16). 2 passes of 32 pixels.
    int pix0 = t >> 3, cg = t & 7;   // 16 channels per thread
#pragma unroll
    for (int pass = 0; pass < 2; pass++) {
        int pix = pix0 + (pass << 5);
        int pg  = ptile + pix;
        int hh  = pg / WW;
        int wpx = pg - hh * WW;
        float gx = -1.0f + wpx * (2.0f / (WW - 1));
        float gy = -1.0f + hh  * (2.0f / (HH - 1));
        float px = (t00 * gx + t01 * gy + t02 + 1.0f) * ((WW - 1) * 0.5f);
        float py = (t10 * gx + t11 * gy + t12 + 1.0f) * ((HH - 1) * 0.5f);
        float x0f = floorf(px), y0f = floorf(py);
        float wx = px - x0f, wy = py - y0f;
        int x0 = (int)x0f, y0 = (int)y0f;
        float wt4[4] = { (1.0f - wx) * (1.0f - wy), wx * (1.0f - wy),
                         (1.0f - wx) * wy,          wx * wy };
        float acc[16];
#pragma unroll
        for (int i = 0; i < 16; i++) acc[i] = 0.0f;
        float comv = 0.0f;
#pragma unroll
        for (int tap = 0; tap < 4; tap++) {
            int xi = x0 + (tap & 1), yi = y0 + (tap >> 1);
            bool inb = (xi >= 0) && (xi < WW) && (yi >= 0) && (yi < HH);
            int xc = min(max(xi, 0), WW - 1);
            int yc = min(max(yi, 0), HH - 1);
            float tw = inb ? wt4[tap] : 0.0f;
            int rt = yc * WW + xc;
            if (cg == 0) comv += tw * Mb[rt];
            const uint4* Ap = (const uint4*)(Ab + (size_t)rt * 64 + cg * 8);
            uint4 v0 = Ap[0], v1 = Ap[1];
            float2 f;
            f = h2f(v0.x); acc[0]  = fmaf(tw, f.x, acc[0]);  acc[1]  = fmaf(tw, f.y, acc[1]);
            f = h2f(v0.y); acc[2]  = fmaf(tw, f.x, acc[2]);  acc[3]  = fmaf(tw, f.y, acc[3]);
            f = h2f(v0.z); acc[4]  = fmaf(tw, f.x, acc[4]);  acc[5]  = fmaf(tw, f.y, acc[5]);
            f = h2f(v0.w); acc[6]  = fmaf(tw, f.x, acc[6]);  acc[7]  = fmaf(tw, f.y, acc[7]);
            f = h2f(v1.x); acc[8]  = fmaf(tw, f.x, acc[8]);  acc[9]  = fmaf(tw, f.y, acc[9]);
            f = h2f(v1.y); acc[10] = fmaf(tw, f.x, acc[10]); acc[11] = fmaf(tw, f.y, acc[11]);
            f = h2f(v1.z); acc[12] = fmaf(tw, f.x, acc[12]); acc[13] = fmaf(tw, f.y, acc[13]);
            f = h2f(v1.w); acc[14] = fmaf(tw, f.x, acc[14]); acc[15] = fmaf(tw, f.y, acc[15]);
        }
        const uint4* Ep = (const uint4*)(Eb + (size_t)pg * 64 + cg * 8);
        uint4 e0 = Ep[0], e1 = Ep[1];
        int c0 = cg * 16;
        uint ow[8];
        uint ev[8] = { e0.x, e0.y, e0.z, e0.w, e1.x, e1.y, e1.z, e1.w };
#pragma unroll
        for (int i = 0; i < 8; i++) {
            float2 ef = h2f(ev[i]);
            float2 sv = *(const float2*)&s_f1s[c0 + 2 * i];
            float2 bv = *(const float2*)&s_f1b[c0 + 2 * i];
            float h0 = fmaxf(0.0f, (acc[2 * i]     + ef.x) * sv.x + bv.x);
            float h1 = fmaxf(0.0f, (acc[2 * i + 1] + ef.y) * sv.y + bv.y);
            __half2 hp = __floats2half2_rn(h0, h1);
            ow[i] = *(uint*)&hp;
        }
        uint4 wv0; wv0.x = ow[0]; wv0.y = ow[1]; wv0.z = ow[2]; wv0.w = ow[3];
        uint4 wv1; wv1.x = ow[4]; wv1.y = ow[5]; wv1.z = ow[6]; wv1.w = ow[7];
        *(uint4*)&s_h1[pix * 68 + cg * 8]     = wv0;
        *(uint4*)&s_h1[pix * 68 + cg * 8 + 4] = wv1;
        if (cg == 0) s_com[pix] = comv;
    }
    __syncthreads();

    // ---- Stage 2: layer2 GEMM [64 x 128] @ [128 x 32], thread = 2 pix x 4 outs
    {
        int tn = t & 7, tp = t >> 3;
        float acc[2][4];
#pragma unroll
        for (int p = 0; p < 2; p++)
#pragma unroll
            for (int o = 0; o < 4; o++) acc[p][o] = 0.0f;
        const uint* h0p = &s_h1[(2 * tp) * 68];
        const uint* h1p = &s_h1[(2 * tp + 1) * 68];
#pragma unroll 4
        for (int k2 = 0; k2 < 64; k2++) {
            float2 ha = h2f(h0p[k2]);
            float2 hb = h2f(h1p[k2]);
            uint4 wv = *(const uint4*)&s_w2p[k2 * 36 + tn * 4];
            float2 w0 = h2f(wv.x), w1f = h2f(wv.y), w2f = h2f(wv.z), w3f = h2f(wv.w);
            acc[0][0] = fmaf(ha.x, w0.x,  fmaf(ha.y, w0.y,  acc[0][0]));
            acc[0][1] = fmaf(ha.x, w1f.x, fmaf(ha.y, w1f.y, acc[0][1]));
            acc[0][2] = fmaf(ha.x, w2f.x, fmaf(ha.y, w2f.y, acc[0][2]));
            acc[0][3] = fmaf(ha.x, w3f.x, fmaf(ha.y, w3f.y, acc[0][3]));
            acc[1][0] = fmaf(hb.x, w0.x,  fmaf(hb.y, w0.y,  acc[1][0]));
            acc[1][1] = fmaf(hb.x, w1f.x, fmaf(hb.y, w1f.y, acc[1][1]));
            acc[1][2] = fmaf(hb.x, w2f.x, fmaf(hb.y, w2f.y, acc[1][2]));
            acc[1][3] = fmaf(hb.x, w3f.x, fmaf(hb.y, w3f.y, acc[1][3]));
        }
        float4 f2s = *(const float4*)&s_f2s[tn * 4];
        float4 f2b = *(const float4*)&s_f2b[tn * 4];
#pragma unroll
        for (int p = 0; p < 2; p++) {
            float4 hv;
            hv.x = fmaxf(0.0f, acc[p][0] * f2s.x + f2b.x);
            hv.y = fmaxf(0.0f, acc[p][1] * f2s.y + f2b.y);
            hv.z = fmaxf(0.0f, acc[p][2] * f2s.z + f2b.z);
            hv.w = fmaxf(0.0f, acc[p][3] * f2s.w + f2b.w);
            *(float4*)&s_h2[(2 * tp + p) * 36 + tn * 4] = hv;
        }
    }
    __syncthreads();

    // ---- Stage 3: layers 3/4 -> score, write scratch. 64 threads (1 pixel each).
    if (t < 64) {
        int pix = t;
        float p3[8];
#pragma unroll
        for (int o = 0; o < 8; o++) p3[o] = 0.0f;
#pragma unroll
        for (int k4 = 0; k4 < 8; k4++) {
            float4 hv = *(const float4*)&s_h2[pix * 36 + k4 * 4];
            float hk[4] = { hv.x, hv.y, hv.z, hv.w };
#pragma unroll
            for (int kk = 0; kk < 4; kk++) {
                float4 wa = *(const float4*)&s_w3[(k4 * 4 + kk) * 8];
                float4 wb = *(const float4*)&s_w3[(k4 * 4 + kk) * 8 + 4];
                p3[0] = fmaf(hk[kk], wa.x, p3[0]);
                p3[1] = fmaf(hk[kk], wa.y, p3[1]);
                p3[2] = fmaf(hk[kk], wa.z, p3[2]);
                p3[3] = fmaf(hk[kk], wa.w, p3[3]);
                p3[4] = fmaf(hk[kk], wb.x, p3[4]);
                p3[5] = fmaf(hk[kk], wb.y, p3[5]);
                p3[6] = fmaf(hk[kk], wb.z, p3[6]);
                p3[7] = fmaf(hk[kk], wb.w, p3[7]);
            }
        }
        float s4 = s_cb4v;
#pragma unroll
        for (int o = 0; o < 8; o++) {
            float h3 = fmaxf(0.0f, p3[o] * s_f3s[o] + s_f3b[o]);
            s4 = fmaf(h3, s_w4v[o], s4);
        }
        float comv = s_com[pix];
        float sc = (comv == 0.0f) ? NEGV : fmaxf(0.0f, s4);
        size_t base = ((size_t)b * HWSZ + ptile + pix) * 4 + j;
        g_S[base] = sc;
        g_C[base] = comv;
    }
}

// ---------------- Kernel 2b: softmax + update gather + final MLP GEMM ----------------
// grid = 600 (64 pixels each); block 256
__global__ __launch_bounds__(256) void disco_k2b(
    const int* __restrict__ rec, const float* __restrict__ ptm,
    const float* __restrict__ mlpw, const float* __restrict__ mlpb,
    float* __restrict__ out)
{
    __shared__ __align__(16) float s_u[64 * 68];   // u[pix][c] then reused as o[d][pix]
    __shared__ __align__(16) float s_mw[64 * 68];  // mlp_w [c][d] padded
    __shared__ __align__(16) float s_mb[64];

    int t = threadIdx.x;
    for (int i = t; i < 4096; i += 256) {
        int c = i >> 6, d = i & 63;
        s_mw[c * 68 + d] = mlpw[i];
    }
    if (t < 64) s_mb[t] = mlpb[t];

    int gt   = blockIdx.x * 64;
    int b    = gt / HWSZ;
    int prem = gt - b * HWSZ;
    int rb   = rec[b];

    // ---- Phase A: softmax + x_t gather -> s_u
    {
        int pix = t >> 2, cg = t & 3;       // 16 channels
        int pr  = prem + pix;
        size_t sbase = ((size_t)b * HWSZ + pr) * 4;
        float4 sc = *(const float4*)&g_S[sbase];
        float4 cm = *(const float4*)&g_C[sbase];
        float sj[4] = { sc.x, sc.y, sc.z, sc.w };
        float cj[4] = { cm.x, cm.y, cm.z, cm.w };
#pragma unroll
        for (int j = 0; j < 4; j++)
            if (j >= rb) { sj[j] = NEGV; cj[j] = 0.0f; }
        float m = fmaxf(fmaxf(sj[0], sj[1]), fmaxf(sj[2], sj[3]));
        float ex[4], ssum = 0.0f;
#pragma unroll
        for (int j = 0; j < 4; j++) { ex[j] = expf(sj[j] - m); ssum += ex[j]; }
        float inv = 1.0f / ssum;

        int hh  = pr / WW;
        int wpx = pr - hh * WW;
        float gx = -1.0f + wpx * (2.0f / (WW - 1));
        float gy = -1.0f + hh  * (2.0f / (HH - 1));

        float u[16];
#pragma unroll
        for (int i = 0; i < 16; i++) u[i] = 0.0f;

        for (int j = 0; j < 4; j++) {
            if (j >= rb) continue;
            float wgt = ex[j] * inv * cj[j];
            if (wgt == 0.0f) continue;
            const float* th = ptm + (size_t)(b * 4 + j) * 24;
            float t00 = th[0], t01 = th[1], t02 = th[2];
            float t10 = th[3], t11 = th[4], t12 = th[5];
            float px = (t00 * gx + t01 * gy + t02 + 1.0f) * ((WW - 1) * 0.5f);
            float py = (t10 * gx + t11 * gy + t12 + 1.0f) * ((HH - 1) * 0.5f);
            float x0f = floorf(px), y0f = floorf(py);
            float wx = px - x0f, wy = py - y0f;
            int x0 = (int)x0f, y0 = (int)y0f;
            float wt4[4] = { (1.0f - wx) * (1.0f - wy), wx * (1.0f - wy),
                             (1.0f - wx) * wy,          wx * wy };
            const float* xtb = g_xt + (size_t)(b * 4 + j) * HWSZ * 64 + cg * 16;
            float n[16];
#pragma unroll
            for (int i = 0; i < 16; i++) n[i] = 0.0f;
#pragma unroll
            for (int tap = 0; tap < 4; tap++) {
                int xi = x0 + (tap & 1), yi = y0 + (tap >> 1);
                bool inb = (xi >= 0) && (xi < WW) && (yi >= 0) && (yi < HH);
                int xc = min(max(xi, 0), WW - 1);
                int yc = min(max(yi, 0), HH - 1);
                float tw = inb ? wt4[tap] : 0.0f;
                const float4* xp = (const float4*)(xtb + (size_t)(yc * WW + xc) * 64);
#pragma unroll
                for (int q = 0; q < 4; q++) {
                    float4 v = xp[q];
                    n[q * 4 + 0] = fmaf(tw, v.x, n[q * 4 + 0]);
                    n[q * 4 + 1] = fmaf(tw, v.y, n[q * 4 + 1]);
                    n[q * 4 + 2] = fmaf(tw, v.z, n[q * 4 + 2]);
                    n[q * 4 + 3] = fmaf(tw, v.w, n[q * 4 + 3]);
                }
            }
#pragma unroll
            for (int i = 0; i < 16; i++) u[i] = fmaf(wgt, n[i], u[i]);
        }
#pragma unroll
        for (int q = 0; q < 4; q++) {
            float4 v = make_float4(u[q * 4], u[q * 4 + 1], u[q * 4 + 2], u[q * 4 + 3]);
            *(float4*)&s_u[pix * 68 + cg * 16 + q * 4] = v;
        }
    }
    __syncthreads();

    // ---- Phase B: final MLP GEMM [64 x 64] @ [64 x 64], thread = 4 pix x 4 d
    int tp = t >> 4, tn = t & 15;
    float acc[4][4];
#pragma unroll
    for (int p = 0; p < 4; p++)
#pragma unroll
        for (int d = 0; d < 4; d++) acc[p][d] = 0.0f;
#pragma unroll 4
    for (int k4 = 0; k4 < 16; k4++) {
        float4 uv[4];
#pragma unroll
        for (int p = 0; p < 4; p++)
            uv[p] = *(const float4*)&s_u[(tp * 4 + p) * 68 + k4 * 4];
        float4 wv[4];
#pragma unroll
        for (int kk = 0; kk < 4; kk++)
            wv[kk] = *(const float4*)&s_mw[(k4 * 4 + kk) * 68 + tn * 4];
#pragma unroll
        for (int p = 0; p < 4; p++) {
            acc[p][0] = fmaf(uv[p].x, wv[0].x, acc[p][0]);
            acc[p][1] = fmaf(uv[p].x, wv[0].y, acc[p][1]);
            acc[p][2] = fmaf(uv[p].x, wv[0].z, acc[p][2]);
            acc[p][3] = fmaf(uv[p].x, wv[0].w, acc[p][3]);
            acc[p][0] = fmaf(uv[p].y, wv[1].x, acc[p][0]);
            acc[p][1] = fmaf(uv[p].y, wv[1].y, acc[p][1]);
            acc[p][2] = fmaf(uv[p].y, wv[1].z, acc[p][2]);
            acc[p][3] = fmaf(uv[p].y, wv[1].w, acc[p][3]);
            acc[p][0] = fmaf(uv[p].z, wv[2].x, acc[p][0]);
            acc[p][1] = fmaf(uv[p].z, wv[2].y, acc[p][1]);
            acc[p][2] = fmaf(uv[p].z, wv[2].z, acc[p][2]);
            acc[p][3] = fmaf(uv[p].z, wv[2].w, acc[p][3]);
            acc[p][0] = fmaf(uv[p].w, wv[3].x, acc[p][0]);
            acc[p][1] = fmaf(uv[p].w, wv[3].y, acc[p][1]);
            acc[p][2] = fmaf(uv[p].w, wv[3].z, acc[p][2]);
            acc[p][3] = fmaf(uv[p].w, wv[3].w, acc[p][3]);
        }
    }
    float4 bias = *(const float4*)&s_mb[tn * 4];
    __syncthreads();    // all reads of s_u done -> safe to overwrite as o[d][pix]
#pragma unroll
    for (int d = 0; d < 4; d++) {
        float bd = (d == 0) ? bias.x : (d == 1) ? bias.y : (d == 2) ? bias.z : bias.w;
        float4 ov = make_float4(acc[0][d] + bd, acc[1][d] + bd, acc[2][d] + bd, acc[3][d] + bd);
        *(float4*)&s_u[(tn * 4 + d) * 68 + tp * 4] = ov;
    }
    __syncthreads();

    for (int i = t; i < 4096; i += 256) {
        int d = i >> 6, pp = i & 63;
        out[((size_t)b * CC + d) * HWSZ + prem + pp] = s_u[d * 68 + pp];
    }
}

extern "C" void kernel_launch(void* const* d_in, const int* in_sizes, int n_in,
                              void* d_out, int out_size) {
    (void)in_sizes; (void)n_in; (void)out_size;
    const float* x    = (const float*)d_in[0];
    const float* mask = (const float*)d_in[1];
    const int*   rec  = (const int*)d_in[2];
    const float* ptm  = (const float*)d_in[3];
    const float* w1   = (const float*)d_in[4];
    const float* cb1  = (const float*)d_in[5];
    const float* ga1  = (const float*)d_in[6];
    const float* be1  = (const float*)d_in[7];
    const float* rm1  = (const float*)d_in[8];
    const float* rv1  = (const float*)d_in[9];
    const float* w2   = (const float*)d_in[10];
    const float* cb2  = (const float*)d_in[11];
    const float* ga2  = (const float*)d_in[12];
    const float* be2  = (const float*)d_in[13];
    const float* rm2  = (const float*)d_in[14];
    const float* rv2  = (const float*)d_in[15];
    const float* w3   = (const float*)d_in[16];
    const float* cb3  = (const float*)d_in[17];
    const float* ga3  = (const float*)d_in[18];
    const float* be3  = (const float*)d_in[19];
    const float* rm3  = (const float*)d_in[20];
    const float* rv3  = (const float*)d_in[21];
    const float* w4   = (const float*)d_in[22];
    const float* cb4  = (const float*)d_in[23];
    const float* mlpw = (const float*)d_in[24];
    const float* mlpb = (const float*)d_in[25];
    float* out = (float*)d_out;

    dim3 grid1(HWSZ / 128, 15);
    disco_k1<<<grid1, 256>>>(x, rec, w1);

    dim3 grid2a(HWSZ / 64, 12);
    disco_k2a<<<grid2a, 256>>>(mask, rec, ptm,
                               cb1, ga1, be1, rm1, rv1,
                               w2, cb2, ga2, be2, rm2, rv2,
                               w3, cb3, ga3, be3, rm3, rv3,
                               w4, cb4);

    disco_k2b<<<(BB * HWSZ) / 64, 256>>>(rec, ptm, mlpw, mlpb, out);
}

// round 7
// speedup vs baseline: 2.6613x; 1.1458x over previous
#include <cuda_runtime.h>
#include <cuda_fp16.h>
#include <mma.h>
#include <math.h>

using namespace nvcuda;

#define CC   64
#define HH   80
#define WW   160
#define HWSZ (HH * WW)      // 12800
#define BB   3
#define LL   4
#define EPSB 1e-5f
#define NEGV -1e30f

typedef unsigned int uint;

// Scratch:
//  g_Ah[b*4+j][pix][o/2]  conv partial (warped-neighbor half of layer1), channel-last, 128 ch, fp16
//  g_Eh[b][pix][o/2]      conv partial (ego half, node[b,0]), channel-last, 128 ch, fp16
//  g_xt[b*4+j][pix][c]    raw x transposed to channel-last (64 ch, fp32) for the updated-gather
//  g_S / g_C [b][pix][j]  scores (NEG-masked) and com values
__device__ __align__(16) __half2 g_Ah[(size_t)BB * LL * HWSZ * 64];  // 39.3 MB
__device__ __align__(16) __half2 g_Eh[(size_t)BB * HWSZ * 64];       // 9.8 MB
__device__ __align__(16) float   g_xt[(size_t)BB * LL * HWSZ * 64];  // 39.3 MB
__device__ __align__(16) float   g_S[(size_t)BB * HWSZ * 4];
__device__ __align__(16) float   g_C[(size_t)BB * HWSZ * 4];

__device__ __forceinline__ float2 h2f(uint u) {
    return __half22float2(*reinterpret_cast<__half2*>(&u));
}

// ---------------- Kernel 1: per-agent GEMM on tensor cores ----------------
// [128-pix tile x 64 k] @ [64 k x 128 out], fp16 in / f32 accum / fp16 out.
// jobs 0..11  : A for (b = job/4, j = job%4)  w1 rows [0,64)  + x_t f32 transpose writeback
// jobs 12..14 : E for b = job-12              w1 rows [64,128)
__global__ __launch_bounds__(256, 2) void disco_k1(const float* __restrict__ x,
                                                   const int* __restrict__ rec,
                                                   const float* __restrict__ w1) {
    __shared__ __align__(16) float Xs[64][132];          // f32 [k][pix] (kept for xt writeback)
    __shared__ __align__(16) unsigned char sbuf[35840];  // Xh[128][72] fp16 | Wh[64][136] fp16 ; reused as stage[128][68] f32
    half*  Xh    = (half*)sbuf;               // 18432 B
    half*  Wh    = (half*)(sbuf + 18432);     // 17408 B
    float* stage = (float*)sbuf;              // 34816 B (reuse after mma)

    int job   = blockIdx.y;
    int ptile = blockIdx.x * 128;
    int r0 = rec[0], r1 = rec[1], r2 = rec[2];

    const float* src;
    __half2* dst;
    int wrow0;
    bool isA = (job < 12);
    if (isA) {
        int b = job >> 2, j = job & 3;
        int rb   = (b == 0) ? r0 : ((b == 1) ? r1 : r2);
        if (j >= rb) return;
        int aoff = (b == 0) ? 0 : ((b == 1) ? r0 : (r0 + r1));
        src   = x + (size_t)(aoff + j) * CC * HWSZ;
        dst   = g_Ah + (size_t)job * HWSZ * 64;
        wrow0 = 0;
    } else {
        int b = job - 12;
        int aoff = (b == 0) ? 0 : ((b == 1) ? r0 : (r0 + r1));
        src   = x + (size_t)aoff * CC * HWSZ;
        dst   = g_Eh + (size_t)b * HWSZ * 64;
        wrow0 = 64;
    }

    int t = threadIdx.x;
    // Load x tile (f32) and w1 (converted to fp16)
    for (int i = t; i < 64 * 128; i += 256) {
        int c = i >> 7, p = i & 127;
        Xs[c][p] = src[c * HWSZ + ptile + p];
    }
    for (int i = t; i < 64 * 128; i += 256) {
        int c = i >> 7, o = i & 127;
        Wh[c * 136 + o] = __float2half(w1[(wrow0 + c) * 128 + o]);
    }
    __syncthreads();
    // Transpose Xs -> Xh [pix][k] fp16
    for (int i = t; i < 128 * 64; i += 256) {
        int p = i >> 6, c = i & 63;
        Xh[p * 72 + c] = __float2half(Xs[c][p]);
    }
    __syncthreads();

    int w = t >> 5;   // warp id: pixel rows [16w, 16w+16)

    wmma::fragment<wmma::accumulator, 16, 16, 16, float> acc[8];
#pragma unroll
    for (int j = 0; j < 8; j++) wmma::fill_fragment(acc[j], 0.0f);

#pragma unroll
    for (int k0 = 0; k0 < 64; k0 += 16) {
        wmma::fragment<wmma::matrix_a, 16, 16, 16, half, wmma::row_major> af;
        wmma::load_matrix_sync(af, Xh + (w * 16) * 72 + k0, 72);
#pragma unroll
        for (int j = 0; j < 8; j++) {
            wmma::fragment<wmma::matrix_b, 16, 16, 16, half, wmma::row_major> bf;
            wmma::load_matrix_sync(bf, Wh + k0 * 136 + j * 16, 136);
            wmma::mma_sync(acc[j], af, bf, acc[j]);
        }
    }
    __syncthreads();   // all Xh/Wh reads done -> safe to reuse as stage

    // Two output passes: cols [0,64) then [64,128)
#pragma unroll
    for (int hid = 0; hid < 2; hid++) {
#pragma unroll
        for (int j = 0; j < 4; j++)
            wmma::store_matrix_sync(stage + (w * 16) * 68 + j * 16, acc[hid * 4 + j], 68, wmma::mem_row_major);
        __syncthreads();
        for (int i = t; i < 128 * 32; i += 256) {
            int p = i >> 5, c2 = i & 31;
            __half2 hv = __floats2half2_rn(stage[p * 68 + 2 * c2], stage[p * 68 + 2 * c2 + 1]);
            dst[(size_t)(ptile + p) * 64 + hid * 32 + c2] = hv;
        }
        __syncthreads();
    }

    // Transposed raw-x (f32) writeback for A-jobs — value path stays full precision
    if (isA) {
        float* xt = g_xt + (size_t)job * HWSZ * 64;
        for (int i = t; i < 64 * 128; i += 256) {
            int p = i >> 6, c = i & 63;
            xt[(size_t)(ptile + p) * 64 + c] = Xs[c][p];
        }
    }
}

// ---------------- Kernel 2a: score pipeline as tile-GEMM ----------------
// grid = (200 pixel-tiles, 12 (b,j)); block 256
__global__ __launch_bounds__(256) void disco_k2a(
    const float* __restrict__ mask,
    const int* __restrict__ rec, const float* __restrict__ ptm,
    const float* __restrict__ cb1, const float* __restrict__ ga1,
    const float* __restrict__ be1, const float* __restrict__ rm1, const float* __restrict__ rv1,
    const float* __restrict__ w2, const float* __restrict__ cb2, const float* __restrict__ ga2,
    const float* __restrict__ be2, const float* __restrict__ rm2, const float* __restrict__ rv2,
    const float* __restrict__ w3, const float* __restrict__ cb3, const float* __restrict__ ga3,
    const float* __restrict__ be3, const float* __restrict__ rm3, const float* __restrict__ rv3,
    const float* __restrict__ w4, const float* __restrict__ cb4)
{
    __shared__ __align__(16) uint  s_h1[64 * 68];    // h1 half2 [pix][k2]
    __shared__ __align__(16) uint  s_w2p[64 * 36];   // w2 half2 k-pairs [k2][o]
    __shared__ __align__(16) float s_h2[64 * 36];    // h2 [pix][o]
    __shared__ __align__(16) float s_f1s[128], s_f1b[128];
    __shared__ __align__(16) float s_f2s[32], s_f2b[32];
    __shared__ __align__(16) float s_w3[256];
    __shared__ __align__(16) float s_f3s[8], s_f3b[8], s_w4v[8];
    __shared__ float s_cb4v;
    __shared__ float s_com[64];

    int job = blockIdx.y;
    int b = job >> 2, j = job & 3;
    if (j >= rec[b]) return;

    int t = threadIdx.x;
    if (t < 128) {
        float sc = ga1[t] * rsqrtf(rv1[t] + EPSB);
        s_f1s[t] = sc;
        s_f1b[t] = (cb1[t] - rm1[t]) * sc + be1[t];
    }
    for (int i = t; i < 2048; i += 256) {
        int k2 = i >> 5, o = i & 31;
        __half2 hp = __floats2half2_rn(w2[(2 * k2) * 32 + o], w2[(2 * k2 + 1) * 32 + o]);
        s_w2p[k2 * 36 + o] = *(uint*)&hp;
    }
    if (t < 32) {
        float sc = ga2[t] * rsqrtf(rv2[t] + EPSB);
        s_f2s[t] = sc;
        s_f2b[t] = (cb2[t] - rm2[t]) * sc + be2[t];
    }
    s_w3[t] = w3[t & 255];
    if (t < 8) {
        float sc = ga3[t] * rsqrtf(rv3[t] + EPSB);
        s_f3s[t] = sc;
        s_f3b[t] = (cb3[t] - rm3[t]) * sc + be3[t];
        s_w4v[t] = w4[t];
    }
    if (t == 0) s_cb4v = cb4[0];
    __syncthreads();

    int ptile = blockIdx.x * 64;
    const float* th = ptm + (size_t)(b * 4 + j) * 24;
    float t00 = th[0], t01 = th[1], t02 = th[2];
    float t10 = th[3], t11 = th[4], t12 = th[5];

    const __half2* Ab = g_Ah + (size_t)job * HWSZ * 64;
    const __half2* Eb = g_Eh + (size_t)b * HWSZ * 64;
    const float*   Mb = mask + (size_t)(b * 4 + j) * HWSZ;

    // ---- Stage 1: gather A taps + E, bn1+relu -> s_h1 (fp16). 2 passes of 32 pixels.
    int pix0 = t >> 3, cg = t & 7;   // 16 channels per thread
#pragma unroll
    for (int pass = 0; pass < 2; pass++) {
        int pix = pix0 + (pass << 5);
        int pg  = ptile + pix;
        int hh  = pg / WW;
        int wpx = pg - hh * WW;
        float gx = -1.0f + wpx * (2.0f / (WW - 1));
        float gy = -1.0f + hh  * (2.0f / (HH - 1));
        float px = (t00 * gx + t01 * gy + t02 + 1.0f) * ((WW - 1) * 0.5f);
        float py = (t10 * gx + t11 * gy + t12 + 1.0f) * ((HH - 1) * 0.5f);
        float x0f = floorf(px), y0f = floorf(py);
        float wx = px - x0f, wy = py - y0f;
        int x0 = (int)x0f, y0 = (int)y0f;
        float wt4[4] = { (1.0f - wx) * (1.0f - wy), wx * (1.0f - wy),
                         (1.0f - wx) * wy,          wx * wy };
        float acc[16];
#pragma unroll
        for (int i = 0; i < 16; i++) acc[i] = 0.0f;
        float comv = 0.0f;
#pragma unroll
        for (int tap = 0; tap < 4; tap++) {
            int xi = x0 + (tap & 1), yi = y0 + (tap >> 1);
            bool inb = (xi >= 0) && (xi < WW) && (yi >= 0) && (yi < HH);
            int xc = min(max(xi, 0), WW - 1);
            int yc = min(max(yi, 0), HH - 1);
            float tw = inb ? wt4[tap] : 0.0f;
            int rt = yc * WW + xc;
            if (cg == 0) comv += tw * Mb[rt];
            const uint4* Ap = (const uint4*)(Ab + (size_t)rt * 64 + cg * 8);
            uint4 v0 = Ap[0], v1 = Ap[1];
            float2 f;
            f = h2f(v0.x); acc[0]  = fmaf(tw, f.x, acc[0]);  acc[1]  = fmaf(tw, f.y, acc[1]);
            f = h2f(v0.y); acc[2]  = fmaf(tw, f.x, acc[2]);  acc[3]  = fmaf(tw, f.y, acc[3]);
            f = h2f(v0.z); acc[4]  = fmaf(tw, f.x, acc[4]);  acc[5]  = fmaf(tw, f.y, acc[5]);
            f = h2f(v0.w); acc[6]  = fmaf(tw, f.x, acc[6]);  acc[7]  = fmaf(tw, f.y, acc[7]);
            f = h2f(v1.x); acc[8]  = fmaf(tw, f.x, acc[8]);  acc[9]  = fmaf(tw, f.y, acc[9]);
            f = h2f(v1.y); acc[10] = fmaf(tw, f.x, acc[10]); acc[11] = fmaf(tw, f.y, acc[11]);
            f = h2f(v1.z); acc[12] = fmaf(tw, f.x, acc[12]); acc[13] = fmaf(tw, f.y, acc[13]);
            f = h2f(v1.w); acc[14] = fmaf(tw, f.x, acc[14]); acc[15] = fmaf(tw, f.y, acc[15]);
        }
        const uint4* Ep = (const uint4*)(Eb + (size_t)pg * 64 + cg * 8);
        uint4 e0 = Ep[0], e1 = Ep[1];
        int c0 = cg * 16;
        uint ow[8];
        uint ev[8] = { e0.x, e0.y, e0.z, e0.w, e1.x, e1.y, e1.z, e1.w };
#pragma unroll
        for (int i = 0; i < 8; i++) {
            float2 ef = h2f(ev[i]);
            float2 sv = *(const float2*)&s_f1s[c0 + 2 * i];
            float2 bv = *(const float2*)&s_f1b[c0 + 2 * i];
            float h0 = fmaxf(0.0f, (acc[2 * i]     + ef.x) * sv.x + bv.x);
            float h1 = fmaxf(0.0f, (acc[2 * i + 1] + ef.y) * sv.y + bv.y);
            __half2 hp = __floats2half2_rn(h0, h1);
            ow[i] = *(uint*)&hp;
        }
        uint4 wv0; wv0.x = ow[0]; wv0.y = ow[1]; wv0.z = ow[2]; wv0.w = ow[3];
        uint4 wv1; wv1.x = ow[4]; wv1.y = ow[5]; wv1.z = ow[6]; wv1.w = ow[7];
        *(uint4*)&s_h1[pix * 68 + cg * 8]     = wv0;
        *(uint4*)&s_h1[pix * 68 + cg * 8 + 4] = wv1;
        if (cg == 0) s_com[pix] = comv;
    }
    __syncthreads();

    // ---- Stage 2: layer2 GEMM [64 x 128] @ [128 x 32], thread = 2 pix x 4 outs
    {
        int tn = t & 7, tp = t >> 3;
        float acc[2][4];
#pragma unroll
        for (int p = 0; p < 2; p++)
#pragma unroll
            for (int o = 0; o < 4; o++) acc[p][o] = 0.0f;
        const uint* h0p = &s_h1[(2 * tp) * 68];
        const uint* h1p = &s_h1[(2 * tp + 1) * 68];
#pragma unroll 4
        for (int k2 = 0; k2 < 64; k2++) {
            float2 ha = h2f(h0p[k2]);
            float2 hb = h2f(h1p[k2]);
            uint4 wv = *(const uint4*)&s_w2p[k2 * 36 + tn * 4];
            float2 w0 = h2f(wv.x), w1f = h2f(wv.y), w2f = h2f(wv.z), w3f = h2f(wv.w);
            acc[0][0] = fmaf(ha.x, w0.x,  fmaf(ha.y, w0.y,  acc[0][0]));
            acc[0][1] = fmaf(ha.x, w1f.x, fmaf(ha.y, w1f.y, acc[0][1]));
            acc[0][2] = fmaf(ha.x, w2f.x, fmaf(ha.y, w2f.y, acc[0][2]));
            acc[0][3] = fmaf(ha.x, w3f.x, fmaf(ha.y, w3f.y, acc[0][3]));
            acc[1][0] = fmaf(hb.x, w0.x,  fmaf(hb.y, w0.y,  acc[1][0]));
            acc[1][1] = fmaf(hb.x, w1f.x, fmaf(hb.y, w1f.y, acc[1][1]));
            acc[1][2] = fmaf(hb.x, w2f.x, fmaf(hb.y, w2f.y, acc[1][2]));
            acc[1][3] = fmaf(hb.x, w3f.x, fmaf(hb.y, w3f.y, acc[1][3]));
        }
        float4 f2s = *(const float4*)&s_f2s[tn * 4];
        float4 f2b = *(const float4*)&s_f2b[tn * 4];
#pragma unroll
        for (int p = 0; p < 2; p++) {
            float4 hv;
            hv.x = fmaxf(0.0f, acc[p][0] * f2s.x + f2b.x);
            hv.y = fmaxf(0.0f, acc[p][1] * f2s.y + f2b.y);
            hv.z = fmaxf(0.0f, acc[p][2] * f2s.z + f2b.z);
            hv.w = fmaxf(0.0f, acc[p][3] * f2s.w + f2b.w);
            *(float4*)&s_h2[(2 * tp + p) * 36 + tn * 4] = hv;
        }
    }
    __syncthreads();

    // ---- Stage 3: layers 3/4 -> score, write scratch. 64 threads (1 pixel each).
    if (t < 64) {
        int pix = t;
        float p3[8];
#pragma unroll
        for (int o = 0; o < 8; o++) p3[o] = 0.0f;
#pragma unroll
        for (int k4 = 0; k4 < 8; k4++) {
            float4 hv = *(const float4*)&s_h2[pix * 36 + k4 * 4];
            float hk[4] = { hv.x, hv.y, hv.z, hv.w };
#pragma unroll
            for (int kk = 0; kk < 4; kk++) {
                float4 wa = *(const float4*)&s_w3[(k4 * 4 + kk) * 8];
                float4 wb = *(const float4*)&s_w3[(k4 * 4 + kk) * 8 + 4];
                p3[0] = fmaf(hk[kk], wa.x, p3[0]);
                p3[1] = fmaf(hk[kk], wa.y, p3[1]);
                p3[2] = fmaf(hk[kk], wa.z, p3[2]);
                p3[3] = fmaf(hk[kk], wa.w, p3[3]);
                p3[4] = fmaf(hk[kk], wb.x, p3[4]);
                p3[5] = fmaf(hk[kk], wb.y, p3[5]);
                p3[6] = fmaf(hk[kk], wb.z, p3[6]);
                p3[7] = fmaf(hk[kk], wb.w, p3[7]);
            }
        }
        float s4 = s_cb4v;
#pragma unroll
        for (int o = 0; o < 8; o++) {
            float h3 = fmaxf(0.0f, p3[o] * s_f3s[o] + s_f3b[o]);
            s4 = fmaf(h3, s_w4v[o], s4);
        }
        float comv = s_com[pix];
        float sc = (comv == 0.0f) ? NEGV : fmaxf(0.0f, s4);
        size_t base = ((size_t)b * HWSZ + ptile + pix) * 4 + j;
        g_S[base] = sc;
        g_C[base] = comv;
    }
}

// ---------------- Kernel 2b: softmax + update gather + final MLP GEMM ----------------
// grid = 600 (64 pixels each); block 256
__global__ __launch_bounds__(256) void disco_k2b(
    const int* __restrict__ rec, const float* __restrict__ ptm,
    const float* __restrict__ mlpw, const float* __restrict__ mlpb,
    float* __restrict__ out)
{
    __shared__ __align__(16) float s_u[64 * 68];   // u[pix][c] then reused as o[d][pix]
    __shared__ __align__(16) float s_mw[64 * 68];  // mlp_w [c][d] padded
    __shared__ __align__(16) float s_mb[64];

    int t = threadIdx.x;
    for (int i = t; i < 4096; i += 256) {
        int c = i >> 6, d = i & 63;
        s_mw[c * 68 + d] = mlpw[i];
    }
    if (t < 64) s_mb[t] = mlpb[t];

    int gt   = blockIdx.x * 64;
    int b    = gt / HWSZ;
    int prem = gt - b * HWSZ;
    int rb   = rec[b];

    // ---- Phase A: softmax + x_t gather -> s_u
    {
        int pix = t >> 2, cg = t & 3;       // 16 channels
        int pr  = prem + pix;
        size_t sbase = ((size_t)b * HWSZ + pr) * 4;
        float4 sc = *(const float4*)&g_S[sbase];
        float4 cm = *(const float4*)&g_C[sbase];
        float sj[4] = { sc.x, sc.y, sc.z, sc.w };
        float cj[4] = { cm.x, cm.y, cm.z, cm.w };
#pragma unroll
        for (int j = 0; j < 4; j++)
            if (j >= rb) { sj[j] = NEGV; cj[j] = 0.0f; }
        float m = fmaxf(fmaxf(sj[0], sj[1]), fmaxf(sj[2], sj[3]));
        float ex[4], ssum = 0.0f;
#pragma unroll
        for (int j = 0; j < 4; j++) { ex[j] = expf(sj[j] - m); ssum += ex[j]; }
        float inv = 1.0f / ssum;

        int hh  = pr / WW;
        int wpx = pr - hh * WW;
        float gx = -1.0f + wpx * (2.0f / (WW - 1));
        float gy = -1.0f + hh  * (2.0f / (HH - 1));

        float u[16];
#pragma unroll
        for (int i = 0; i < 16; i++) u[i] = 0.0f;

        for (int j = 0; j < 4; j++) {
            if (j >= rb) continue;
            float wgt = ex[j] * inv * cj[j];
            if (wgt == 0.0f) continue;
            const float* th = ptm + (size_t)(b * 4 + j) * 24;
            float t00 = th[0], t01 = th[1], t02 = th[2];
            float t10 = th[3], t11 = th[4], t12 = th[5];
            float px = (t00 * gx + t01 * gy + t02 + 1.0f) * ((WW - 1) * 0.5f);
            float py = (t10 * gx + t11 * gy + t12 + 1.0f) * ((HH - 1) * 0.5f);
            float x0f = floorf(px), y0f = floorf(py);
            float wx = px - x0f, wy = py - y0f;
            int x0 = (int)x0f, y0 = (int)y0f;
            float wt4[4] = { (1.0f - wx) * (1.0f - wy), wx * (1.0f - wy),
                             (1.0f - wx) * wy,          wx * wy };
            const float* xtb = g_xt + (size_t)(b * 4 + j) * HWSZ * 64 + cg * 16;
            float n[16];
#pragma unroll
            for (int i = 0; i < 16; i++) n[i] = 0.0f;
#pragma unroll
            for (int tap = 0; tap < 4; tap++) {
                int xi = x0 + (tap & 1), yi = y0 + (tap >> 1);
                bool inb = (xi >= 0) && (xi < WW) && (yi >= 0) && (yi < HH);
                int xc = min(max(xi, 0), WW - 1);
                int yc = min(max(yi, 0), HH - 1);
                float tw = inb ? wt4[tap] : 0.0f;
                const float4* xp = (const float4*)(xtb + (size_t)(yc * WW + xc) * 64);
#pragma unroll
                for (int q = 0; q < 4; q++) {
                    float4 v = xp[q];
                    n[q * 4 + 0] = fmaf(tw, v.x, n[q * 4 + 0]);
                    n[q * 4 + 1] = fmaf(tw, v.y, n[q * 4 + 1]);
                    n[q * 4 + 2] = fmaf(tw, v.z, n[q * 4 + 2]);
                    n[q * 4 + 3] = fmaf(tw, v.w, n[q * 4 + 3]);
                }
            }
#pragma unroll
            for (int i = 0; i < 16; i++) u[i] = fmaf(wgt, n[i], u[i]);
        }
#pragma unroll
        for (int q = 0; q < 4; q++) {
            float4 v = make_float4(u[q * 4], u[q * 4 + 1], u[q * 4 + 2], u[q * 4 + 3]);
            *(float4*)&s_u[pix * 68 + cg * 16 + q * 4] = v;
        }
    }
    __syncthreads();

    // ---- Phase B: final MLP GEMM [64 x 64] @ [64 x 64], thread = 4 pix x 4 d
    int tp = t >> 4, tn = t & 15;
    float acc[4][4];
#pragma unroll
    for (int p = 0; p < 4; p++)
#pragma unroll
        for (int d = 0; d < 4; d++) acc[p][d] = 0.0f;
#pragma unroll 4
    for (int k4 = 0; k4 < 16; k4++) {
        float4 uv[4];
#pragma unroll
        for (int p = 0; p < 4; p++)
            uv[p] = *(const float4*)&s_u[(tp * 4 + p) * 68 + k4 * 4];
        float4 wv[4];
#pragma unroll
        for (int kk = 0; kk < 4; kk++)
            wv[kk] = *(const float4*)&s_mw[(k4 * 4 + kk) * 68 + tn * 4];
#pragma unroll
        for (int p = 0; p < 4; p++) {
            acc[p][0] = fmaf(uv[p].x, wv[0].x, acc[p][0]);
            acc[p][1] = fmaf(uv[p].x, wv[0].y, acc[p][1]);
            acc[p][2] = fmaf(uv[p].x, wv[0].z, acc[p][2]);
            acc[p][3] = fmaf(uv[p].x, wv[0].w, acc[p][3]);
            acc[p][0] = fmaf(uv[p].y, wv[1].x, acc[p][0]);
            acc[p][1] = fmaf(uv[p].y, wv[1].y, acc[p][1]);
            acc[p][2] = fmaf(uv[p].y, wv[1].z, acc[p][2]);
            acc[p][3] = fmaf(uv[p].y, wv[1].w, acc[p][3]);
            acc[p][0] = fmaf(uv[p].z, wv[2].x, acc[p][0]);
            acc[p][1] = fmaf(uv[p].z, wv[2].y, acc[p][1]);
            acc[p][2] = fmaf(uv[p].z, wv[2].z, acc[p][2]);
            acc[p][3] = fmaf(uv[p].z, wv[2].w, acc[p][3]);
            acc[p][0] = fmaf(uv[p].w, wv[3].x, acc[p][0]);
            acc[p][1] = fmaf(uv[p].w, wv[3].y, acc[p][1]);
            acc[p][2] = fmaf(uv[p].w, wv[3].z, acc[p][2]);
            acc[p][3] = fmaf(uv[p].w, wv[3].w, acc[p][3]);
        }
    }
    float4 bias = *(const float4*)&s_mb[tn * 4];
    __syncthreads();    // all reads of s_u done -> safe to overwrite as o[d][pix]
#pragma unroll
    for (int d = 0; d < 4; d++) {
        float bd = (d == 0) ? bias.x : (d == 1) ? bias.y : (d == 2) ? bias.z : bias.w;
        float4 ov = make_float4(acc[0][d] + bd, acc[1][d] + bd, acc[2][d] + bd, acc[3][d] + bd);
        *(float4*)&s_u[(tn * 4 + d) * 68 + tp * 4] = ov;
    }
    __syncthreads();

    for (int i = t; i < 4096; i += 256) {
        int d = i >> 6, pp = i & 63;
        out[((size_t)b * CC + d) * HWSZ + prem + pp] = s_u[d * 68 + pp];
    }
}

extern "C" void kernel_launch(void* const* d_in, const int* in_sizes, int n_in,
                              void* d_out, int out_size) {
    (void)in_sizes; (void)n_in; (void)out_size;
    const float* x    = (const float*)d_in[0];
    const float* mask = (const float*)d_in[1];
    const int*   rec  = (const int*)d_in[2];
    const float* ptm  = (const float*)d_in[3];
    const float* w1   = (const float*)d_in[4];
    const float* cb1  = (const float*)d_in[5];
    const float* ga1  = (const float*)d_in[6];
    const float* be1  = (const float*)d_in[7];
    const float* rm1  = (const float*)d_in[8];
    const float* rv1  = (const float*)d_in[9];
    const float* w2   = (const float*)d_in[10];
    const float* cb2  = (const float*)d_in[11];
    const float* ga2  = (const float*)d_in[12];
    const float* be2  = (const float*)d_in[13];
    const float* rm2  = (const float*)d_in[14];
    const float* rv2  = (const float*)d_in[15];
    const float* w3   = (const float*)d_in[16];
    const float* cb3  = (const float*)d_in[17];
    const float* ga3  = (const float*)d_in[18];
    const float* be3  = (const float*)d_in[19];
    const float* rm3  = (const float*)d_in[20];
    const float* rv3  = (const float*)d_in[21];
    const float* w4   = (const float*)d_in[22];
    const float* cb4  = (const float*)d_in[23];
    const float* mlpw = (const float*)d_in[24];
    const float* mlpb = (const float*)d_in[25];
    float* out = (float*)d_out;

    dim3 grid1(HWSZ / 128, 15);
    disco_k1<<<grid1, 256>>>(x, rec, w1);

    dim3 grid2a(HWSZ / 64, 12);
    disco_k2a<<<grid2a, 256>>>(mask, rec, ptm,
                               cb1, ga1, be1, rm1, rv1,
                               w2, cb2, ga2, be2, rm2, rv2,
                               w3, cb3, ga3, be3, rm3, rv3,
                               w4, cb4);

    disco_k2b<<<(BB * HWSZ) / 64, 256>>>(rec, ptm, mlpw, mlpb, out);
}

// round 8
// speedup vs baseline: 2.7046x; 1.0163x over previous
#include <cuda_runtime.h>
#include <cuda_fp16.h>
#include <mma.h>
#include <math.h>

using namespace nvcuda;

#define CC   64
#define HH   80
#define WW   160
#define HWSZ (HH * WW)      // 12800
#define BB   3
#define LL   4
#define EPSB 1e-5f
#define NEGV -1e30f

typedef unsigned int uint;

// Scratch:
//  g_Eh[b][pix][o/2]      conv partial (ego half, node[b,0]), channel-last, 128 ch, fp16
//  g_xt[b*4+j][pix][c]    raw x transposed channel-last (64 ch, fp32)  -> value-path gather
//  g_xth[b*4+j][pix][c/2] raw x transposed channel-last (64 ch, fp16)  -> score-path gather
//  g_S / g_C [b][pix][j]  scores (NEG-masked) and com values
__device__ __align__(16) __half2 g_Eh[(size_t)BB * HWSZ * 64];        // 9.8 MB
__device__ __align__(16) float   g_xt[(size_t)BB * LL * HWSZ * 64];   // 39.3 MB
__device__ __align__(16) __half2 g_xth[(size_t)BB * LL * HWSZ * 32];  // 19.7 MB
__device__ __align__(16) float   g_S[(size_t)BB * HWSZ * 4];
__device__ __align__(16) float   g_C[(size_t)BB * HWSZ * 4];

__device__ __forceinline__ float2 h2f(uint u) {
    return __half22float2(*reinterpret_cast<__half2*>(&u));
}

// ---------------- Kernel 1: transposes (A-jobs) + ego GEMM on tensor cores (E-jobs) ----
// jobs 0..11  : transpose x slice (b=job/4, j=job%4) -> g_xt (f32) + g_xth (fp16)
// jobs 12..14 : E = node[b,0] @ w1[64:128] -> g_Eh  (wmma fp16/f32)
__global__ __launch_bounds__(256, 2) void disco_k1(const float* __restrict__ x,
                                                   const int* __restrict__ rec,
                                                   const float* __restrict__ w1) {
    __shared__ __align__(16) float Xs[64][133];          // f32 [k][pix], 133: conflict-free transpose
    __shared__ __align__(16) unsigned char sbuf[35840];  // E-jobs: Xh[128][72]h | Wh[64][136]h ; reused as stage[128][68] f32
    half*  Xh    = (half*)sbuf;               // 18432 B
    half*  Wh    = (half*)(sbuf + 18432);     // 17408 B
    float* stage = (float*)sbuf;              // 34816 B (reuse after mma)

    int job   = blockIdx.y;
    int ptile = blockIdx.x * 128;
    int r0 = rec[0], r1 = rec[1], r2 = rec[2];

    int t = threadIdx.x;
    bool isA = (job < 12);

    if (isA) {
        int b = job >> 2, j = job & 3;
        int rb   = (b == 0) ? r0 : ((b == 1) ? r1 : r2);
        if (j >= rb) return;
        int aoff = (b == 0) ? 0 : ((b == 1) ? r0 : (r0 + r1));
        const float* src = x + (size_t)(aoff + j) * CC * HWSZ;

        for (int i = t; i < 64 * 128; i += 256) {
            int c = i >> 7, p = i & 127;
            Xs[c][p] = src[c * HWSZ + ptile + p];
        }
        __syncthreads();

        float*   xt  = g_xt  + (size_t)job * HWSZ * 64;
        __half2* xth = g_xth + (size_t)job * HWSZ * 32;
        // f32 transpose (value path)
        for (int i = t; i < 128 * 64; i += 256) {
            int p = i >> 6, c = i & 63;
            xt[(size_t)(ptile + p) * 64 + c] = Xs[c][p];
        }
        // fp16 transpose (score-gather path), packed half2
        for (int i = t; i < 128 * 32; i += 256) {
            int p = i >> 5, c2 = i & 31;
            xth[(size_t)(ptile + p) * 32 + c2] =
                __floats2half2_rn(Xs[2 * c2][p], Xs[2 * c2 + 1][p]);
        }
        return;
    }

    // ---- E job: [128 pix x 64 k] @ [64 k x 128 out] on tensor cores
    int b = job - 12;
    int aoff = (b == 0) ? 0 : ((b == 1) ? r0 : (r0 + r1));
    const float* src = x + (size_t)aoff * CC * HWSZ;
    __half2* dst = g_Eh + (size_t)b * HWSZ * 64;

    for (int i = t; i < 64 * 128; i += 256) {
        int c = i >> 7, p = i & 127;
        Xs[c][p] = src[c * HWSZ + ptile + p];
    }
    for (int i = t; i < 64 * 128; i += 256) {
        int c = i >> 7, o = i & 127;
        Wh[c * 136 + o] = __float2half(w1[(64 + c) * 128 + o]);
    }
    __syncthreads();
    for (int i = t; i < 128 * 64; i += 256) {
        int p = i >> 6, c = i & 63;
        Xh[p * 72 + c] = __float2half(Xs[c][p]);
    }
    __syncthreads();

    int w = t >> 5;
    wmma::fragment<wmma::accumulator, 16, 16, 16, float> acc[8];
#pragma unroll
    for (int j = 0; j < 8; j++) wmma::fill_fragment(acc[j], 0.0f);
#pragma unroll
    for (int k0 = 0; k0 < 64; k0 += 16) {
        wmma::fragment<wmma::matrix_a, 16, 16, 16, half, wmma::row_major> af;
        wmma::load_matrix_sync(af, Xh + (w * 16) * 72 + k0, 72);
#pragma unroll
        for (int j = 0; j < 8; j++) {
            wmma::fragment<wmma::matrix_b, 16, 16, 16, half, wmma::row_major> bf;
            wmma::load_matrix_sync(bf, Wh + k0 * 136 + j * 16, 136);
            wmma::mma_sync(acc[j], af, bf, acc[j]);
        }
    }
    __syncthreads();

#pragma unroll
    for (int hid = 0; hid < 2; hid++) {
#pragma unroll
        for (int j = 0; j < 4; j++)
            wmma::store_matrix_sync(stage + (w * 16) * 68 + j * 16, acc[hid * 4 + j], 68, wmma::mem_row_major);
        __syncthreads();
        for (int i = t; i < 128 * 32; i += 256) {
            int p = i >> 5, c2 = i & 31;
            __half2 hv = __floats2half2_rn(stage[p * 68 + 2 * c2], stage[p * 68 + 2 * c2 + 1]);
            dst[(size_t)(ptile + p) * 64 + hid * 32 + c2] = hv;
        }
        __syncthreads();
    }
}

// ---------------- Kernel 2a: warped-gather + layer1 wmma + layers 2-4 -> scores --------
// grid = (200 pixel-tiles, 12 (b,j)); block 256
__global__ __launch_bounds__(256, 2) void disco_k2a(
    const float* __restrict__ mask,
    const int* __restrict__ rec, const float* __restrict__ ptm,
    const float* __restrict__ w1,
    const float* __restrict__ cb1, const float* __restrict__ ga1,
    const float* __restrict__ be1, const float* __restrict__ rm1, const float* __restrict__ rv1,
    const float* __restrict__ w2, const float* __restrict__ cb2, const float* __restrict__ ga2,
    const float* __restrict__ be2, const float* __restrict__ rm2, const float* __restrict__ rv2,
    const float* __restrict__ w3, const float* __restrict__ cb3, const float* __restrict__ ga3,
    const float* __restrict__ be3, const float* __restrict__ rm3, const float* __restrict__ rv3,
    const float* __restrict__ w4, const float* __restrict__ cb4)
{
    // union: {s_nb[64][72]h (9216B) | s_w1a[64][136]h (17408B)}  ->  stage[64][132] f32 (33792B)
    __shared__ __align__(16) unsigned char u_buf[33792];
    half*  s_nb  = (half*)u_buf;
    half*  s_w1a = (half*)(u_buf + 9216);
    float* stage = (float*)u_buf;

    __shared__ __align__(16) uint  s_h1[64 * 68];    // h1 half2 [pix][k2]
    __shared__ __align__(16) uint  s_w2p[64 * 36];   // w2 half2 k-pairs [k2][o]
    __shared__ __align__(16) float s_h2[64 * 36];    // h2 [pix][o]
    __shared__ __align__(16) float s_f1s[128], s_f1b[128];
    __shared__ __align__(16) float s_f2s[32], s_f2b[32];
    __shared__ __align__(16) float s_w3[256];
    __shared__ __align__(16) float s_f3s[8], s_f3b[8], s_w4v[8];
    __shared__ float s_cb4v;
    __shared__ float s_com[64];

    int job = blockIdx.y;
    int b = job >> 2, j = job & 3;
    if (j >= rec[b]) return;

    int t = threadIdx.x;
    if (t < 128) {
        float sc = ga1[t] * rsqrtf(rv1[t] + EPSB);
        s_f1s[t] = sc;
        s_f1b[t] = (cb1[t] - rm1[t]) * sc + be1[t];
    }
    // w1 nbr-half rows [0,64) -> fp16 row-major [k][o] ld 136
    for (int i = t; i < 64 * 128; i += 256) {
        int c = i >> 7, o = i & 127;
        s_w1a[c * 136 + o] = __float2half(w1[c * 128 + o]);
    }
    for (int i = t; i < 2048; i += 256) {
        int k2 = i >> 5, o = i & 31;
        __half2 hp = __floats2half2_rn(w2[(2 * k2) * 32 + o], w2[(2 * k2 + 1) * 32 + o]);
        s_w2p[k2 * 36 + o] = *(uint*)&hp;
    }
    if (t < 32) {
        float sc = ga2[t] * rsqrtf(rv2[t] + EPSB);
        s_f2s[t] = sc;
        s_f2b[t] = (cb2[t] - rm2[t]) * sc + be2[t];
    }
    s_w3[t] = w3[t & 255];
    if (t < 8) {
        float sc = ga3[t] * rsqrtf(rv3[t] + EPSB);
        s_f3s[t] = sc;
        s_f3b[t] = (cb3[t] - rm3[t]) * sc + be3[t];
        s_w4v[t] = w4[t];
    }
    if (t == 0) s_cb4v = cb4[0];

    int ptile = blockIdx.x * 64;
    const float* th = ptm + (size_t)(b * 4 + j) * 24;
    float t00 = th[0], t01 = th[1], t02 = th[2];
    float t10 = th[3], t11 = th[4], t12 = th[5];

    const __half2* Xb = g_xth + (size_t)job * HWSZ * 32;
    const float*   Mb = mask  + (size_t)(b * 4 + j) * HWSZ;

    // ---- Stage 1: gather warped raw x (64 ch fp16) -> s_nb; com from mask.
    // 256 threads = 64 pix x 4 cg, 16 channels each.
    {
        int pix = t >> 2, cg = t & 3;
        int pg  = ptile + pix;
        int hh  = pg / WW;
        int wpx = pg - hh * WW;
        float gx = -1.0f + wpx * (2.0f / (WW - 1));
        float gy = -1.0f + hh  * (2.0f / (HH - 1));
        float px = (t00 * gx + t01 * gy + t02 + 1.0f) * ((WW - 1) * 0.5f);
        float py = (t10 * gx + t11 * gy + t12 + 1.0f) * ((HH - 1) * 0.5f);
        float x0f = floorf(px), y0f = floorf(py);
        float wx = px - x0f, wy = py - y0f;
        int x0 = (int)x0f, y0 = (int)y0f;
        float wt4[4] = { (1.0f - wx) * (1.0f - wy), wx * (1.0f - wy),
                         (1.0f - wx) * wy,          wx * wy };
        float acc[16];
#pragma unroll
        for (int i = 0; i < 16; i++) acc[i] = 0.0f;
        float comv = 0.0f;
#pragma unroll
        for (int tap = 0; tap < 4; tap++) {
            int xi = x0 + (tap & 1), yi = y0 + (tap >> 1);
            bool inb = (xi >= 0) && (xi < WW) && (yi >= 0) && (yi < HH);
            int xc = min(max(xi, 0), WW - 1);
            int yc = min(max(yi, 0), HH - 1);
            float tw = inb ? wt4[tap] : 0.0f;
            int rt = yc * WW + xc;
            if (cg == 0) comv += tw * Mb[rt];
            const uint4* Xp = (const uint4*)(Xb + (size_t)rt * 32 + cg * 8);
            uint4 v0 = Xp[0], v1 = Xp[1];
            float2 f;
            f = h2f(v0.x); acc[0]  = fmaf(tw, f.x, acc[0]);  acc[1]  = fmaf(tw, f.y, acc[1]);
            f = h2f(v0.y); acc[2]  = fmaf(tw, f.x, acc[2]);  acc[3]  = fmaf(tw, f.y, acc[3]);
            f = h2f(v0.z); acc[4]  = fmaf(tw, f.x, acc[4]);  acc[5]  = fmaf(tw, f.y, acc[5]);
            f = h2f(v0.w); acc[6]  = fmaf(tw, f.x, acc[6]);  acc[7]  = fmaf(tw, f.y, acc[7]);
            f = h2f(v1.x); acc[8]  = fmaf(tw, f.x, acc[8]);  acc[9]  = fmaf(tw, f.y, acc[9]);
            f = h2f(v1.y); acc[10] = fmaf(tw, f.x, acc[10]); acc[11] = fmaf(tw, f.y, acc[11]);
            f = h2f(v1.z); acc[12] = fmaf(tw, f.x, acc[12]); acc[13] = fmaf(tw, f.y, acc[13]);
            f = h2f(v1.w); acc[14] = fmaf(tw, f.x, acc[14]); acc[15] = fmaf(tw, f.y, acc[15]);
        }
        uint ow[8];
#pragma unroll
        for (int i = 0; i < 8; i++) {
            __half2 hp = __floats2half2_rn(acc[2 * i], acc[2 * i + 1]);
            ow[i] = *(uint*)&hp;
        }
        uint4* np = (uint4*)(s_nb + pix * 72 + cg * 16);
        uint4 wv0; wv0.x = ow[0]; wv0.y = ow[1]; wv0.z = ow[2]; wv0.w = ow[3];
        uint4 wv1; wv1.x = ow[4]; wv1.y = ow[5]; wv1.z = ow[6]; wv1.w = ow[7];
        np[0] = wv0;
        np[1] = wv1;
        if (cg == 0) s_com[pix] = comv;
    }
    __syncthreads();

    // ---- Stage 2: layer1 GEMM on tensor cores: [64 pix x 64 k] @ [64 k x 128 out]
    // 8 warps: warp w -> m-rows [(w&3)*16, +16), n-cols [(w>>2)*64, +64) (4 frags)
    {
        int w = t >> 5;
        int mrow = (w & 3) * 16;
        int ncol = (w >> 2) * 64;
        wmma::fragment<wmma::accumulator, 16, 16, 16, float> acc[4];
#pragma unroll
        for (int jf = 0; jf < 4; jf++) wmma::fill_fragment(acc[jf], 0.0f);
#pragma unroll
        for (int k0 = 0; k0 < 64; k0 += 16) {
            wmma::fragment<wmma::matrix_a, 16, 16, 16, half, wmma::row_major> af;
            wmma::load_matrix_sync(af, s_nb + mrow * 72 + k0, 72);
#pragma unroll
            for (int jf = 0; jf < 4; jf++) {
                wmma::fragment<wmma::matrix_b, 16, 16, 16, half, wmma::row_major> bf;
                wmma::load_matrix_sync(bf, s_w1a + k0 * 136 + ncol + jf * 16, 136);
                wmma::mma_sync(acc[jf], af, bf, acc[jf]);
            }
        }
        __syncthreads();   // s_nb/s_w1a reads done -> reuse as stage
#pragma unroll
        for (int jf = 0; jf < 4; jf++)
            wmma::store_matrix_sync(stage + mrow * 132 + ncol + jf * 16, acc[jf], 132, wmma::mem_row_major);
    }
    __syncthreads();

    // ---- Stage 2e: + E, bn1, relu, pack fp16 -> s_h1 (same layout as before)
    {
        const __half2* Eb = g_Eh + (size_t)b * HWSZ * 64;
        for (int i = t; i < 64 * 64; i += 256) {
            int pix = i >> 6, c2 = i & 63;
            uint eu = *(const uint*)(Eb + (size_t)(ptile + pix) * 64 + c2);
            float2 ef = h2f(eu);
            float a0 = stage[pix * 132 + 2 * c2]     + ef.x;
            float a1 = stage[pix * 132 + 2 * c2 + 1] + ef.y;
            float2 sv = *(const float2*)&s_f1s[2 * c2];
            float2 bv = *(const float2*)&s_f1b[2 * c2];
            float h0 = fmaxf(0.0f, a0 * sv.x + bv.x);
            float h1 = fmaxf(0.0f, a1 * sv.y + bv.y);
            __half2 hp = __floats2half2_rn(h0, h1);
            s_h1[pix * 68 + c2] = *(uint*)&hp;
        }
    }
    __syncthreads();

    // ---- Stage 3: layer2 GEMM [64 x 128] @ [128 x 32], thread = 2 pix x 4 outs
    {
        int tn = t & 7, tp = t >> 3;
        float acc[2][4];
#pragma unroll
        for (int p = 0; p < 2; p++)
#pragma unroll
            for (int o = 0; o < 4; o++) acc[p][o] = 0.0f;
        const uint* h0p = &s_h1[(2 * tp) * 68];
        const uint* h1p = &s_h1[(2 * tp + 1) * 68];
#pragma unroll 4
        for (int k2 = 0; k2 < 64; k2++) {
            float2 ha = h2f(h0p[k2]);
            float2 hb = h2f(h1p[k2]);
            uint4 wv = *(const uint4*)&s_w2p[k2 * 36 + tn * 4];
            float2 w0 = h2f(wv.x), w1f = h2f(wv.y), w2f = h2f(wv.z), w3f = h2f(wv.w);
            acc[0][0] = fmaf(ha.x, w0.x,  fmaf(ha.y, w0.y,  acc[0][0]));
            acc[0][1] = fmaf(ha.x, w1f.x, fmaf(ha.y, w1f.y, acc[0][1]));
            acc[0][2] = fmaf(ha.x, w2f.x, fmaf(ha.y, w2f.y, acc[0][2]));
            acc[0][3] = fmaf(ha.x, w3f.x, fmaf(ha.y, w3f.y, acc[0][3]));
            acc[1][0] = fmaf(hb.x, w0.x,  fmaf(hb.y, w0.y,  acc[1][0]));
            acc[1][1] = fmaf(hb.x, w1f.x, fmaf(hb.y, w1f.y, acc[1][1]));
            acc[1][2] = fmaf(hb.x, w2f.x, fmaf(hb.y, w2f.y, acc[1][2]));
            acc[1][3] = fmaf(hb.x, w3f.x, fmaf(hb.y, w3f.y, acc[1][3]));
        }
        float4 f2s = *(const float4*)&s_f2s[tn * 4];
        float4 f2b = *(const float4*)&s_f2b[tn * 4];
#pragma unroll
        for (int p = 0; p < 2; p++) {
            float4 hv;
            hv.x = fmaxf(0.0f, acc[p][0] * f2s.x + f2b.x);
            hv.y = fmaxf(0.0f, acc[p][1] * f2s.y + f2b.y);
            hv.z = fmaxf(0.0f, acc[p][2] * f2s.z + f2b.z);
            hv.w = fmaxf(0.0f, acc[p][3] * f2s.w + f2b.w);
            *(float4*)&s_h2[(2 * tp + p) * 36 + tn * 4] = hv;
        }
    }
    __syncthreads();

    // ---- Stage 4: layers 3/4 -> score, write scratch. 64 threads (1 pixel each).
    if (t < 64) {
        int pix = t;
        float p3[8];
#pragma unroll
        for (int o = 0; o < 8; o++) p3[o] = 0.0f;
#pragma unroll
        for (int k4 = 0; k4 < 8; k4++) {
            float4 hv = *(const float4*)&s_h2[pix * 36 + k4 * 4];
            float hk[4] = { hv.x, hv.y, hv.z, hv.w };
#pragma unroll
            for (int kk = 0; kk < 4; kk++) {
                float4 wa = *(const float4*)&s_w3[(k4 * 4 + kk) * 8];
                float4 wb = *(const float4*)&s_w3[(k4 * 4 + kk) * 8 + 4];
                p3[0] = fmaf(hk[kk], wa.x, p3[0]);
                p3[1] = fmaf(hk[kk], wa.y, p3[1]);
                p3[2] = fmaf(hk[kk], wa.z, p3[2]);
                p3[3] = fmaf(hk[kk], wa.w, p3[3]);
                p3[4] = fmaf(hk[kk], wb.x, p3[4]);
                p3[5] = fmaf(hk[kk], wb.y, p3[5]);
                p3[6] = fmaf(hk[kk], wb.z, p3[6]);
                p3[7] = fmaf(hk[kk], wb.w, p3[7]);
            }
        }
        float s4 = s_cb4v;
#pragma unroll
        for (int o = 0; o < 8; o++) {
            float h3 = fmaxf(0.0f, p3[o] * s_f3s[o] + s_f3b[o]);
            s4 = fmaf(h3, s_w4v[o], s4);
        }
        float comv = s_com[pix];
        float sc = (comv == 0.0f) ? NEGV : fmaxf(0.0f, s4);
        size_t base = ((size_t)b * HWSZ + ptile + pix) * 4 + j;
        g_S[base] = sc;
        g_C[base] = comv;
    }
}

// ---------------- Kernel 2b: softmax + update gather + final MLP GEMM ----------------
// grid = 600 (64 pixels each); block 256
__global__ __launch_bounds__(256) void disco_k2b(
    const int* __restrict__ rec, const float* __restrict__ ptm,
    const float* __restrict__ mlpw, const float* __restrict__ mlpb,
    float* __restrict__ out)
{
    __shared__ __align__(16) float s_u[64 * 68];   // u[pix][c] then reused as o[d][pix]
    __shared__ __align__(16) float s_mw[64 * 68];  // mlp_w [c][d] padded
    __shared__ __align__(16) float s_mb[64];

    int t = threadIdx.x;
    for (int i = t; i < 4096; i += 256) {
        int c = i >> 6, d = i & 63;
        s_mw[c * 68 + d] = mlpw[i];
    }
    if (t < 64) s_mb[t] = mlpb[t];

    int gt   = blockIdx.x * 64;
    int b    = gt / HWSZ;
    int prem = gt - b * HWSZ;
    int rb   = rec[b];

    // ---- Phase A: softmax + x_t gather -> s_u
    {
        int pix = t >> 2, cg = t & 3;       // 16 channels
        int pr  = prem + pix;
        size_t sbase = ((size_t)b * HWSZ + pr) * 4;
        float4 sc = *(const float4*)&g_S[sbase];
        float4 cm = *(const float4*)&g_C[sbase];
        float sj[4] = { sc.x, sc.y, sc.z, sc.w };
        float cj[4] = { cm.x, cm.y, cm.z, cm.w };
#pragma unroll
        for (int j = 0; j < 4; j++)
            if (j >= rb) { sj[j] = NEGV; cj[j] = 0.0f; }
        float m = fmaxf(fmaxf(sj[0], sj[1]), fmaxf(sj[2], sj[3]));
        float ex[4], ssum = 0.0f;
#pragma unroll
        for (int j = 0; j < 4; j++) { ex[j] = expf(sj[j] - m); ssum += ex[j]; }
        float inv = 1.0f / ssum;

        int hh  = pr / WW;
        int wpx = pr - hh * WW;
        float gx = -1.0f + wpx * (2.0f / (WW - 1));
        float gy = -1.0f + hh  * (2.0f / (HH - 1));

        float u[16];
#pragma unroll
        for (int i = 0; i < 16; i++) u[i] = 0.0f;

        for (int j = 0; j < 4; j++) {
            if (j >= rb) continue;
            float wgt = ex[j] * inv * cj[j];
            if (wgt == 0.0f) continue;
            const float* th = ptm + (size_t)(b * 4 + j) * 24;
            float t00 = th[0], t01 = th[1], t02 = th[2];
            float t10 = th[3], t11 = th[4], t12 = th[5];
            float px = (t00 * gx + t01 * gy + t02 + 1.0f) * ((WW - 1) * 0.5f);
            float py = (t10 * gx + t11 * gy + t12 + 1.0f) * ((HH - 1) * 0.5f);
            float x0f = floorf(px), y0f = floorf(py);
            float wx = px - x0f, wy = py - y0f;
            int x0 = (int)x0f, y0 = (int)y0f;
            float wt4[4] = { (1.0f - wx) * (1.0f - wy), wx * (1.0f - wy),
                             (1.0f - wx) * wy,          wx * wy };
            const float* xtb = g_xt + (size_t)(b * 4 + j) * HWSZ * 64 + cg * 16;
            float n[16];
#pragma unroll
            for (int i = 0; i < 16; i++) n[i] = 0.0f;
#pragma unroll
            for (int tap = 0; tap < 4; tap++) {
                int xi = x0 + (tap & 1), yi = y0 + (tap >> 1);
                bool inb = (xi >= 0) && (xi < WW) && (yi >= 0) && (yi < HH);
                int xc = min(max(xi, 0), WW - 1);
                int yc = min(max(yi, 0), HH - 1);
                float tw = inb ? wt4[tap] : 0.0f;
                const float4* xp = (const float4*)(xtb + (size_t)(yc * WW + xc) * 64);
#pragma unroll
                for (int q = 0; q < 4; q++) {
                    float4 v = xp[q];
                    n[q * 4 + 0] = fmaf(tw, v.x, n[q * 4 + 0]);
                    n[q * 4 + 1] = fmaf(tw, v.y, n[q * 4 + 1]);
                    n[q * 4 + 2] = fmaf(tw, v.z, n[q * 4 + 2]);
                    n[q * 4 + 3] = fmaf(tw, v.w, n[q * 4 + 3]);
                }
            }
#pragma unroll
            for (int i = 0; i < 16; i++) u[i] = fmaf(wgt, n[i], u[i]);
        }
#pragma unroll
        for (int q = 0; q < 4; q++) {
            float4 v = make_float4(u[q * 4], u[q * 4 + 1], u[q * 4 + 2], u[q * 4 + 3]);
            *(float4*)&s_u[pix * 68 + cg * 16 + q * 4] = v;
        }
    }
    __syncthreads();

    // ---- Phase B: final MLP GEMM [64 x 64] @ [64 x 64], thread = 4 pix x 4 d
    int tp = t >> 4, tn = t & 15;
    float acc[4][4];
#pragma unroll
    for (int p = 0; p < 4; p++)
#pragma unroll
        for (int d = 0; d < 4; d++) acc[p][d] = 0.0f;
#pragma unroll 4
    for (int k4 = 0; k4 < 16; k4++) {
        float4 uv[4];
#pragma unroll
        for (int p = 0; p < 4; p++)
            uv[p] = *(const float4*)&s_u[(tp * 4 + p) * 68 + k4 * 4];
        float4 wv[4];
#pragma unroll
        for (int kk = 0; kk < 4; kk++)
            wv[kk] = *(const float4*)&s_mw[(k4 * 4 + kk) * 68 + tn * 4];
#pragma unroll
        for (int p = 0; p < 4; p++) {
            acc[p][0] = fmaf(uv[p].x, wv[0].x, acc[p][0]);
            acc[p][1] = fmaf(uv[p].x, wv[0].y, acc[p][1]);
            acc[p][2] = fmaf(uv[p].x, wv[0].z, acc[p][2]);
            acc[p][3] = fmaf(uv[p].x, wv[0].w, acc[p][3]);
            acc[p][0] = fmaf(uv[p].y, wv[1].x, acc[p][0]);
            acc[p][1] = fmaf(uv[p].y, wv[1].y, acc[p][1]);
            acc[p][2] = fmaf(uv[p].y, wv[1].z, acc[p][2]);
            acc[p][3] = fmaf(uv[p].y, wv[1].w, acc[p][3]);
            acc[p][0] = fmaf(uv[p].z, wv[2].x, acc[p][0]);
            acc[p][1] = fmaf(uv[p].z, wv[2].y, acc[p][1]);
            acc[p][2] = fmaf(uv[p].z, wv[2].z, acc[p][2]);
            acc[p][3] = fmaf(uv[p].z, wv[2].w, acc[p][3]);
            acc[p][0] = fmaf(uv[p].w, wv[3].x, acc[p][0]);
            acc[p][1] = fmaf(uv[p].w, wv[3].y, acc[p][1]);
            acc[p][2] = fmaf(uv[p].w, wv[3].z, acc[p][2]);
            acc[p][3] = fmaf(uv[p].w, wv[3].w, acc[p][3]);
        }
    }
    float4 bias = *(const float4*)&s_mb[tn * 4];
    __syncthreads();    // all reads of s_u done -> safe to overwrite as o[d][pix]
#pragma unroll
    for (int d = 0; d < 4; d++) {
        float bd = (d == 0) ? bias.x : (d == 1) ? bias.y : (d == 2) ? bias.z : bias.w;
        float4 ov = make_float4(acc[0][d] + bd, acc[1][d] + bd, acc[2][d] + bd, acc[3][d] + bd);
        *(float4*)&s_u[(tn * 4 + d) * 68 + tp * 4] = ov;
    }
    __syncthreads();

    for (int i = t; i < 4096; i += 256) {
        int d = i >> 6, pp = i & 63;
        out[((size_t)b * CC + d) * HWSZ + prem + pp] = s_u[d * 68 + pp];
    }
}

extern "C" void kernel_launch(void* const* d_in, const int* in_sizes, int n_in,
                              void* d_out, int out_size) {
    (void)in_sizes; (void)n_in; (void)out_size;
    const float* x    = (const float*)d_in[0];
    const float* mask = (const float*)d_in[1];
    const int*   rec  = (const int*)d_in[2];
    const float* ptm  = (const float*)d_in[3];
    const float* w1   = (const float*)d_in[4];
    const float* cb1  = (const float*)d_in[5];
    const float* ga1  = (const float*)d_in[6];
    const float* be1  = (const float*)d_in[7];
    const float* rm1  = (const float*)d_in[8];
    const float* rv1  = (const float*)d_in[9];
    const float* w2   = (const float*)d_in[10];
    const float* cb2  = (const float*)d_in[11];
    const float* ga2  = (const float*)d_in[12];
    const float* be2  = (const float*)d_in[13];
    const float* rm2  = (const float*)d_in[14];
    const float* rv2  = (const float*)d_in[15];
    const float* w3   = (const float*)d_in[16];
    const float* cb3  = (const float*)d_in[17];
    const float* ga3  = (const float*)d_in[18];
    const float* be3  = (const float*)d_in[19];
    const float* rm3  = (const float*)d_in[20];
    const float* rv3  = (const float*)d_in[21];
    const float* w4   = (const float*)d_in[22];
    const float* cb4  = (const float*)d_in[23];
    const float* mlpw = (const float*)d_in[24];
    const float* mlpb = (const float*)d_in[25];
    float* out = (float*)d_out;

    dim3 grid1(HWSZ / 128, 15);
    disco_k1<<<grid1, 256>>>(x, rec, w1);

    dim3 grid2a(HWSZ / 64, 12);
    disco_k2a<<<grid2a, 256>>>(mask, rec, ptm, w1,
                               cb1, ga1, be1, rm1, rv1,
                               w2, cb2, ga2, be2, rm2, rv2,
                               w3, cb3, ga3, be3, rm3, rv3,
                               w4, cb4);

    disco_k2b<<<(BB * HWSZ) / 64, 256>>>(rec, ptm, mlpw, mlpb, out);
}

// round 9
// speedup vs baseline: 3.5353x; 1.3072x over previous
#include <cuda_runtime.h>
#include <cuda_fp16.h>
#include <mma.h>
#include <math.h>

using namespace nvcuda;

#define CC   64
#define HH   80
#define WW   160
#define HWSZ (HH * WW)      // 12800
#define BB   3
#define LL   4
#define EPSB 1e-5f
#define NEGV -1e30f

typedef unsigned int uint;

// Scratch:
//  g_Eh[b][pix][o/2]      conv partial (ego half, node[b,0]), channel-last, 128 ch, fp16
//  g_xth[b*4+j][pix][c/2] raw x transposed channel-last (64 ch, fp16) -> warped gathers
__device__ __align__(16) __half2 g_Eh[(size_t)BB * HWSZ * 64];        // 9.8 MB
__device__ __align__(16) __half2 g_xth[(size_t)BB * LL * HWSZ * 32];  // 19.7 MB

__device__ __forceinline__ float2 h2f(uint u) {
    return __half22float2(*reinterpret_cast<__half2*>(&u));
}

// ---------------- Kernel 1: fp16 transposes (A-jobs) + ego GEMM (E-jobs) ----------------
// jobs 0..11  : transpose x slice (b=job/4, j=job%4) -> g_xth (fp16 channel-last)
// jobs 12..14 : E = node[b,0] @ w1[64:128] -> g_Eh  (wmma fp16/f32)
__global__ __launch_bounds__(256, 2) void disco_k1(const float* __restrict__ x,
                                                   const int* __restrict__ rec,
                                                   const float* __restrict__ w1) {
    __shared__ __align__(16) float Xs[64][133];          // f32 [k][pix], conflict-free transpose
    __shared__ __align__(16) unsigned char sbuf[35840];  // Xh[128][72]h | Wh[64][136]h ; reused as stage[128][68] f32
    half*  Xh    = (half*)sbuf;
    half*  Wh    = (half*)(sbuf + 18432);
    float* stage = (float*)sbuf;

    int job   = blockIdx.y;
    int ptile = blockIdx.x * 128;
    int r0 = rec[0], r1 = rec[1], r2 = rec[2];

    int t = threadIdx.x;
    bool isA = (job < 12);

    if (isA) {
        int b = job >> 2, j = job & 3;
        int rb   = (b == 0) ? r0 : ((b == 1) ? r1 : r2);
        if (j >= rb) return;
        int aoff = (b == 0) ? 0 : ((b == 1) ? r0 : (r0 + r1));
        const float* src = x + (size_t)(aoff + j) * CC * HWSZ;

        for (int i = t; i < 64 * 128; i += 256) {
            int c = i >> 7, p = i & 127;
            Xs[c][p] = src[c * HWSZ + ptile + p];
        }
        __syncthreads();

        __half2* xth = g_xth + (size_t)job * HWSZ * 32;
        for (int i = t; i < 128 * 32; i += 256) {
            int p = i >> 5, c2 = i & 31;
            xth[(size_t)(ptile + p) * 32 + c2] =
                __floats2half2_rn(Xs[2 * c2][p], Xs[2 * c2 + 1][p]);
        }
        return;
    }

    // ---- E job: [128 pix x 64 k] @ [64 k x 128 out] on tensor cores
    int b = job - 12;
    int aoff = (b == 0) ? 0 : ((b == 1) ? r0 : (r0 + r1));
    const float* src = x + (size_t)aoff * CC * HWSZ;
    __half2* dst = g_Eh + (size_t)b * HWSZ * 64;

    for (int i = t; i < 64 * 128; i += 256) {
        int c = i >> 7, p = i & 127;
        Xs[c][p] = src[c * HWSZ + ptile + p];
    }
    for (int i = t; i < 64 * 128; i += 256) {
        int c = i >> 7, o = i & 127;
        Wh[c * 136 + o] = __float2half(w1[(64 + c) * 128 + o]);
    }
    __syncthreads();
    for (int i = t; i < 128 * 64; i += 256) {
        int p = i >> 6, c = i & 63;
        Xh[p * 72 + c] = __float2half(Xs[c][p]);
    }
    __syncthreads();

    int w = t >> 5;
    wmma::fragment<wmma::accumulator, 16, 16, 16, float> acc[8];
#pragma unroll
    for (int j = 0; j < 8; j++) wmma::fill_fragment(acc[j], 0.0f);
#pragma unroll
    for (int k0 = 0; k0 < 64; k0 += 16) {
        wmma::fragment<wmma::matrix_a, 16, 16, 16, half, wmma::row_major> af;
        wmma::load_matrix_sync(af, Xh + (w * 16) * 72 + k0, 72);
#pragma unroll
        for (int j = 0; j < 8; j++) {
            wmma::fragment<wmma::matrix_b, 16, 16, 16, half, wmma::row_major> bf;
            wmma::load_matrix_sync(bf, Wh + k0 * 136 + j * 16, 136);
            wmma::mma_sync(acc[j], af, bf, acc[j]);
        }
    }
    __syncthreads();

#pragma unroll
    for (int hid = 0; hid < 2; hid++) {
#pragma unroll
        for (int j = 0; j < 4; j++)
            wmma::store_matrix_sync(stage + (w * 16) * 68 + j * 16, acc[hid * 4 + j], 68, wmma::mem_row_major);
        __syncthreads();
        for (int i = t; i < 128 * 32; i += 256) {
            int p = i >> 5, c2 = i & 31;
            __half2 hv = __floats2half2_rn(stage[p * 68 + 2 * c2], stage[p * 68 + 2 * c2 + 1]);
            dst[(size_t)(ptile + p) * 64 + hid * 32 + c2] = hv;
        }
        __syncthreads();
    }
}

// ---------------- Kernel 2: fused scores + softmax + value + final MLP ----------------
// grid = (200 pixel-tiles, 3 b); block 256
__global__ __launch_bounds__(256, 2) void disco_k2(
    const float* __restrict__ mask,
    const int* __restrict__ rec, const float* __restrict__ ptm,
    const float* __restrict__ w1,
    const float* __restrict__ cb1, const float* __restrict__ ga1,
    const float* __restrict__ be1, const float* __restrict__ rm1, const float* __restrict__ rv1,
    const float* __restrict__ w2, const float* __restrict__ cb2, const float* __restrict__ ga2,
    const float* __restrict__ be2, const float* __restrict__ rm2, const float* __restrict__ rv2,
    const float* __restrict__ w3, const float* __restrict__ cb3, const float* __restrict__ ga3,
    const float* __restrict__ be3, const float* __restrict__ rm3, const float* __restrict__ rv3,
    const float* __restrict__ w4, const float* __restrict__ cb4,
    const float* __restrict__ mlpw, const float* __restrict__ mlpb,
    float* __restrict__ out)
{
    __shared__ __align__(16) half  s_nb[4 * 64 * 72];    // warped nbr fp16 per j (persistent)  36864 B
    __shared__ __align__(16) half  s_w1a[64 * 136];      // w1 nbr-half fp16                    17408 B
    __shared__ __align__(16) uint  s_w2p[64 * 36];       // w2 half2 k-pairs                     9216 B
    __shared__ __align__(16) float u_buf[64 * 68];       // stage f32 -> s_h2 -> s_mw           17408 B
    __shared__ __align__(16) uint  s_h1[64 * 68];        // h1 half2 per j -> s_u f32           17408 B
    __shared__ __align__(16) float s_f1s[128], s_f1b[128];
    __shared__ __align__(16) float s_f2s[32], s_f2b[32];
    __shared__ __align__(16) float s_w3[256];
    __shared__ __align__(16) float s_f3s[8], s_f3b[8], s_w4v[8];
    __shared__ float s_cb4v;
    __shared__ __align__(16) float s_com[4][64];
    __shared__ __align__(16) float s_sj[4][64];
    __shared__ __align__(16) float s_mb[64];

    int b  = blockIdx.y;
    int rb = rec[b];
    int t  = threadIdx.x;
    int ptile = blockIdx.x * 64;

    if (t < 128) {
        float sc = ga1[t] * rsqrtf(rv1[t] + EPSB);
        s_f1s[t] = sc;
        s_f1b[t] = (cb1[t] - rm1[t]) * sc + be1[t];
    }
    for (int i = t; i < 64 * 128; i += 256) {
        int c = i >> 7, o = i & 127;
        s_w1a[c * 136 + o] = __float2half(w1[c * 128 + o]);
    }
    for (int i = t; i < 2048; i += 256) {
        int k2 = i >> 5, o = i & 31;
        __half2 hp = __floats2half2_rn(w2[(2 * k2) * 32 + o], w2[(2 * k2 + 1) * 32 + o]);
        s_w2p[k2 * 36 + o] = *(uint*)&hp;
    }
    if (t < 32) {
        float sc = ga2[t] * rsqrtf(rv2[t] + EPSB);
        s_f2s[t] = sc;
        s_f2b[t] = (cb2[t] - rm2[t]) * sc + be2[t];
    }
    s_w3[t] = w3[t & 255];
    if (t < 8) {
        float sc = ga3[t] * rsqrtf(rv3[t] + EPSB);
        s_f3s[t] = sc;
        s_f3b[t] = (cb3[t] - rm3[t]) * sc + be3[t];
        s_w4v[t] = w4[t];
    }
    if (t == 0) s_cb4v = cb4[0];
    if (t < 64) s_mb[t] = mlpb[t];
    __syncthreads();

    const __half2* Eb = g_Eh + (size_t)b * HWSZ * 64;

    for (int j = 0; j < 4; j++) {           // rb is block-uniform -> uniform control flow
        if (j >= rb) {
            if (t < 64) { s_sj[j][t] = NEGV; s_com[j][t] = 0.0f; }
            continue;
        }
        int job = b * 4 + j;
        const float* th = ptm + (size_t)job * 24;
        float t00 = th[0], t01 = th[1], t02 = th[2];
        float t10 = th[3], t11 = th[4], t12 = th[5];
        const __half2* Xb = g_xth + (size_t)job * HWSZ * 32;
        const float*   Mb = mask  + (size_t)job * HWSZ;
        half* nbj = s_nb + j * 4608;

        // ---- Stage 1: gather warped raw x (64 ch fp16) -> nbj; com from mask.
        {
            int pix = t >> 2, cg = t & 3;
            int pg  = ptile + pix;
            int hh  = pg / WW;
            int wpx = pg - hh * WW;
            float gx = -1.0f + wpx * (2.0f / (WW - 1));
            float gy = -1.0f + hh  * (2.0f / (HH - 1));
            float px = (t00 * gx + t01 * gy + t02 + 1.0f) * ((WW - 1) * 0.5f);
            float py = (t10 * gx + t11 * gy + t12 + 1.0f) * ((HH - 1) * 0.5f);
            float x0f = floorf(px), y0f = floorf(py);
            float wx = px - x0f, wy = py - y0f;
            int x0 = (int)x0f, y0 = (int)y0f;
            float wt4[4] = { (1.0f - wx) * (1.0f - wy), wx * (1.0f - wy),
                             (1.0f - wx) * wy,          wx * wy };
            float acc[16];
#pragma unroll
            for (int i = 0; i < 16; i++) acc[i] = 0.0f;
            float comv = 0.0f;
#pragma unroll
            for (int tap = 0; tap < 4; tap++) {
                int xi = x0 + (tap & 1), yi = y0 + (tap >> 1);
                bool inb = (xi >= 0) && (xi < WW) && (yi >= 0) && (yi < HH);
                int xc = min(max(xi, 0), WW - 1);
                int yc = min(max(yi, 0), HH - 1);
                float tw = inb ? wt4[tap] : 0.0f;
                int rt = yc * WW + xc;
                if (cg == 0) comv += tw * Mb[rt];
                const uint4* Xp = (const uint4*)(Xb + (size_t)rt * 32 + cg * 8);
                uint4 v0 = Xp[0], v1 = Xp[1];
                float2 f;
                f = h2f(v0.x); acc[0]  = fmaf(tw, f.x, acc[0]);  acc[1]  = fmaf(tw, f.y, acc[1]);
                f = h2f(v0.y); acc[2]  = fmaf(tw, f.x, acc[2]);  acc[3]  = fmaf(tw, f.y, acc[3]);
                f = h2f(v0.z); acc[4]  = fmaf(tw, f.x, acc[4]);  acc[5]  = fmaf(tw, f.y, acc[5]);
                f = h2f(v0.w); acc[6]  = fmaf(tw, f.x, acc[6]);  acc[7]  = fmaf(tw, f.y, acc[7]);
                f = h2f(v1.x); acc[8]  = fmaf(tw, f.x, acc[8]);  acc[9]  = fmaf(tw, f.y, acc[9]);
                f = h2f(v1.y); acc[10] = fmaf(tw, f.x, acc[10]); acc[11] = fmaf(tw, f.y, acc[11]);
                f = h2f(v1.z); acc[12] = fmaf(tw, f.x, acc[12]); acc[13] = fmaf(tw, f.y, acc[13]);
                f = h2f(v1.w); acc[14] = fmaf(tw, f.x, acc[14]); acc[15] = fmaf(tw, f.y, acc[15]);
            }
            uint ow[8];
#pragma unroll
            for (int i = 0; i < 8; i++) {
                __half2 hp = __floats2half2_rn(acc[2 * i], acc[2 * i + 1]);
                ow[i] = *(uint*)&hp;
            }
            uint4* np = (uint4*)(nbj + pix * 72 + cg * 16);
            uint4 wv0; wv0.x = ow[0]; wv0.y = ow[1]; wv0.z = ow[2]; wv0.w = ow[3];
            uint4 wv1; wv1.x = ow[4]; wv1.y = ow[5]; wv1.z = ow[6]; wv1.w = ow[7];
            np[0] = wv0;
            np[1] = wv1;
            if (cg == 0) s_com[j][pix] = comv;
        }
        __syncthreads();

        // ---- Stage 2: layer1 wmma [64 x 64] @ [64 x 128]; warp w: rows (w&3)*16, cols (w>>2)*64
        int w = t >> 5;
        int mrow = (w & 3) * 16;
        int pgrp = w >> 2;
        int nbase = pgrp * 64;
        wmma::fragment<wmma::accumulator, 16, 16, 16, float> acc1[4];
#pragma unroll
        for (int jf = 0; jf < 4; jf++) wmma::fill_fragment(acc1[jf], 0.0f);
#pragma unroll
        for (int k0 = 0; k0 < 64; k0 += 16) {
            wmma::fragment<wmma::matrix_a, 16, 16, 16, half, wmma::row_major> af;
            wmma::load_matrix_sync(af, nbj + mrow * 72 + k0, 72);
#pragma unroll
            for (int jf = 0; jf < 4; jf++) {
                wmma::fragment<wmma::matrix_b, 16, 16, 16, half, wmma::row_major> bf;
                wmma::load_matrix_sync(bf, s_w1a + k0 * 136 + nbase + jf * 16, 136);
                wmma::mma_sync(acc1[jf], af, bf, acc1[jf]);
            }
        }

        // ---- epilogue in 2 passes of 64 cols through u_buf (stage)
#pragma unroll
        for (int pass = 0; pass < 2; pass++) {
            __syncthreads();                     // prior u_buf reads done
            if (pgrp == pass) {
#pragma unroll
                for (int jf = 0; jf < 4; jf++)
                    wmma::store_matrix_sync(u_buf + mrow * 68 + jf * 16, acc1[jf], 68, wmma::mem_row_major);
            }
            __syncthreads();
            for (int i = t; i < 64 * 32; i += 256) {
                int pix = i >> 5, c2r = i & 31;
                int c2 = pass * 32 + c2r;        // global half2 channel index
                uint eu = *(const uint*)(Eb + (size_t)(ptile + pix) * 64 + c2);
                float2 ef = h2f(eu);
                float a0 = u_buf[pix * 68 + 2 * c2r]     + ef.x;
                float a1 = u_buf[pix * 68 + 2 * c2r + 1] + ef.y;
                float2 sv = *(const float2*)&s_f1s[2 * c2];
                float2 bv = *(const float2*)&s_f1b[2 * c2];
                float h0 = fmaxf(0.0f, a0 * sv.x + bv.x);
                float h1 = fmaxf(0.0f, a1 * sv.y + bv.y);
                __half2 hp = __floats2half2_rn(h0, h1);
                s_h1[pix * 68 + c2] = *(uint*)&hp;
            }
        }
        __syncthreads();

        // ---- Stage 3: layer2 [64 x 128] @ [128 x 32] -> s_h2 (aliases u_buf)
        {
            float* s_h2f = u_buf;
            int tn = t & 7, tp = t >> 3;
            float acc[2][4];
#pragma unroll
            for (int p = 0; p < 2; p++)
#pragma unroll
                for (int o = 0; o < 4; o++) acc[p][o] = 0.0f;
            const uint* h0p = &s_h1[(2 * tp) * 68];
            const uint* h1p = &s_h1[(2 * tp + 1) * 68];
#pragma unroll 4
            for (int k2 = 0; k2 < 64; k2++) {
                float2 ha = h2f(h0p[k2]);
                float2 hb = h2f(h1p[k2]);
                uint4 wv = *(const uint4*)&s_w2p[k2 * 36 + tn * 4];
                float2 w0 = h2f(wv.x), w1f = h2f(wv.y), w2f = h2f(wv.z), w3f = h2f(wv.w);
                acc[0][0] = fmaf(ha.x, w0.x,  fmaf(ha.y, w0.y,  acc[0][0]));
                acc[0][1] = fmaf(ha.x, w1f.x, fmaf(ha.y, w1f.y, acc[0][1]));
                acc[0][2] = fmaf(ha.x, w2f.x, fmaf(ha.y, w2f.y, acc[0][2]));
                acc[0][3] = fmaf(ha.x, w3f.x, fmaf(ha.y, w3f.y, acc[0][3]));
                acc[1][0] = fmaf(hb.x, w0.x,  fmaf(hb.y, w0.y,  acc[1][0]));
                acc[1][1] = fmaf(hb.x, w1f.x, fmaf(hb.y, w1f.y, acc[1][1]));
                acc[1][2] = fmaf(hb.x, w2f.x, fmaf(hb.y, w2f.y, acc[1][2]));
                acc[1][3] = fmaf(hb.x, w3f.x, fmaf(hb.y, w3f.y, acc[1][3]));
            }
            float4 f2s = *(const float4*)&s_f2s[tn * 4];
            float4 f2b = *(const float4*)&s_f2b[tn * 4];
            __syncthreads();                    // s_h1 reads done? (s_h1 not re-written; protects u_buf stage->s_h2 overwrite)
#pragma unroll
            for (int p = 0; p < 2; p++) {
                float4 hv;
                hv.x = fmaxf(0.0f, acc[p][0] * f2s.x + f2b.x);
                hv.y = fmaxf(0.0f, acc[p][1] * f2s.y + f2b.y);
                hv.z = fmaxf(0.0f, acc[p][2] * f2s.z + f2b.z);
                hv.w = fmaxf(0.0f, acc[p][3] * f2s.w + f2b.w);
                *(float4*)&s_h2f[(2 * tp + p) * 36 + tn * 4] = hv;
            }
        }
        __syncthreads();

        // ---- Stage 4: layers 3/4 -> score
        if (t < 64) {
            const float* s_h2f = u_buf;
            int pix = t;
            float p3[8];
#pragma unroll
            for (int o = 0; o < 8; o++) p3[o] = 0.0f;
#pragma unroll
            for (int k4 = 0; k4 < 8; k4++) {
                float4 hv = *(const float4*)&s_h2f[pix * 36 + k4 * 4];
                float hk[4] = { hv.x, hv.y, hv.z, hv.w };
#pragma unroll
                for (int kk = 0; kk < 4; kk++) {
                    float4 wa = *(const float4*)&s_w3[(k4 * 4 + kk) * 8];
                    float4 wb = *(const float4*)&s_w3[(k4 * 4 + kk) * 8 + 4];
                    p3[0] = fmaf(hk[kk], wa.x, p3[0]);
                    p3[1] = fmaf(hk[kk], wa.y, p3[1]);
                    p3[2] = fmaf(hk[kk], wa.z, p3[2]);
                    p3[3] = fmaf(hk[kk], wa.w, p3[3]);
                    p3[4] = fmaf(hk[kk], wb.x, p3[4]);
                    p3[5] = fmaf(hk[kk], wb.y, p3[5]);
                    p3[6] = fmaf(hk[kk], wb.z, p3[6]);
                    p3[7] = fmaf(hk[kk], wb.w, p3[7]);
                }
            }
            float s4 = s_cb4v;
#pragma unroll
            for (int o = 0; o < 8; o++) {
                float h3 = fmaxf(0.0f, p3[o] * s_f3s[o] + s_f3b[o]);
                s4 = fmaf(h3, s_w4v[o], s4);
            }
            float comv = s_com[j][pix];
            s_sj[j][pix] = (comv == 0.0f) ? NEGV : fmaxf(0.0f, s4);
        }
        __syncthreads();                        // u_buf / s_h1 safe to reuse next j
    }

    // ---- load mlp_w into u_buf [c][d] ld 68
    for (int i = t; i < 4096; i += 256) {
        int c = i >> 6, d = i & 63;
        u_buf[c * 68 + d] = mlpw[i];
    }
    __syncthreads();

    // ---- softmax + value-combine from smem -> s_u (aliases s_h1)
    float* s_u = (float*)s_h1;
    {
        int pix = t >> 2, cg = t & 3;
        float sj[4], cj[4];
#pragma unroll
        for (int j = 0; j < 4; j++) { sj[j] = s_sj[j][pix]; cj[j] = s_com[j][pix]; }
        float m = fmaxf(fmaxf(sj[0], sj[1]), fmaxf(sj[2], sj[3]));
        float ex[4], ssum = 0.0f;
#pragma unroll
        for (int j = 0; j < 4; j++) { ex[j] = expf(sj[j] - m); ssum += ex[j]; }
        float inv = 1.0f / ssum;

        float u[16];
#pragma unroll
        for (int i = 0; i < 16; i++) u[i] = 0.0f;
        for (int j = 0; j < 4; j++) {
            if (j >= rb) continue;
            float wgt = ex[j] * inv * cj[j];
            if (wgt == 0.0f) continue;
            const uint4* np = (const uint4*)(s_nb + j * 4608 + pix * 72 + cg * 16);
            uint4 v0 = np[0], v1 = np[1];
            uint vv[8] = { v0.x, v0.y, v0.z, v0.w, v1.x, v1.y, v1.z, v1.w };
#pragma unroll
            for (int i = 0; i < 8; i++) {
                float2 f = h2f(vv[i]);
                u[2 * i]     = fmaf(wgt, f.x, u[2 * i]);
                u[2 * i + 1] = fmaf(wgt, f.y, u[2 * i + 1]);
            }
        }
#pragma unroll
        for (int q = 0; q < 4; q++) {
            float4 v = make_float4(u[q * 4], u[q * 4 + 1], u[q * 4 + 2], u[q * 4 + 3]);
            *(float4*)&s_u[pix * 68 + cg * 16 + q * 4] = v;
        }
    }
    __syncthreads();

    // ---- final MLP GEMM [64 x 64] @ [64 x 64], thread = 4 pix x 4 d
    {
        int tp = t >> 4, tn = t & 15;
        float acc[4][4];
#pragma unroll
        for (int p = 0; p < 4; p++)
#pragma unroll
            for (int d = 0; d < 4; d++) acc[p][d] = 0.0f;
#pragma unroll 4
        for (int k4 = 0; k4 < 16; k4++) {
            float4 uv[4];
#pragma unroll
            for (int p = 0; p < 4; p++)
                uv[p] = *(const float4*)&s_u[(tp * 4 + p) * 68 + k4 * 4];
            float4 wv[4];
#pragma unroll
            for (int kk = 0; kk < 4; kk++)
                wv[kk] = *(const float4*)&u_buf[(k4 * 4 + kk) * 68 + tn * 4];
#pragma unroll
            for (int p = 0; p < 4; p++) {
                acc[p][0] = fmaf(uv[p].x, wv[0].x, acc[p][0]);
                acc[p][1] = fmaf(uv[p].x, wv[0].y, acc[p][1]);
                acc[p][2] = fmaf(uv[p].x, wv[0].z, acc[p][2]);
                acc[p][3] = fmaf(uv[p].x, wv[0].w, acc[p][3]);
                acc[p][0] = fmaf(uv[p].y, wv[1].x, acc[p][0]);
                acc[p][1] = fmaf(uv[p].y, wv[1].y, acc[p][1]);
                acc[p][2] = fmaf(uv[p].y, wv[1].z, acc[p][2]);
                acc[p][3] = fmaf(uv[p].y, wv[1].w, acc[p][3]);
                acc[p][0] = fmaf(uv[p].z, wv[2].x, acc[p][0]);
                acc[p][1] = fmaf(uv[p].z, wv[2].y, acc[p][1]);
                acc[p][2] = fmaf(uv[p].z, wv[2].z, acc[p][2]);
                acc[p][3] = fmaf(uv[p].z, wv[2].w, acc[p][3]);
                acc[p][0] = fmaf(uv[p].w, wv[3].x, acc[p][0]);
                acc[p][1] = fmaf(uv[p].w, wv[3].y, acc[p][1]);
                acc[p][2] = fmaf(uv[p].w, wv[3].z, acc[p][2]);
                acc[p][3] = fmaf(uv[p].w, wv[3].w, acc[p][3]);
            }
        }
        float4 bias = *(const float4*)&s_mb[tn * 4];
        __syncthreads();    // s_u reads done -> overwrite as o[d][pix]
#pragma unroll
        for (int d = 0; d < 4; d++) {
            float bd = (d == 0) ? bias.x : (d == 1) ? bias.y : (d == 2) ? bias.z : bias.w;
            float4 ov = make_float4(acc[0][d] + bd, acc[1][d] + bd, acc[2][d] + bd, acc[3][d] + bd);
            *(float4*)&s_u[(tn * 4 + d) * 68 + tp * 4] = ov;
        }
    }
    __syncthreads();

    for (int i = t; i < 4096; i += 256) {
        int d = i >> 6, pp = i & 63;
        out[((size_t)b * CC + d) * HWSZ + ptile + pp] = s_u[d * 68 + pp];
    }
}

extern "C" void kernel_launch(void* const* d_in, const int* in_sizes, int n_in,
                              void* d_out, int out_size) {
    (void)in_sizes; (void)n_in; (void)out_size;
    const float* x    = (const float*)d_in[0];
    const float* mask = (const float*)d_in[1];
    const int*   rec  = (const int*)d_in[2];
    const float* ptm  = (const float*)d_in[3];
    const float* w1   = (const float*)d_in[4];
    const float* cb1  = (const float*)d_in[5];
    const float* ga1  = (const float*)d_in[6];
    const float* be1  = (const float*)d_in[7];
    const float* rm1  = (const float*)d_in[8];
    const float* rv1  = (const float*)d_in[9];
    const float* w2   = (const float*)d_in[10];
    const float* cb2  = (const float*)d_in[11];
    const float* ga2  = (const float*)d_in[12];
    const float* be2  = (const float*)d_in[13];
    const float* rm2  = (const float*)d_in[14];
    const float* rv2  = (const float*)d_in[15];
    const float* w3   = (const float*)d_in[16];
    const float* cb3  = (const float*)d_in[17];
    const float* ga3  = (const float*)d_in[18];
    const float* be3  = (const float*)d_in[19];
    const float* rm3  = (const float*)d_in[20];
    const float* rv3  = (const float*)d_in[21];
    const float* w4   = (const float*)d_in[22];
    const float* cb4  = (const float*)d_in[23];
    const float* mlpw = (const float*)d_in[24];
    const float* mlpb = (const float*)d_in[25];
    float* out = (float*)d_out;

    dim3 grid1(HWSZ / 128, 15);
    disco_k1<<<grid1, 256>>>(x, rec, w1);

    dim3 grid2(HWSZ / 64, BB);
    disco_k2<<<grid2, 256>>>(mask, rec, ptm, w1,
                             cb1, ga1, be1, rm1, rv1,
                             w2, cb2, ga2, be2, rm2, rv2,
                             w3, cb3, ga3, be3, rm3, rv3,
                             w4, cb4, mlpw, mlpb, out);
}

// round 10
// speedup vs baseline: 4.8533x; 1.3728x over previous
#include <cuda_runtime.h>
#include <cuda_fp16.h>
#include <mma.h>
#include <math.h>

using namespace nvcuda;

#define CC   64
#define HH   80
#define WW   160
#define HWSZ (HH * WW)      // 12800
#define BB   3
#define LL   4
#define EPSB 1e-5f
#define NEGV -1e30f

typedef unsigned int uint;

// Scratch:
//  g_Eh[b][pix][o/2]      conv partial (ego half, node[b,0]), channel-last, 128 ch, fp16
//  g_xth[b*4+j][pix][c/2] raw x transposed channel-last (64 ch, fp16) -> warped gathers
__device__ __align__(16) __half2 g_Eh[(size_t)BB * HWSZ * 64];        // 9.8 MB
__device__ __align__(16) __half2 g_xth[(size_t)BB * LL * HWSZ * 32];  // 19.7 MB

__device__ __forceinline__ float2 h2f(uint u) {
    return __half22float2(*reinterpret_cast<__half2*>(&u));
}

// ---------------- Kernel 1: fp16 transposes (A-jobs) + ego GEMM (E-jobs) ----------------
__global__ __launch_bounds__(256, 2) void disco_k1(const float* __restrict__ x,
                                                   const int* __restrict__ rec,
                                                   const float* __restrict__ w1) {
    __shared__ __align__(16) float Xs[64][133];
    __shared__ __align__(16) unsigned char sbuf[35840];
    half*  Xh    = (half*)sbuf;
    half*  Wh    = (half*)(sbuf + 18432);
    float* stage = (float*)sbuf;

    int job   = blockIdx.y;
    int ptile = blockIdx.x * 128;
    int r0 = rec[0], r1 = rec[1], r2 = rec[2];

    int t = threadIdx.x;
    bool isA = (job < 12);

    if (isA) {
        int b = job >> 2, j = job & 3;
        int rb   = (b == 0) ? r0 : ((b == 1) ? r1 : r2);
        if (j >= rb) return;
        int aoff = (b == 0) ? 0 : ((b == 1) ? r0 : (r0 + r1));
        const float* src = x + (size_t)(aoff + j) * CC * HWSZ;

        for (int i = t; i < 64 * 128; i += 256) {
            int c = i >> 7, p = i & 127;
            Xs[c][p] = src[c * HWSZ + ptile + p];
        }
        __syncthreads();

        __half2* xth = g_xth + (size_t)job * HWSZ * 32;
        for (int i = t; i < 128 * 32; i += 256) {
            int p = i >> 5, c2 = i & 31;
            xth[(size_t)(ptile + p) * 32 + c2] =
                __floats2half2_rn(Xs[2 * c2][p], Xs[2 * c2 + 1][p]);
        }
        return;
    }

    int b = job - 12;
    int aoff = (b == 0) ? 0 : ((b == 1) ? r0 : (r0 + r1));
    const float* src = x + (size_t)aoff * CC * HWSZ;
    __half2* dst = g_Eh + (size_t)b * HWSZ * 64;

    for (int i = t; i < 64 * 128; i += 256) {
        int c = i >> 7, p = i & 127;
        Xs[c][p] = src[c * HWSZ + ptile + p];
    }
    for (int i = t; i < 64 * 128; i += 256) {
        int c = i >> 7, o = i & 127;
        Wh[c * 136 + o] = __float2half(w1[(64 + c) * 128 + o]);
    }
    __syncthreads();
    for (int i = t; i < 128 * 64; i += 256) {
        int p = i >> 6, c = i & 63;
        Xh[p * 72 + c] = __float2half(Xs[c][p]);
    }
    __syncthreads();

    int w = t >> 5;
    wmma::fragment<wmma::accumulator, 16, 16, 16, float> acc[8];
#pragma unroll
    for (int j = 0; j < 8; j++) wmma::fill_fragment(acc[j], 0.0f);
#pragma unroll
    for (int k0 = 0; k0 < 64; k0 += 16) {
        wmma::fragment<wmma::matrix_a, 16, 16, 16, half, wmma::row_major> af;
        wmma::load_matrix_sync(af, Xh + (w * 16) * 72 + k0, 72);
#pragma unroll
        for (int j = 0; j < 8; j++) {
            wmma::fragment<wmma::matrix_b, 16, 16, 16, half, wmma::row_major> bf;
            wmma::load_matrix_sync(bf, Wh + k0 * 136 + j * 16, 136);
            wmma::mma_sync(acc[j], af, bf, acc[j]);
        }
    }
    __syncthreads();

#pragma unroll
    for (int hid = 0; hid < 2; hid++) {
#pragma unroll
        for (int j = 0; j < 4; j++)
            wmma::store_matrix_sync(stage + (w * 16) * 68 + j * 16, acc[hid * 4 + j], 68, wmma::mem_row_major);
        __syncthreads();
        for (int i = t; i < 128 * 32; i += 256) {
            int p = i >> 5, c2 = i & 31;
            __half2 hv = __floats2half2_rn(stage[p * 68 + 2 * c2], stage[p * 68 + 2 * c2 + 1]);
            dst[(size_t)(ptile + p) * 64 + hid * 32 + c2] = hv;
        }
        __syncthreads();
    }
}

// ---------------- Kernel 2: fused scores + softmax + value + final MLP ----------------
// grid = (200 pixel-tiles, 3 b); block 256
__global__ __launch_bounds__(256, 2) void disco_k2(
    const float* __restrict__ mask,
    const int* __restrict__ rec, const float* __restrict__ ptm,
    const float* __restrict__ w1,
    const float* __restrict__ cb1, const float* __restrict__ ga1,
    const float* __restrict__ be1, const float* __restrict__ rm1, const float* __restrict__ rv1,
    const float* __restrict__ w2, const float* __restrict__ cb2, const float* __restrict__ ga2,
    const float* __restrict__ be2, const float* __restrict__ rm2, const float* __restrict__ rv2,
    const float* __restrict__ w3, const float* __restrict__ cb3, const float* __restrict__ ga3,
    const float* __restrict__ be3, const float* __restrict__ rm3, const float* __restrict__ rv3,
    const float* __restrict__ w4, const float* __restrict__ cb4,
    const float* __restrict__ mlpw, const float* __restrict__ mlpb,
    float* __restrict__ out)
{
    __shared__ __align__(16) half  s_nb[4 * 64 * 72];    // warped nbr fp16 per j (persistent)  36864 B
    __shared__ __align__(16) half  s_w1a[64 * 136];      // w1 nbr-half fp16                    17408 B
    __shared__ __align__(16) half  s_w2h[128 * 40];      // w2 fp16 [k][o] ld 40                10240 B
    __shared__ __align__(16) float u_buf[64 * 68];       // stage f32 -> h2 f32 -> s_mw         17408 B
    __shared__ __align__(16) uint  s_h1[64 * 68];        // h1 half2 per j -> s_u f32           17408 B
    __shared__ __align__(16) float s_f1s[128], s_f1b[128];
    __shared__ __align__(16) float s_f2s[32], s_f2b[32];
    __shared__ __align__(16) float s_w3[256];
    __shared__ __align__(16) float s_f3s[8], s_f3b[8], s_w4v[8];
    __shared__ float s_cb4v;
    __shared__ __align__(16) float s_com[4][64];
    __shared__ __align__(16) float s_sj[4][64];
    __shared__ __align__(16) float s_mb[64];

    int b  = blockIdx.y;
    int rb = rec[b];
    int t  = threadIdx.x;
    int ptile = blockIdx.x * 64;

    if (t < 128) {
        float sc = ga1[t] * rsqrtf(rv1[t] + EPSB);
        s_f1s[t] = sc;
        s_f1b[t] = (cb1[t] - rm1[t]) * sc + be1[t];
    }
    for (int i = t; i < 64 * 128; i += 256) {
        int c = i >> 7, o = i & 127;
        s_w1a[c * 136 + o] = __float2half(w1[c * 128 + o]);
    }
    for (int i = t; i < 4096; i += 256) {
        int c = i >> 5, o = i & 31;
        s_w2h[c * 40 + o] = __float2half(w2[c * 32 + o]);
    }
    if (t < 32) {
        float sc = ga2[t] * rsqrtf(rv2[t] + EPSB);
        s_f2s[t] = sc;
        s_f2b[t] = (cb2[t] - rm2[t]) * sc + be2[t];
    }
    s_w3[t] = w3[t & 255];
    if (t < 8) {
        float sc = ga3[t] * rsqrtf(rv3[t] + EPSB);
        s_f3s[t] = sc;
        s_f3b[t] = (cb3[t] - rm3[t]) * sc + be3[t];
        s_w4v[t] = w4[t];
    }
    if (t == 0) s_cb4v = cb4[0];
    if (t < 64) s_mb[t] = mlpb[t];
    __syncthreads();

    const __half2* Eb = g_Eh + (size_t)b * HWSZ * 64;

    for (int j = 0; j < 4; j++) {           // rb is block-uniform -> uniform control flow
        if (j >= rb) {
            if (t < 64) { s_sj[j][t] = NEGV; s_com[j][t] = 0.0f; }
            continue;
        }
        int job = b * 4 + j;
        const float* th = ptm + (size_t)job * 24;
        float t00 = th[0], t01 = th[1], t02 = th[2];
        float t10 = th[3], t11 = th[4], t12 = th[5];
        const __half2* Xb = g_xth + (size_t)job * HWSZ * 32;
        const float*   Mb = mask  + (size_t)job * HWSZ;
        half* nbj = s_nb + j * 4608;

        // ---- Stage 1: gather warped raw x (64 ch fp16) -> nbj; com from mask.
        {
            int pix = t >> 2, cg = t & 3;
            int pg  = ptile + pix;
            int hh  = pg / WW;
            int wpx = pg - hh * WW;
            float gx = -1.0f + wpx * (2.0f / (WW - 1));
            float gy = -1.0f + hh  * (2.0f / (HH - 1));
            float px = (t00 * gx + t01 * gy + t02 + 1.0f) * ((WW - 1) * 0.5f);
            float py = (t10 * gx + t11 * gy + t12 + 1.0f) * ((HH - 1) * 0.5f);
            float x0f = floorf(px), y0f = floorf(py);
            float wx = px - x0f, wy = py - y0f;
            int x0 = (int)x0f, y0 = (int)y0f;
            float wt4[4] = { (1.0f - wx) * (1.0f - wy), wx * (1.0f - wy),
                             (1.0f - wx) * wy,          wx * wy };
            float acc[16];
#pragma unroll
            for (int i = 0; i < 16; i++) acc[i] = 0.0f;
            float comv = 0.0f;
#pragma unroll
            for (int tap = 0; tap < 4; tap++) {
                int xi = x0 + (tap & 1), yi = y0 + (tap >> 1);
                bool inb = (xi >= 0) && (xi < WW) && (yi >= 0) && (yi < HH);
                int xc = min(max(xi, 0), WW - 1);
                int yc = min(max(yi, 0), HH - 1);
                float tw = inb ? wt4[tap] : 0.0f;
                int rt = yc * WW + xc;
                if (cg == 0) comv += tw * Mb[rt];
                const uint4* Xp = (const uint4*)(Xb + (size_t)rt * 32 + cg * 8);
                uint4 v0 = Xp[0], v1 = Xp[1];
                float2 f;
                f = h2f(v0.x); acc[0]  = fmaf(tw, f.x, acc[0]);  acc[1]  = fmaf(tw, f.y, acc[1]);
                f = h2f(v0.y); acc[2]  = fmaf(tw, f.x, acc[2]);  acc[3]  = fmaf(tw, f.y, acc[3]);
                f = h2f(v0.z); acc[4]  = fmaf(tw, f.x, acc[4]);  acc[5]  = fmaf(tw, f.y, acc[5]);
                f = h2f(v0.w); acc[6]  = fmaf(tw, f.x, acc[6]);  acc[7]  = fmaf(tw, f.y, acc[7]);
                f = h2f(v1.x); acc[8]  = fmaf(tw, f.x, acc[8]);  acc[9]  = fmaf(tw, f.y, acc[9]);
                f = h2f(v1.y); acc[10] = fmaf(tw, f.x, acc[10]); acc[11] = fmaf(tw, f.y, acc[11]);
                f = h2f(v1.z); acc[12] = fmaf(tw, f.x, acc[12]); acc[13] = fmaf(tw, f.y, acc[13]);
                f = h2f(v1.w); acc[14] = fmaf(tw, f.x, acc[14]); acc[15] = fmaf(tw, f.y, acc[15]);
            }
            uint ow[8];
#pragma unroll
            for (int i = 0; i < 8; i++) {
                __half2 hp = __floats2half2_rn(acc[2 * i], acc[2 * i + 1]);
                ow[i] = *(uint*)&hp;
            }
            uint4* np = (uint4*)(nbj + pix * 72 + cg * 16);
            uint4 wv0; wv0.x = ow[0]; wv0.y = ow[1]; wv0.z = ow[2]; wv0.w = ow[3];
            uint4 wv1; wv1.x = ow[4]; wv1.y = ow[5]; wv1.z = ow[6]; wv1.w = ow[7];
            np[0] = wv0;
            np[1] = wv1;
            if (cg == 0) s_com[j][pix] = comv;
        }
        __syncthreads();

        // ---- Stage 2: layer1 wmma [64 x 64] @ [64 x 128]; warp w: rows (w&3)*16, cols (w>>2)*64
        int w = t >> 5;
        {
            int mrow = (w & 3) * 16;
            int pgrp = w >> 2;
            int nbase = pgrp * 64;
            wmma::fragment<wmma::accumulator, 16, 16, 16, float> acc1[4];
#pragma unroll
            for (int jf = 0; jf < 4; jf++) wmma::fill_fragment(acc1[jf], 0.0f);
#pragma unroll
            for (int k0 = 0; k0 < 64; k0 += 16) {
                wmma::fragment<wmma::matrix_a, 16, 16, 16, half, wmma::row_major> af;
                wmma::load_matrix_sync(af, nbj + mrow * 72 + k0, 72);
#pragma unroll
                for (int jf = 0; jf < 4; jf++) {
                    wmma::fragment<wmma::matrix_b, 16, 16, 16, half, wmma::row_major> bf;
                    wmma::load_matrix_sync(bf, s_w1a + k0 * 136 + nbase + jf * 16, 136);
                    wmma::mma_sync(acc1[jf], af, bf, acc1[jf]);
                }
            }

            // ---- epilogue in 2 passes of 64 cols through u_buf (stage)
#pragma unroll
            for (int pass = 0; pass < 2; pass++) {
                __syncthreads();
                if (pgrp == pass) {
#pragma unroll
                    for (int jf = 0; jf < 4; jf++)
                        wmma::store_matrix_sync(u_buf + mrow * 68 + jf * 16, acc1[jf], 68, wmma::mem_row_major);
                }
                __syncthreads();
                for (int i = t; i < 64 * 32; i += 256) {
                    int pix = i >> 5, c2r = i & 31;
                    int c2 = pass * 32 + c2r;
                    uint eu = *(const uint*)(Eb + (size_t)(ptile + pix) * 64 + c2);
                    float2 ef = h2f(eu);
                    float a0 = u_buf[pix * 68 + 2 * c2r]     + ef.x;
                    float a1 = u_buf[pix * 68 + 2 * c2r + 1] + ef.y;
                    float2 sv = *(const float2*)&s_f1s[2 * c2];
                    float2 bv = *(const float2*)&s_f1b[2 * c2];
                    float h0 = fmaxf(0.0f, a0 * sv.x + bv.x);
                    float h1 = fmaxf(0.0f, a1 * sv.y + bv.y);
                    __half2 hp = __floats2half2_rn(h0, h1);
                    s_h1[pix * 68 + c2] = *(uint*)&hp;
                }
            }
        }
        __syncthreads();

        // ---- Stage 3: layer2 wmma [64 x 128] @ [128 x 32] -> u_buf f32 (ld 36)
        {
            const half* h1h = (const half*)s_h1;   // row-major [64][ld 136]
            int mrow = (w >> 1) * 16;
            int ncol = (w & 1) * 16;
            wmma::fragment<wmma::accumulator, 16, 16, 16, float> acc2;
            wmma::fill_fragment(acc2, 0.0f);
#pragma unroll
            for (int k0 = 0; k0 < 128; k0 += 16) {
                wmma::fragment<wmma::matrix_a, 16, 16, 16, half, wmma::row_major> af;
                wmma::fragment<wmma::matrix_b, 16, 16, 16, half, wmma::row_major> bf;
                wmma::load_matrix_sync(af, h1h + mrow * 136 + k0, 136);
                wmma::load_matrix_sync(bf, s_w2h + k0 * 40 + ncol, 40);
                wmma::mma_sync(acc2, af, bf, acc2);
            }
            // last u_buf readers synced at end of stage-2 epilogue -> safe to store
            wmma::store_matrix_sync(u_buf + mrow * 36 + ncol, acc2, 36, wmma::mem_row_major);
        }
        __syncthreads();

        // bn2 + relu elementwise on u_buf [64][36] (32 valid cols)
        for (int i = t; i < 2048; i += 256) {
            int pix = i >> 5, o = i & 31;
            float v = u_buf[pix * 36 + o];
            u_buf[pix * 36 + o] = fmaxf(0.0f, v * s_f2s[o] + s_f2b[o]);
        }
        __syncthreads();

        // ---- Stage 4: layers 3/4 -> score
        if (t < 64) {
            const float* s_h2f = u_buf;
            int pix = t;
            float p3[8];
#pragma unroll
            for (int o = 0; o < 8; o++) p3[o] = 0.0f;
#pragma unroll
            for (int k4 = 0; k4 < 8; k4++) {
                float4 hv = *(const float4*)&s_h2f[pix * 36 + k4 * 4];
                float hk[4] = { hv.x, hv.y, hv.z, hv.w };
#pragma unroll
                for (int kk = 0; kk < 4; kk++) {
                    float4 wa = *(const float4*)&s_w3[(k4 * 4 + kk) * 8];
                    float4 wb = *(const float4*)&s_w3[(k4 * 4 + kk) * 8 + 4];
                    p3[0] = fmaf(hk[kk], wa.x, p3[0]);
                    p3[1] = fmaf(hk[kk], wa.y, p3[1]);
                    p3[2] = fmaf(hk[kk], wa.z, p3[2]);
                    p3[3] = fmaf(hk[kk], wa.w, p3[3]);
                    p3[4] = fmaf(hk[kk], wb.x, p3[4]);
                    p3[5] = fmaf(hk[kk], wb.y, p3[5]);
                    p3[6] = fmaf(hk[kk], wb.z, p3[6]);
                    p3[7] = fmaf(hk[kk], wb.w, p3[7]);
                }
            }
            float s4 = s_cb4v;
#pragma unroll
            for (int o = 0; o < 8; o++) {
                float h3 = fmaxf(0.0f, p3[o] * s_f3s[o] + s_f3b[o]);
                s4 = fmaf(h3, s_w4v[o], s4);
            }
            float comv = s_com[j][pix];
            s_sj[j][pix] = (comv == 0.0f) ? NEGV : fmaxf(0.0f, s4);
        }
        __syncthreads();
    }

    // ---- load mlp_w into u_buf [c][d] ld 68
    for (int i = t; i < 4096; i += 256) {
        int c = i >> 6, d = i & 63;
        u_buf[c * 68 + d] = mlpw[i];
    }
    __syncthreads();

    // ---- softmax + value-combine from smem -> s_u (aliases s_h1)
    float* s_u = (float*)s_h1;
    {
        int pix = t >> 2, cg = t & 3;
        float sj[4], cj[4];
#pragma unroll
        for (int j = 0; j < 4; j++) { sj[j] = s_sj[j][pix]; cj[j] = s_com[j][pix]; }
        float m = fmaxf(fmaxf(sj[0], sj[1]), fmaxf(sj[2], sj[3]));
        float ex[4], ssum = 0.0f;
#pragma unroll
        for (int j = 0; j < 4; j++) { ex[j] = expf(sj[j] - m); ssum += ex[j]; }
        float inv = 1.0f / ssum;

        float u[16];
#pragma unroll
        for (int i = 0; i < 16; i++) u[i] = 0.0f;
        for (int j = 0; j < 4; j++) {
            if (j >= rb) continue;
            float wgt = ex[j] * inv * cj[j];
            if (wgt == 0.0f) continue;
            const uint4* np = (const uint4*)(s_nb + j * 4608 + pix * 72 + cg * 16);
            uint4 v0 = np[0], v1 = np[1];
            uint vv[8] = { v0.x, v0.y, v0.z, v0.w, v1.x, v1.y, v1.z, v1.w };
#pragma unroll
            for (int i = 0; i < 8; i++) {
                float2 f = h2f(vv[i]);
                u[2 * i]     = fmaf(wgt, f.x, u[2 * i]);
                u[2 * i + 1] = fmaf(wgt, f.y, u[2 * i + 1]);
            }
        }
#pragma unroll
        for (int q = 0; q < 4; q++) {
            float4 v = make_float4(u[q * 4], u[q * 4 + 1], u[q * 4 + 2], u[q * 4 + 3]);
            *(float4*)&s_u[pix * 68 + cg * 16 + q * 4] = v;
        }
    }
    __syncthreads();

    // ---- final MLP GEMM [64 x 64] @ [64 x 64], thread = 4 pix x 4 d
    {
        int tp = t >> 4, tn = t & 15;
        float acc[4][4];
#pragma unroll
        for (int p = 0; p < 4; p++)
#pragma unroll
            for (int d = 0; d < 4; d++) acc[p][d] = 0.0f;
#pragma unroll 4
        for (int k4 = 0; k4 < 16; k4++) {
            float4 uv[4];
#pragma unroll
            for (int p = 0; p < 4; p++)
                uv[p] = *(const float4*)&s_u[(tp * 4 + p) * 68 + k4 * 4];
            float4 wv[4];
#pragma unroll
            for (int kk = 0; kk < 4; kk++)
                wv[kk] = *(const float4*)&u_buf[(k4 * 4 + kk) * 68 + tn * 4];
#pragma unroll
            for (int p = 0; p < 4; p++) {
                acc[p][0] = fmaf(uv[p].x, wv[0].x, acc[p][0]);
                acc[p][1] = fmaf(uv[p].x, wv[0].y, acc[p][1]);
                acc[p][2] = fmaf(uv[p].x, wv[0].z, acc[p][2]);
                acc[p][3] = fmaf(uv[p].x, wv[0].w, acc[p][3]);
                acc[p][0] = fmaf(uv[p].y, wv[1].x, acc[p][0]);
                acc[p][1] = fmaf(uv[p].y, wv[1].y, acc[p][1]);
                acc[p][2] = fmaf(uv[p].y, wv[1].z, acc[p][2]);
                acc[p][3] = fmaf(uv[p].y, wv[1].w, acc[p][3]);
                acc[p][0] = fmaf(uv[p].z, wv[2].x, acc[p][0]);
                acc[p][1] = fmaf(uv[p].z, wv[2].y, acc[p][1]);
                acc[p][2] = fmaf(uv[p].z, wv[2].z, acc[p][2]);
                acc[p][3] = fmaf(uv[p].z, wv[2].w, acc[p][3]);
                acc[p][0] = fmaf(uv[p].w, wv[3].x, acc[p][0]);
                acc[p][1] = fmaf(uv[p].w, wv[3].y, acc[p][1]);
                acc[p][2] = fmaf(uv[p].w, wv[3].z, acc[p][2]);
                acc[p][3] = fmaf(uv[p].w, wv[3].w, acc[p][3]);
            }
        }
        float4 bias = *(const float4*)&s_mb[tn * 4];
        __syncthreads();
#pragma unroll
        for (int d = 0; d < 4; d++) {
            float bd = (d == 0) ? bias.x : (d == 1) ? bias.y : (d == 2) ? bias.z : bias.w;
            float4 ov = make_float4(acc[0][d] + bd, acc[1][d] + bd, acc[2][d] + bd, acc[3][d] + bd);
            *(float4*)&s_u[(tn * 4 + d) * 68 + tp * 4] = ov;
        }
    }
    __syncthreads();

    for (int i = t; i < 4096; i += 256) {
        int d = i >> 6, pp = i & 63;
        out[((size_t)b * CC + d) * HWSZ + ptile + pp] = s_u[d * 68 + pp];
    }
}

extern "C" void kernel_launch(void* const* d_in, const int* in_sizes, int n_in,
                              void* d_out, int out_size) {
    (void)in_sizes; (void)n_in; (void)out_size;
    const float* x    = (const float*)d_in[0];
    const float* mask = (const float*)d_in[1];
    const int*   rec  = (const int*)d_in[2];
    const float* ptm  = (const float*)d_in[3];
    const float* w1   = (const float*)d_in[4];
    const float* cb1  = (const float*)d_in[5];
    const float* ga1  = (const float*)d_in[6];
    const float* be1  = (const float*)d_in[7];
    const float* rm1  = (const float*)d_in[8];
    const float* rv1  = (const float*)d_in[9];
    const float* w2   = (const float*)d_in[10];
    const float* cb2  = (const float*)d_in[11];
    const float* ga2  = (const float*)d_in[12];
    const float* be2  = (const float*)d_in[13];
    const float* rm2  = (const float*)d_in[14];
    const float* rv2  = (const float*)d_in[15];
    const float* w3   = (const float*)d_in[16];
    const float* cb3  = (const float*)d_in[17];
    const float* ga3  = (const float*)d_in[18];
    const float* be3  = (const float*)d_in[19];
    const float* rm3  = (const float*)d_in[20];
    const float* rv3  = (const float*)d_in[21];
    const float* w4   = (const float*)d_in[22];
    const float* cb4  = (const float*)d_in[23];
    const float* mlpw = (const float*)d_in[24];
    const float* mlpb = (const float*)d_in[25];
    float* out = (float*)d_out;

    dim3 grid1(HWSZ / 128, 15);
    disco_k1<<<grid1, 256>>>(x, rec, w1);

    dim3 grid2(HWSZ / 64, BB);
    disco_k2<<<grid2, 256>>>(mask, rec, ptm, w1,
                             cb1, ga1, be1, rm1, rv1,
                             w2, cb2, ga2, be2, rm2, rv2,
                             w3, cb3, ga3, be3, rm3, rv3,
                             w4, cb4, mlpw, mlpb, out);
}

// round 11
// speedup vs baseline: 4.8841x; 1.0064x over previous
#include <cuda_runtime.h>
#include <cuda_fp16.h>
#include <mma.h>
#include <math.h>

using namespace nvcuda;

#define CC   64
#define HH   80
#define WW   160
#define HWSZ (HH * WW)      // 12800
#define BB   3
#define LL   4
#define EPSB 1e-5f
#define NEGV -1e30f

typedef unsigned int uint;

// Scratch:
//  g_Eh[b][pix][o/2]      conv partial (ego half, node[b,0]), channel-last, 128 ch, fp16
//  g_xth[b*4+j][pix][c/2] raw x transposed channel-last (64 ch, fp16) -> warped gathers
__device__ __align__(16) __half2 g_Eh[(size_t)BB * HWSZ * 64];        // 9.8 MB
__device__ __align__(16) __half2 g_xth[(size_t)BB * LL * HWSZ * 32];  // 19.7 MB

__device__ __forceinline__ float2 h2f(uint u) {
    return __half22float2(*reinterpret_cast<__half2*>(&u));
}

// ---------------- Kernel 1: fp16 transposes (A-jobs) + ego GEMM (E-jobs) ----------------
__global__ __launch_bounds__(256, 2) void disco_k1(const float* __restrict__ x,
                                                   const int* __restrict__ rec,
                                                   const float* __restrict__ w1) {
    __shared__ __align__(16) float Xs[64][133];
    __shared__ __align__(16) unsigned char sbuf[35840];
    half*  Xh    = (half*)sbuf;
    half*  Wh    = (half*)(sbuf + 18432);
    float* stage = (float*)sbuf;

    int job   = blockIdx.y;
    int ptile = blockIdx.x * 128;
    int r0 = rec[0], r1 = rec[1], r2 = rec[2];

    int t = threadIdx.x;
    bool isA = (job < 12);

    if (isA) {
        int b = job >> 2, j = job & 3;
        int rb   = (b == 0) ? r0 : ((b == 1) ? r1 : r2);
        if (j >= rb) return;
        int aoff = (b == 0) ? 0 : ((b == 1) ? r0 : (r0 + r1));
        const float* src = x + (size_t)(aoff + j) * CC * HWSZ;

        for (int i = t; i < 64 * 128; i += 256) {
            int c = i >> 7, p = i & 127;
            Xs[c][p] = src[c * HWSZ + ptile + p];
        }
        __syncthreads();

        __half2* xth = g_xth + (size_t)job * HWSZ * 32;
        for (int i = t; i < 128 * 32; i += 256) {
            int p = i >> 5, c2 = i & 31;
            xth[(size_t)(ptile + p) * 32 + c2] =
                __floats2half2_rn(Xs[2 * c2][p], Xs[2 * c2 + 1][p]);
        }
        return;
    }

    int b = job - 12;
    int aoff = (b == 0) ? 0 : ((b == 1) ? r0 : (r0 + r1));
    const float* src = x + (size_t)aoff * CC * HWSZ;
    __half2* dst = g_Eh + (size_t)b * HWSZ * 64;

    for (int i = t; i < 64 * 128; i += 256) {
        int c = i >> 7, p = i & 127;
        Xs[c][p] = src[c * HWSZ + ptile + p];
    }
    for (int i = t; i < 64 * 128; i += 256) {
        int c = i >> 7, o = i & 127;
        Wh[c * 136 + o] = __float2half(w1[(64 + c) * 128 + o]);
    }
    __syncthreads();
    for (int i = t; i < 128 * 64; i += 256) {
        int p = i >> 6, c = i & 63;
        Xh[p * 72 + c] = __float2half(Xs[c][p]);
    }
    __syncthreads();

    int w = t >> 5;
    wmma::fragment<wmma::accumulator, 16, 16, 16, float> acc[8];
#pragma unroll
    for (int j = 0; j < 8; j++) wmma::fill_fragment(acc[j], 0.0f);
#pragma unroll
    for (int k0 = 0; k0 < 64; k0 += 16) {
        wmma::fragment<wmma::matrix_a, 16, 16, 16, half, wmma::row_major> af;
        wmma::load_matrix_sync(af, Xh + (w * 16) * 72 + k0, 72);
#pragma unroll
        for (int j = 0; j < 8; j++) {
            wmma::fragment<wmma::matrix_b, 16, 16, 16, half, wmma::row_major> bf;
            wmma::load_matrix_sync(bf, Wh + k0 * 136 + j * 16, 136);
            wmma::mma_sync(acc[j], af, bf, acc[j]);
        }
    }
    __syncthreads();

#pragma unroll
    for (int hid = 0; hid < 2; hid++) {
#pragma unroll
        for (int j = 0; j < 4; j++)
            wmma::store_matrix_sync(stage + (w * 16) * 68 + j * 16, acc[hid * 4 + j], 68, wmma::mem_row_major);
        __syncthreads();
        for (int i = t; i < 128 * 32; i += 256) {
            int p = i >> 5, c2 = i & 31;
            __half2 hv = __floats2half2_rn(stage[p * 68 + 2 * c2], stage[p * 68 + 2 * c2 + 1]);
            dst[(size_t)(ptile + p) * 64 + hid * 32 + c2] = hv;
        }
        __syncthreads();
    }
}

// ---------------- Kernel 2: fused scores + softmax + value + final MLP ----------------
// grid = (200 pixel-tiles, 3 b); block 256
__global__ __launch_bounds__(256, 2) void disco_k2(
    const float* __restrict__ mask,
    const int* __restrict__ rec, const float* __restrict__ ptm,
    const float* __restrict__ w1,
    const float* __restrict__ cb1, const float* __restrict__ ga1,
    const float* __restrict__ be1, const float* __restrict__ rm1, const float* __restrict__ rv1,
    const float* __restrict__ w2, const float* __restrict__ cb2, const float* __restrict__ ga2,
    const float* __restrict__ be2, const float* __restrict__ rm2, const float* __restrict__ rv2,
    const float* __restrict__ w3, const float* __restrict__ cb3, const float* __restrict__ ga3,
    const float* __restrict__ be3, const float* __restrict__ rm3, const float* __restrict__ rv3,
    const float* __restrict__ w4, const float* __restrict__ cb4,
    const float* __restrict__ mlpw, const float* __restrict__ mlpb,
    float* __restrict__ out)
{
    __shared__ __align__(16) half  s_nb[4 * 64 * 72];    // warped nbr fp16 per j (persistent)
    __shared__ __align__(16) half  s_w1a[64 * 136];      // w1 nbr-half fp16
    __shared__ __align__(16) half  s_w2h[128 * 40];      // w2 fp16 [k][o] ld 40
    __shared__ __align__(16) float u_buf[64 * 68];       // stage f32 -> h2 f32 -> s_mw
    __shared__ __align__(16) uint  s_h1[64 * 68];        // h1 half2 per j -> s_u f32
    __shared__ __align__(16) float s_f1s[128], s_f1b[128];
    __shared__ __align__(16) float s_f2s[32], s_f2b[32];
    __shared__ __align__(16) float s_w3[256];
    __shared__ __align__(16) float s_f3s[8], s_f3b[8], s_w4v[8];
    __shared__ float s_cb4v;
    __shared__ __align__(16) float s_com[4][64];
    __shared__ __align__(16) float s_sj[4][64];
    __shared__ __align__(16) float s_mb[64];

    int b  = blockIdx.y;
    int rb = rec[b];
    int t  = threadIdx.x;
    int ptile = blockIdx.x * 64;

    if (t < 128) {
        float sc = ga1[t] * rsqrtf(rv1[t] + EPSB);
        s_f1s[t] = sc;
        s_f1b[t] = (cb1[t] - rm1[t]) * sc + be1[t];
    }
    for (int i = t; i < 64 * 128; i += 256) {
        int c = i >> 7, o = i & 127;
        s_w1a[c * 136 + o] = __float2half(w1[c * 128 + o]);
    }
    for (int i = t; i < 4096; i += 256) {
        int c = i >> 5, o = i & 31;
        s_w2h[c * 40 + o] = __float2half(w2[c * 32 + o]);
    }
    if (t < 32) {
        float sc = ga2[t] * rsqrtf(rv2[t] + EPSB);
        s_f2s[t] = sc;
        s_f2b[t] = (cb2[t] - rm2[t]) * sc + be2[t];
    }
    s_w3[t] = w3[t & 255];
    if (t < 8) {
        float sc = ga3[t] * rsqrtf(rv3[t] + EPSB);
        s_f3s[t] = sc;
        s_f3b[t] = (cb3[t] - rm3[t]) * sc + be3[t];
        s_w4v[t] = w4[t];
    }
    if (t == 0) s_cb4v = cb4[0];
    if (t < 64) s_mb[t] = mlpb[t];

    const __half2* Eb = g_Eh + (size_t)b * HWSZ * 64;

    // ================= GATHER PHASE: all 4 j's, no intervening barriers =================
    // (deep MLP: LDG streams of different j overlap; warps never wait on each other here)
    {
        int pix = t >> 2, cg = t & 3;
        int pg  = ptile + pix;
        int hh  = pg / WW;
        int wpx = pg - hh * WW;
        float gx = -1.0f + wpx * (2.0f / (WW - 1));
        float gy = -1.0f + hh  * (2.0f / (HH - 1));

        for (int j = 0; j < 4; j++) {
            if (j >= rb) {
                if (t < 64) { s_sj[j][t] = NEGV; s_com[j][t] = 0.0f; }
                continue;
            }
            int job = b * 4 + j;
            const float* th = ptm + (size_t)job * 24;
            float t00 = th[0], t01 = th[1], t02 = th[2];
            float t10 = th[3], t11 = th[4], t12 = th[5];
            const __half2* Xb = g_xth + (size_t)job * HWSZ * 32;
            const float*   Mb = mask  + (size_t)job * HWSZ;
            half* nbj = s_nb + j * 4608;

            float px = (t00 * gx + t01 * gy + t02 + 1.0f) * ((WW - 1) * 0.5f);
            float py = (t10 * gx + t11 * gy + t12 + 1.0f) * ((HH - 1) * 0.5f);
            float x0f = floorf(px), y0f = floorf(py);
            float wx = px - x0f, wy = py - y0f;
            int x0 = (int)x0f, y0 = (int)y0f;
            float wt4[4] = { (1.0f - wx) * (1.0f - wy), wx * (1.0f - wy),
                             (1.0f - wx) * wy,          wx * wy };
            float acc[16];
#pragma unroll
            for (int i = 0; i < 16; i++) acc[i] = 0.0f;
            float comv = 0.0f;
#pragma unroll
            for (int tap = 0; tap < 4; tap++) {
                int xi = x0 + (tap & 1), yi = y0 + (tap >> 1);
                bool inb = (xi >= 0) && (xi < WW) && (yi >= 0) && (yi < HH);
                int xc = min(max(xi, 0), WW - 1);
                int yc = min(max(yi, 0), HH - 1);
                float tw = inb ? wt4[tap] : 0.0f;
                int rt = yc * WW + xc;
                if (cg == 0) comv += tw * Mb[rt];
                const uint4* Xp = (const uint4*)(Xb + (size_t)rt * 32 + cg * 8);
                uint4 v0 = Xp[0], v1 = Xp[1];
                float2 f;
                f = h2f(v0.x); acc[0]  = fmaf(tw, f.x, acc[0]);  acc[1]  = fmaf(tw, f.y, acc[1]);
                f = h2f(v0.y); acc[2]  = fmaf(tw, f.x, acc[2]);  acc[3]  = fmaf(tw, f.y, acc[3]);
                f = h2f(v0.z); acc[4]  = fmaf(tw, f.x, acc[4]);  acc[5]  = fmaf(tw, f.y, acc[5]);
                f = h2f(v0.w); acc[6]  = fmaf(tw, f.x, acc[6]);  acc[7]  = fmaf(tw, f.y, acc[7]);
                f = h2f(v1.x); acc[8]  = fmaf(tw, f.x, acc[8]);  acc[9]  = fmaf(tw, f.y, acc[9]);
                f = h2f(v1.y); acc[10] = fmaf(tw, f.x, acc[10]); acc[11] = fmaf(tw, f.y, acc[11]);
                f = h2f(v1.z); acc[12] = fmaf(tw, f.x, acc[12]); acc[13] = fmaf(tw, f.y, acc[13]);
                f = h2f(v1.w); acc[14] = fmaf(tw, f.x, acc[14]); acc[15] = fmaf(tw, f.y, acc[15]);
            }
            uint ow[8];
#pragma unroll
            for (int i = 0; i < 8; i++) {
                __half2 hp = __floats2half2_rn(acc[2 * i], acc[2 * i + 1]);
                ow[i] = *(uint*)&hp;
            }
            uint4* np = (uint4*)(nbj + pix * 72 + cg * 16);
            uint4 wv0; wv0.x = ow[0]; wv0.y = ow[1]; wv0.z = ow[2]; wv0.w = ow[3];
            uint4 wv1; wv1.x = ow[4]; wv1.y = ow[5]; wv1.z = ow[6]; wv1.w = ow[7];
            np[0] = wv0;
            np[1] = wv1;
            if (cg == 0) s_com[j][pix] = comv;
        }
    }
    __syncthreads();

    // ================= COMPUTE PHASE: per valid j =================
    int w = t >> 5;
    for (int j = 0; j < rb; j++) {
        half* nbj = s_nb + j * 4608;

        // ---- Stage 2: layer1 wmma [64 x 64] @ [64 x 128]; warp w: rows (w&3)*16, cols (w>>2)*64
        {
            int mrow = (w & 3) * 16;
            int pgrp = w >> 2;
            int nbase = pgrp * 64;
            wmma::fragment<wmma::accumulator, 16, 16, 16, float> acc1[4];
#pragma unroll
            for (int jf = 0; jf < 4; jf++) wmma::fill_fragment(acc1[jf], 0.0f);
#pragma unroll
            for (int k0 = 0; k0 < 64; k0 += 16) {
                wmma::fragment<wmma::matrix_a, 16, 16, 16, half, wmma::row_major> af;
                wmma::load_matrix_sync(af, nbj + mrow * 72 + k0, 72);
#pragma unroll
                for (int jf = 0; jf < 4; jf++) {
                    wmma::fragment<wmma::matrix_b, 16, 16, 16, half, wmma::row_major> bf;
                    wmma::load_matrix_sync(bf, s_w1a + k0 * 136 + nbase + jf * 16, 136);
                    wmma::mma_sync(acc1[jf], af, bf, acc1[jf]);
                }
            }

            // epilogue in 2 passes of 64 cols through u_buf
#pragma unroll
            for (int pass = 0; pass < 2; pass++) {
                __syncthreads();               // orders prior u_buf readers (incl. prev-j stage4)
                if (pgrp == pass) {
#pragma unroll
                    for (int jf = 0; jf < 4; jf++)
                        wmma::store_matrix_sync(u_buf + mrow * 68 + jf * 16, acc1[jf], 68, wmma::mem_row_major);
                }
                __syncthreads();
                for (int i = t; i < 64 * 32; i += 256) {
                    int pix = i >> 5, c2r = i & 31;
                    int c2 = pass * 32 + c2r;
                    uint eu = *(const uint*)(Eb + (size_t)(ptile + pix) * 64 + c2);
                    float2 ef = h2f(eu);
                    float a0 = u_buf[pix * 68 + 2 * c2r]     + ef.x;
                    float a1 = u_buf[pix * 68 + 2 * c2r + 1] + ef.y;
                    float2 sv = *(const float2*)&s_f1s[2 * c2];
                    float2 bv = *(const float2*)&s_f1b[2 * c2];
                    float h0 = fmaxf(0.0f, a0 * sv.x + bv.x);
                    float h1 = fmaxf(0.0f, a1 * sv.y + bv.y);
                    __half2 hp = __floats2half2_rn(h0, h1);
                    s_h1[pix * 68 + c2] = *(uint*)&hp;
                }
            }
        }
        __syncthreads();

        // ---- Stage 3: layer2 wmma [64 x 128] @ [128 x 32] -> u_buf f32 (ld 36)
        {
            const half* h1h = (const half*)s_h1;   // row-major [64][ld 136]
            int mrow = (w >> 1) * 16;
            int ncol = (w & 1) * 16;
            wmma::fragment<wmma::accumulator, 16, 16, 16, float> acc2;
            wmma::fill_fragment(acc2, 0.0f);
#pragma unroll
            for (int k0 = 0; k0 < 128; k0 += 16) {
                wmma::fragment<wmma::matrix_a, 16, 16, 16, half, wmma::row_major> af;
                wmma::fragment<wmma::matrix_b, 16, 16, 16, half, wmma::row_major> bf;
                wmma::load_matrix_sync(af, h1h + mrow * 136 + k0, 136);
                wmma::load_matrix_sync(bf, s_w2h + k0 * 40 + ncol, 40);
                wmma::mma_sync(acc2, af, bf, acc2);
            }
            wmma::store_matrix_sync(u_buf + mrow * 36 + ncol, acc2, 36, wmma::mem_row_major);
        }
        __syncthreads();

        // ---- Stage 4: layers 3/4 with fused bn2+relu -> score
        if (t < 64) {
            const float* s_h2f = u_buf;
            int pix = t;
            float p3[8];
#pragma unroll
            for (int o = 0; o < 8; o++) p3[o] = 0.0f;
#pragma unroll
            for (int k4 = 0; k4 < 8; k4++) {
                float4 hv = *(const float4*)&s_h2f[pix * 36 + k4 * 4];
                float4 f2s = *(const float4*)&s_f2s[k4 * 4];
                float4 f2b = *(const float4*)&s_f2b[k4 * 4];
                float hk[4];
                hk[0] = fmaxf(0.0f, hv.x * f2s.x + f2b.x);
                hk[1] = fmaxf(0.0f, hv.y * f2s.y + f2b.y);
                hk[2] = fmaxf(0.0f, hv.z * f2s.z + f2b.z);
                hk[3] = fmaxf(0.0f, hv.w * f2s.w + f2b.w);
#pragma unroll
                for (int kk = 0; kk < 4; kk++) {
                    float4 wa = *(const float4*)&s_w3[(k4 * 4 + kk) * 8];
                    float4 wb = *(const float4*)&s_w3[(k4 * 4 + kk) * 8 + 4];
                    p3[0] = fmaf(hk[kk], wa.x, p3[0]);
                    p3[1] = fmaf(hk[kk], wa.y, p3[1]);
                    p3[2] = fmaf(hk[kk], wa.z, p3[2]);
                    p3[3] = fmaf(hk[kk], wa.w, p3[3]);
                    p3[4] = fmaf(hk[kk], wb.x, p3[4]);
                    p3[5] = fmaf(hk[kk], wb.y, p3[5]);
                    p3[6] = fmaf(hk[kk], wb.z, p3[6]);
                    p3[7] = fmaf(hk[kk], wb.w, p3[7]);
                }
            }
            float s4 = s_cb4v;
#pragma unroll
            for (int o = 0; o < 8; o++) {
                float h3 = fmaxf(0.0f, p3[o] * s_f3s[o] + s_f3b[o]);
                s4 = fmaf(h3, s_w4v[o], s4);
            }
            float comv = s_com[j][pix];
            s_sj[j][pix] = (comv == 0.0f) ? NEGV : fmaxf(0.0f, s4);
        }
        // no trailing sync: next j's epilogue leading sync orders u_buf reuse
    }
    __syncthreads();   // stage4 u_buf reads + s_sj writes done

    // ---- load mlp_w into u_buf [c][d] ld 68
    for (int i = t; i < 4096; i += 256) {
        int c = i >> 6, d = i & 63;
        u_buf[c * 68 + d] = mlpw[i];
    }
    __syncthreads();

    // ---- softmax + value-combine from smem -> s_u (aliases s_h1)
    float* s_u = (float*)s_h1;
    {
        int pix = t >> 2, cg = t & 3;
        float sj[4], cj[4];
#pragma unroll
        for (int j = 0; j < 4; j++) { sj[j] = s_sj[j][pix]; cj[j] = s_com[j][pix]; }
        float m = fmaxf(fmaxf(sj[0], sj[1]), fmaxf(sj[2], sj[3]));
        float ex[4], ssum = 0.0f;
#pragma unroll
        for (int j = 0; j < 4; j++) { ex[j] = expf(sj[j] - m); ssum += ex[j]; }
        float inv = 1.0f / ssum;

        float u[16];
#pragma unroll
        for (int i = 0; i < 16; i++) u[i] = 0.0f;
        for (int j = 0; j < 4; j++) {
            if (j >= rb) continue;
            float wgt = ex[j] * inv * cj[j];
            if (wgt == 0.0f) continue;
            const uint4* np = (const uint4*)(s_nb + j * 4608 + pix * 72 + cg * 16);
            uint4 v0 = np[0], v1 = np[1];
            uint vv[8] = { v0.x, v0.y, v0.z, v0.w, v1.x, v1.y, v1.z, v1.w };
#pragma unroll
            for (int i = 0; i < 8; i++) {
                float2 f = h2f(vv[i]);
                u[2 * i]     = fmaf(wgt, f.x, u[2 * i]);
                u[2 * i + 1] = fmaf(wgt, f.y, u[2 * i + 1]);
            }
        }
#pragma unroll
        for (int q = 0; q < 4; q++) {
            float4 v = make_float4(u[q * 4], u[q * 4 + 1], u[q * 4 + 2], u[q * 4 + 3]);
            *(float4*)&s_u[pix * 68 + cg * 16 + q * 4] = v;
        }
    }
    __syncthreads();

    // ---- final MLP GEMM [64 x 64] @ [64 x 64], thread = 4 pix x 4 d
    {
        int tp = t >> 4, tn = t & 15;
        float acc[4][4];
#pragma unroll
        for (int p = 0; p < 4; p++)
#pragma unroll
            for (int d = 0; d < 4; d++) acc[p][d] = 0.0f;
#pragma unroll 4
        for (int k4 = 0; k4 < 16; k4++) {
            float4 uv[4];
#pragma unroll
            for (int p = 0; p < 4; p++)
                uv[p] = *(const float4*)&s_u[(tp * 4 + p) * 68 + k4 * 4];
            float4 wv[4];
#pragma unroll
            for (int kk = 0; kk < 4; kk++)
                wv[kk] = *(const float4*)&u_buf[(k4 * 4 + kk) * 68 + tn * 4];
#pragma unroll
            for (int p = 0; p < 4; p++) {
                acc[p][0] = fmaf(uv[p].x, wv[0].x, acc[p][0]);
                acc[p][1] = fmaf(uv[p].x, wv[0].y, acc[p][1]);
                acc[p][2] = fmaf(uv[p].x, wv[0].z, acc[p][2]);
                acc[p][3] = fmaf(uv[p].x, wv[0].w, acc[p][3]);
                acc[p][0] = fmaf(uv[p].y, wv[1].x, acc[p][0]);
                acc[p][1] = fmaf(uv[p].y, wv[1].y, acc[p][1]);
                acc[p][2] = fmaf(uv[p].y, wv[1].z, acc[p][2]);
                acc[p][3] = fmaf(uv[p].y, wv[1].w, acc[p][3]);
                acc[p][0] = fmaf(uv[p].z, wv[2].x, acc[p][0]);
                acc[p][1] = fmaf(uv[p].z, wv[2].y, acc[p][1]);
                acc[p][2] = fmaf(uv[p].z, wv[2].z, acc[p][2]);
                acc[p][3] = fmaf(uv[p].z, wv[2].w, acc[p][3]);
                acc[p][0] = fmaf(uv[p].w, wv[3].x, acc[p][0]);
                acc[p][1] = fmaf(uv[p].w, wv[3].y, acc[p][1]);
                acc[p][2] = fmaf(uv[p].w, wv[3].z, acc[p][2]);
                acc[p][3] = fmaf(uv[p].w, wv[3].w, acc[p][3]);
            }
        }
        float4 bias = *(const float4*)&s_mb[tn * 4];
        __syncthreads();
#pragma unroll
        for (int d = 0; d < 4; d++) {
            float bd = (d == 0) ? bias.x : (d == 1) ? bias.y : (d == 2) ? bias.z : bias.w;
            float4 ov = make_float4(acc[0][d] + bd, acc[1][d] + bd, acc[2][d] + bd, acc[3][d] + bd);
            *(float4*)&s_u[(tn * 4 + d) * 68 + tp * 4] = ov;
        }
    }
    __syncthreads();

    for (int i = t; i < 4096; i += 256) {
        int d = i >> 6, pp = i & 63;
        out[((size_t)b * CC + d) * HWSZ + ptile + pp] = s_u[d * 68 + pp];
    }
}

extern "C" void kernel_launch(void* const* d_in, const int* in_sizes, int n_in,
                              void* d_out, int out_size) {
    (void)in_sizes; (void)n_in; (void)out_size;
    const float* x    = (const float*)d_in[0];
    const float* mask = (const float*)d_in[1];
    const int*   rec  = (const int*)d_in[2];
    const float* ptm  = (const float*)d_in[3];
    const float* w1   = (const float*)d_in[4];
    const float* cb1  = (const float*)d_in[5];
    const float* ga1  = (const float*)d_in[6];
    const float* be1  = (const float*)d_in[7];
    const float* rm1  = (const float*)d_in[8];
    const float* rv1  = (const float*)d_in[9];
    const float* w2   = (const float*)d_in[10];
    const float* cb2  = (const float*)d_in[11];
    const float* ga2  = (const float*)d_in[12];
    const float* be2  = (const float*)d_in[13];
    const float* rm2  = (const float*)d_in[14];
    const float* rv2  = (const float*)d_in[15];
    const float* w3   = (const float*)d_in[16];
    const float* cb3  = (const float*)d_in[17];
    const float* ga3  = (const float*)d_in[18];
    const float* be3  = (const float*)d_in[19];
    const float* rm3  = (const float*)d_in[20];
    const float* rv3  = (const float*)d_in[21];
    const float* w4   = (const float*)d_in[22];
    const float* cb4  = (const float*)d_in[23];
    const float* mlpw = (const float*)d_in[24];
    const float* mlpb = (const float*)d_in[25];
    float* out = (float*)d_out;

    dim3 grid1(HWSZ / 128, 15);
    disco_k1<<<grid1, 256>>>(x, rec, w1);

    dim3 grid2(HWSZ / 64, BB);
    disco_k2<<<grid2, 256>>>(mask, rec, ptm, w1,
                             cb1, ga1, be1, rm1, rv1,
                             w2, cb2, ga2, be2, rm2, rv2,
                             w3, cb3, ga3, be3, rm3, rv3,
                             w4, cb4, mlpw, mlpb, out);
}